// round 1
// baseline (speedup 1.0000x reference)
#include <cuda_runtime.h>
#include <math.h>

// Problem dims
#define BD   512      // batch
#define SD   128      // seq len
#define NED  8192     // num entities
#define EDD  128      // link emb dim
#define DDD  32       // dir emb dim
#define IND  160      // ED+DD
#define HD   512      // hidden
#define G4D  2048     // 4*H
#define NDD  8        // num directions
#define PLD  5        // tile factor

// Output layout: [pred_hard (B*NE*PL) | pred_d_rand (B*ND*PL) | loss | dc]
#define OUT_PRED_HARD 0
#define OUT_PRED_D    (512u*8192u*5u)                 // 20971520
#define OUT_LOSS      (OUT_PRED_D + 512u*8u*5u)       // 20992000
#define OUT_DC        (OUT_LOSS + 1u)                 // 20992001

// Scratch (device globals; no allocation allowed)
__device__ float g_xw[134217728];      // [s][b][4H]  = x@Wih^T + b_ih + b_hh  (512 MB)
__device__ float g_h[2][BD * HD];      // double-buffered hidden state
__device__ float g_c[BD * HD];         // cell state
__device__ float g_z1[BD * HD];
__device__ float g_z2[BD * HD];
__device__ float g_logits[BD * NDD];
__device__ float g_query[BD * EDD];

__device__ __forceinline__ float sigmf(float x) { return 1.0f / (1.0f + expf(-x)); }

// ---------------------------------------------------------------------------
// K0: zero h0, c0 (must happen INSIDE the captured graph: replays reuse state)
// ---------------------------------------------------------------------------
__global__ void k_init() {
    int i = blockIdx.x * blockDim.x + threadIdx.x;
    if (i < BD * HD) { g_h[0][i] = 0.0f; g_c[i] = 0.0f; }
}

// ---------------------------------------------------------------------------
// K1: g_xw[m][n] = concat(link_emb[inp], dir_emb[dir]) @ w_ih^T + b_ih + b_hh
//     m = s*B + b  (rows per step contiguous), M=65536, N=2048, K=160
//     64x64 tile, 4x4 micro, K-chunk 16 (chunks are uniformly link or dir).
// ---------------------------------------------------------------------------
__global__ void k_xw(const int* __restrict__ inputs, const int* __restrict__ dirs,
                     const float* __restrict__ link, const float* __restrict__ dire,
                     const float* __restrict__ w_ih, const float* __restrict__ b_ih,
                     const float* __restrict__ b_hh) {
    __shared__ float sA[64][17];
    __shared__ float sB[16][65];     // sB[c][n]
    __shared__ int sInp[64], sDir[64];

    const int tid = threadIdx.x;
    const int tx = tid & 15, ty = tid >> 4;
    const int mBase = blockIdx.x * 64;
    const int nBase = blockIdx.y * 64;

    if (tid < 64) {
        int m = mBase + tid;
        int b = m & (BD - 1);
        int s = m >> 9;
        sInp[tid] = inputs[b * SD + s];
        sDir[tid] = dirs[b * SD + s];
    }
    __syncthreads();

    float acc[16];
#pragma unroll
    for (int i = 0; i < 16; i++) acc[i] = 0.0f;

    for (int kb = 0; kb < IND; kb += 16) {
#pragma unroll
        for (int i = 0; i < 4; i++) {
            int idx = tid + i * 256;
            int r = idx >> 4, c = idx & 15;
            int k = kb + c;
            float v;
            if (k < EDD) v = link[(size_t)sInp[r] * EDD + k];
            else         v = dire[sDir[r] * DDD + (k - EDD)];
            sA[r][c] = v;
        }
#pragma unroll
        for (int i = 0; i < 4; i++) {
            int idx = tid + i * 256;
            int r = idx >> 4, c = idx & 15;
            sB[c][r] = w_ih[(nBase + r) * IND + kb + c];
        }
        __syncthreads();
#pragma unroll
        for (int kk = 0; kk < 16; kk++) {
            float a0 = sA[ty][kk],      a1 = sA[ty + 16][kk];
            float a2 = sA[ty + 32][kk], a3 = sA[ty + 48][kk];
            float w0 = sB[kk][tx],      w1 = sB[kk][tx + 16];
            float w2 = sB[kk][tx + 32], w3 = sB[kk][tx + 48];
            acc[0]  += a0 * w0; acc[1]  += a0 * w1; acc[2]  += a0 * w2; acc[3]  += a0 * w3;
            acc[4]  += a1 * w0; acc[5]  += a1 * w1; acc[6]  += a1 * w2; acc[7]  += a1 * w3;
            acc[8]  += a2 * w0; acc[9]  += a2 * w1; acc[10] += a2 * w2; acc[11] += a2 * w3;
            acc[12] += a3 * w0; acc[13] += a3 * w1; acc[14] += a3 * w2; acc[15] += a3 * w3;
        }
        __syncthreads();
    }
#pragma unroll
    for (int mi = 0; mi < 4; mi++) {
#pragma unroll
        for (int ni = 0; ni < 4; ni++) {
            int m = mBase + ty + mi * 16;
            int n = nBase + tx + ni * 16;
            g_xw[(size_t)m * G4D + n] = acc[mi * 4 + ni] + b_ih[n] + b_hh[n];
        }
    }
}

// ---------------------------------------------------------------------------
// K2: one LSTM step. gates = xw[s] + h_prev @ w_hh^T ; update c, h.
//     Per (b,j) this thread owns all 4 gates. 32b x 32j tile, 2x2 micro.
// ---------------------------------------------------------------------------
__global__ void k_lstm_step(int s, const float* __restrict__ w_hh) {
    __shared__ float sh[32][33];
    __shared__ float sw[4][32][33];
    const int tid = threadIdx.x;
    const int tx = tid & 15, ty = tid >> 4;
    const int bBase = blockIdx.x * 32;
    const int jBase = blockIdx.y * 32;
    const float* __restrict__ hprev = g_h[s & 1];
    float* __restrict__ hnext = g_h[(s + 1) & 1];

    float acc[16];
#pragma unroll
    for (int i = 0; i < 16; i++) acc[i] = 0.0f;

    for (int kb = 0; kb < HD; kb += 32) {
#pragma unroll
        for (int i = 0; i < 4; i++) {
            int idx = tid + i * 256;
            int r = idx >> 5, c = idx & 31;
            sh[r][c] = hprev[(bBase + r) * HD + kb + c];
        }
#pragma unroll
        for (int i = 0; i < 16; i++) {
            int idx = tid + i * 256;
            int g = idx >> 10;
            int rem = idx & 1023;
            int r = rem >> 5, c = rem & 31;
            sw[g][r][c] = w_hh[(g * HD + jBase + r) * HD + kb + c];
        }
        __syncthreads();
#pragma unroll
        for (int kk = 0; kk < 32; kk++) {
            float h0 = sh[ty][kk], h1 = sh[ty + 16][kk];
#pragma unroll
            for (int g = 0; g < 4; g++) {
                float w0 = sw[g][tx][kk], w1 = sw[g][tx + 16][kk];
                acc[g * 4 + 0] += h0 * w0;
                acc[g * 4 + 1] += h0 * w1;
                acc[g * 4 + 2] += h1 * w0;
                acc[g * 4 + 3] += h1 * w1;
            }
        }
        __syncthreads();
    }
#pragma unroll
    for (int bi = 0; bi < 2; bi++) {
#pragma unroll
        for (int ji = 0; ji < 2; ji++) {
            int b = bBase + ty + bi * 16;
            int j = jBase + tx + ji * 16;
            size_t xo = ((size_t)s * BD + b) * G4D + j;
            int a = bi * 2 + ji;
            float gi = acc[0 * 4 + a] + g_xw[xo];
            float gf = acc[1 * 4 + a] + g_xw[xo + HD];
            float gg = acc[2 * 4 + a] + g_xw[xo + 2 * HD];
            float go = acc[3 * 4 + a] + g_xw[xo + 3 * HD];
            float co = g_c[b * HD + j];
            float cn = sigmf(gf) * co + sigmf(gi) * tanhf(gg);
            g_c[b * HD + j] = cn;
            hnext[b * HD + j] = sigmf(go) * tanhf(cn);
        }
    }
}

// ---------------------------------------------------------------------------
// K3/K4: z = relu(A @ W^T + b), M=N=K=512. which=0: g_h[0]->g_z1 ; 1: g_z1->g_z2
// ---------------------------------------------------------------------------
__global__ void k_mlp(int which, const float* __restrict__ W, const float* __restrict__ bias) {
    __shared__ float sa[32][33];
    __shared__ float swm[32][33];
    const int tid = threadIdx.x;
    const int tx = tid & 15, ty = tid >> 4;
    const int mBase = blockIdx.x * 32;
    const int nBase = blockIdx.y * 32;
    const float* __restrict__ A = (which == 0) ? g_h[0] : g_z1;
    float* __restrict__ out = (which == 0) ? g_z1 : g_z2;

    float acc[4] = {0.f, 0.f, 0.f, 0.f};
    for (int kb = 0; kb < HD; kb += 32) {
#pragma unroll
        for (int i = 0; i < 4; i++) {
            int idx = tid + i * 256;
            int r = idx >> 5, c = idx & 31;
            sa[r][c]  = A[(mBase + r) * HD + kb + c];
            swm[r][c] = W[(nBase + r) * HD + kb + c];
        }
        __syncthreads();
#pragma unroll
        for (int kk = 0; kk < 32; kk++) {
            float a0 = sa[ty][kk], a1 = sa[ty + 16][kk];
            float w0 = swm[tx][kk], w1 = swm[tx + 16][kk];
            acc[0] += a0 * w0; acc[1] += a0 * w1;
            acc[2] += a1 * w0; acc[3] += a1 * w1;
        }
        __syncthreads();
    }
#pragma unroll
    for (int bi = 0; bi < 2; bi++) {
#pragma unroll
        for (int ni = 0; ni < 2; ni++) {
            int m = mBase + ty + bi * 16;
            int n = nBase + tx + ni * 16;
            float v = acc[bi * 2 + ni] + bias[n];
            out[m * HD + n] = fmaxf(v, 0.0f);
        }
    }
}

// ---------------------------------------------------------------------------
// K5: logits = g_z2 @ W3^T + b3   (512 x 8)
// ---------------------------------------------------------------------------
__global__ void k_logits(const float* __restrict__ W3, const float* __restrict__ b3) {
    int idx = blockIdx.x * blockDim.x + threadIdx.x;
    if (idx >= BD * NDD) return;
    int b = idx >> 3, n = idx & 7;
    const float4* z = (const float4*)(g_z2 + b * HD);
    const float4* w = (const float4*)(W3 + n * HD);
    float acc = b3[n];
#pragma unroll 4
    for (int k = 0; k < HD / 4; k++) {
        float4 zv = z[k], wv = w[k];
        acc += zv.x * wv.x + zv.y * wv.y + zv.z * wv.z + zv.w * wv.w;
    }
    g_logits[idx] = acc;
}

// ---------------------------------------------------------------------------
// K6: per-batch head: double log_softmax, top-2 (stable/first-occurrence ties,
//     matching jax.lax.top_k), loss, direction_correct, query build,
//     pred_d_rand passthrough. One block, one thread per b -> deterministic.
// ---------------------------------------------------------------------------
__global__ void k_head(const int* __restrict__ inputs, const int* __restrict__ goal,
                       const int* __restrict__ locd, const float* __restrict__ link,
                       const float* __restrict__ dire, const float* __restrict__ pdr,
                       float* __restrict__ out) {
    int b = threadIdx.x;
    float p[NDD];
    float mx = -1e30f;
#pragma unroll
    for (int n = 0; n < NDD; n++) { p[n] = g_logits[b * NDD + n]; mx = fmaxf(mx, p[n]); }
    float se = 0.0f;
#pragma unroll
    for (int n = 0; n < NDD; n++) se += expf(p[n] - mx);
    float lse = mx + logf(se);
#pragma unroll
    for (int n = 0; n < NDD; n++) p[n] -= lse;

    float mx2 = -1e30f;
#pragma unroll
    for (int n = 0; n < NDD; n++) mx2 = fmaxf(mx2, p[n]);
    float se2 = 0.0f;
#pragma unroll
    for (int n = 0; n < NDD; n++) se2 += expf(p[n] - mx2);
    float lse2 = mx2 + logf(se2);

    int i0 = 0; float v0 = p[0];
#pragma unroll
    for (int n = 1; n < NDD; n++) if (p[n] > v0) { v0 = p[n]; i0 = n; }
    int i1 = -1; float v1 = -1e30f;
#pragma unroll
    for (int n = 0; n < NDD; n++) if (n != i0 && p[n] > v1) { v1 = p[n]; i1 = n; }

    int last = inputs[b * SD + SD - 1];
    int lbl = locd[(size_t)(last - 1) * NED + goal[b]];
    float lossi = -(p[lbl] - lse2);
    int corr = (i0 == lbl) || (i1 == lbl);

    const float* le = link + (size_t)last * EDD;
    const float* d0 = dire + (i0 + 1) * DDD;
    const float* d1 = dire + (i1 + 1) * DDD;
#pragma unroll 4
    for (int k = 0; k < EDD; k++) {
        float q = le[k];
        if (k < DDD) q += 0.5f * (d0[k] + d1[k]);
        g_query[b * EDD + k] = q;
    }

    __shared__ float sl[BD];
    __shared__ int sc[BD];
    sl[b] = lossi; sc[b] = corr;
    __syncthreads();
    for (int st = BD / 2; st > 0; st >>= 1) {
        if (b < st) { sl[b] += sl[b + st]; sc[b] += sc[b + st]; }
        __syncthreads();
    }
    if (b == 0) {
        out[OUT_LOSS] = sl[0] * (5.0f / (float)BD);
        out[OUT_DC] = (float)sc[0];
    }
    for (int i = b; i < BD * NDD * PLD; i += BD) out[OUT_PRED_D + i] = pdr[i];
}

// ---------------------------------------------------------------------------
// K7: sim[b][e] = query[b] . link_emb_w[e+1], written 5x into pred_hard.
//     M=512(b), N=8192(e), K=128. 64x64 tile, 4x4 micro.
// ---------------------------------------------------------------------------
__global__ void k_sim(const float* __restrict__ link, float* __restrict__ out) {
    __shared__ float sq[64][17];
    __shared__ float sl[16][65];   // sl[c][e]
    const int tid = threadIdx.x;
    const int tx = tid & 15, ty = tid >> 4;
    const int eBase = blockIdx.x * 64;
    const int mBase = blockIdx.y * 64;

    float acc[16];
#pragma unroll
    for (int i = 0; i < 16; i++) acc[i] = 0.0f;

    for (int kb = 0; kb < EDD; kb += 16) {
#pragma unroll
        for (int i = 0; i < 4; i++) {
            int idx = tid + i * 256;
            int r = idx >> 4, c = idx & 15;
            sq[r][c] = g_query[(mBase + r) * EDD + kb + c];
            sl[c][r] = link[((size_t)(eBase + r + 1)) * EDD + kb + c];
        }
        __syncthreads();
#pragma unroll
        for (int kk = 0; kk < 16; kk++) {
            float a0 = sq[ty][kk],      a1 = sq[ty + 16][kk];
            float a2 = sq[ty + 32][kk], a3 = sq[ty + 48][kk];
            float w0 = sl[kk][tx],      w1 = sl[kk][tx + 16];
            float w2 = sl[kk][tx + 32], w3 = sl[kk][tx + 48];
            acc[0]  += a0 * w0; acc[1]  += a0 * w1; acc[2]  += a0 * w2; acc[3]  += a0 * w3;
            acc[4]  += a1 * w0; acc[5]  += a1 * w1; acc[6]  += a1 * w2; acc[7]  += a1 * w3;
            acc[8]  += a2 * w0; acc[9]  += a2 * w1; acc[10] += a2 * w2; acc[11] += a2 * w3;
            acc[12] += a3 * w0; acc[13] += a3 * w1; acc[14] += a3 * w2; acc[15] += a3 * w3;
        }
        __syncthreads();
    }
#pragma unroll
    for (int mi = 0; mi < 4; mi++) {
#pragma unroll
        for (int ni = 0; ni < 4; ni++) {
            int b = mBase + ty + mi * 16;
            int e = eBase + tx + ni * 16;
            float v = acc[mi * 4 + ni];
            size_t base = (size_t)b * (NED * PLD) + e;
#pragma unroll
            for (int pl = 0; pl < PLD; pl++) out[base + (size_t)pl * NED] = v;
        }
    }
}

// ---------------------------------------------------------------------------
// Launcher
// ---------------------------------------------------------------------------
extern "C" void kernel_launch(void* const* d_in, const int* in_sizes, int n_in,
                              void* d_out, int out_size) {
    const int*   inputs = (const int*)d_in[0];
    const int*   dirs   = (const int*)d_in[1];
    const int*   goal   = (const int*)d_in[2];
    const int*   locd   = (const int*)d_in[3];
    const float* pdr    = (const float*)d_in[4];
    const float* link   = (const float*)d_in[5];
    const float* dire   = (const float*)d_in[6];
    const float* w_ih   = (const float*)d_in[7];
    const float* b_ih   = (const float*)d_in[8];
    const float* w_hh   = (const float*)d_in[9];
    const float* b_hh   = (const float*)d_in[10];
    const float* W1     = (const float*)d_in[11];
    const float* b1     = (const float*)d_in[12];
    const float* W2     = (const float*)d_in[13];
    const float* b2     = (const float*)d_in[14];
    const float* W3     = (const float*)d_in[15];
    const float* b3     = (const float*)d_in[16];
    float* out = (float*)d_out;

    k_init<<<(BD * HD + 255) / 256, 256>>>();

    // Input projection (gather + GEMM), M=65536 N=2048 K=160
    k_xw<<<dim3((BD * SD) / 64, G4D / 64), 256>>>(inputs, dirs, link, dire, w_ih, b_ih, b_hh);

    // Recurrence: 128 sequential steps
    for (int s = 0; s < SD; s++)
        k_lstm_step<<<dim3(BD / 32, HD / 32), 256>>>(s, w_hh);

    // MLP head (final h is in g_h[0] since S is even)
    k_mlp<<<dim3(BD / 32, HD / 32), 256>>>(0, W1, b1);
    k_mlp<<<dim3(BD / 32, HD / 32), 256>>>(1, W2, b2);
    k_logits<<<(BD * NDD + 255) / 256, 256>>>(W3, b3);

    // Softmax/top2/loss/query + pred_d_rand passthrough (deterministic, 1 block)
    k_head<<<1, BD>>>(inputs, goal, locd, link, dire, pdr, out);

    // Similarity GEMM + 5x tiling into pred_hard
    k_sim<<<dim3(NED / 64, BD / 64), 256>>>(link, out);
}

// round 2
// speedup vs baseline: 1.1813x; 1.1813x over previous
#include <cuda_runtime.h>
#include <math.h>
#include <stdint.h>

// Problem dims
#define BD   512
#define SD   128
#define NED  8192
#define EDD  128
#define DDD  32
#define IND  160
#define HD   512
#define G4D  2048
#define NDD  8
#define PLD  5

#define OUT_PRED_D (512u*8192u*5u)
#define OUT_LOSS   (OUT_PRED_D + 512u*8u*5u)
#define OUT_DC     (OUT_LOSS + 1u)

// ---------------- device scratch (no allocation allowed) ----------------
__device__ float g_xw[134217728];                 // [s][b][2048]
__device__ float g_whh_hi[G4D*HD], g_whh_lo[G4D*HD];
__device__ float g_wih_hi[G4D*IND], g_wih_lo[G4D*IND];
__device__ float g_link_hi[(NED+1)*EDD], g_link_lo[(NED+1)*EDD];
__device__ float g_dir_hi[(NDD+1)*DDD], g_dir_lo[(NDD+1)*DDD];
__device__ float g_hhi[2][BD*HD], g_hlo[2][BD*HD];
__device__ float g_c[BD*HD], g_hfp[BD*HD];
__device__ float g_z1[BD*HD], g_z2[BD*HD];
__device__ float g_logits[BD*NDD], g_query[BD*EDD];

__device__ __forceinline__ float sigmf(float x) { return 1.0f / (1.0f + expf(-x)); }

__device__ __forceinline__ void tf32_split(float v, float& hi, float& lo) {
    unsigned hb; asm("cvt.rna.tf32.f32 %0, %1;" : "=r"(hb) : "f"(v));
    hi = __uint_as_float(hb);
    float r = v - hi;
    unsigned lb; asm("cvt.rna.tf32.f32 %0, %1;" : "=r"(lb) : "f"(r));
    lo = __uint_as_float(lb);
}

#define FB(x) __float_as_uint(x)
#define MMA8(d, a, b) \
    asm volatile("mma.sync.aligned.m16n8k8.row.col.f32.tf32.tf32.f32 " \
                 "{%0,%1,%2,%3},{%4,%5,%6,%7},{%8,%9},{%0,%1,%2,%3};" \
                 : "+f"(d[0]), "+f"(d[1]), "+f"(d[2]), "+f"(d[3]) \
                 : "r"(a[0]), "r"(a[1]), "r"(a[2]), "r"(a[3]), "r"(b[0]), "r"(b[1]))

// ---------------------------------------------------------------------------
// K-init: zero h0(hi/lo), c  (inside the graph: replays must reset state)
// ---------------------------------------------------------------------------
__global__ void k_init() {
    int i = blockIdx.x * blockDim.x + threadIdx.x;
    if (i < BD * HD) { g_hhi[0][i] = 0.0f; g_hlo[0][i] = 0.0f; g_c[i] = 0.0f; }
}

// ---------------------------------------------------------------------------
// K-split: split weights + embeddings into tf32 hi/lo parts
// ---------------------------------------------------------------------------
__global__ void k_split(const float* __restrict__ whh, const float* __restrict__ wih,
                        const float* __restrict__ link, const float* __restrict__ dire) {
    int i = blockIdx.x * blockDim.x + threadIdx.x;
    int stride = gridDim.x * blockDim.x;
    for (int idx = i; idx < G4D*HD; idx += stride) tf32_split(whh[idx], g_whh_hi[idx], g_whh_lo[idx]);
    for (int idx = i; idx < G4D*IND; idx += stride) tf32_split(wih[idx], g_wih_hi[idx], g_wih_lo[idx]);
    for (int idx = i; idx < (NED+1)*EDD; idx += stride) tf32_split(link[idx], g_link_hi[idx], g_link_lo[idx]);
    for (int idx = i; idx < (NDD+1)*DDD; idx += stride) tf32_split(dire[idx], g_dir_hi[idx], g_dir_lo[idx]);
}

// ---------------------------------------------------------------------------
// K-xw: g_xw[m][n] = x[m] @ w_ih^T + b_ih + b_hh  via 3xTF32 tensor cores.
//       M=65536 (m = s*512+b), N=2048, K=160. Block tile 128m x 64n, KC=16.
// ---------------------------------------------------------------------------
__global__ void k_xw(const int* __restrict__ inputs, const int* __restrict__ dirs,
                     const float* __restrict__ b_ih, const float* __restrict__ b_hh) {
    __shared__ float sAhi[16][132], sAlo[16][132];   // [k][m], stride%32==4
    __shared__ float sBhi[16][68],  sBlo[16][68];    // [k][n]
    __shared__ int sL[128], sDi[128];

    const int tid = threadIdx.x;
    const int lane = tid & 31, wid = tid >> 5;
    const int gid = lane >> 2, tig = lane & 3;
    const int mBase = blockIdx.x * 128, nBase = blockIdx.y * 64;
    const int warpM = (wid >> 1) * 32, warpN = (wid & 1) * 32;

    if (tid < 128) {
        int m = mBase + tid;
        int b = m & (BD - 1), s = m >> 9;
        sL[tid]  = inputs[b * SD + s];
        sDi[tid] = dirs[b * SD + s];
    }
    __syncthreads();

    float acc[2][4][4];
#pragma unroll
    for (int a = 0; a < 2; a++)
#pragma unroll
        for (int b = 0; b < 4; b++)
#pragma unroll
            for (int c = 0; c < 4; c++) acc[a][b][c] = 0.0f;

    for (int ch = 0; ch < 10; ch++) {
        int kb = ch * 16;
        // A tile: gather 128 rows x 16 k (hi+lo)
#pragma unroll
        for (int it = 0; it < 2; it++) {
            int idx = tid + it * 256;
            int r = idx >> 2, kq = idx & 3;
            int k = kb + kq * 4;
            float4 vh, vl;
            if (ch < 8) {
                size_t off = (size_t)sL[r] * EDD + k;
                vh = *(const float4*)(g_link_hi + off);
                vl = *(const float4*)(g_link_lo + off);
            } else {
                int off = sDi[r] * DDD + (k - EDD);
                vh = *(const float4*)(g_dir_hi + off);
                vl = *(const float4*)(g_dir_lo + off);
            }
            sAhi[kq*4+0][r] = vh.x; sAhi[kq*4+1][r] = vh.y; sAhi[kq*4+2][r] = vh.z; sAhi[kq*4+3][r] = vh.w;
            sAlo[kq*4+0][r] = vl.x; sAlo[kq*4+1][r] = vl.y; sAlo[kq*4+2][r] = vl.z; sAlo[kq*4+3][r] = vl.w;
        }
        // B tile: 64 n-rows x 16 k
        {
            int r = tid >> 2, kq = tid & 3;
            int k = kb + kq * 4;
            size_t off = (size_t)(nBase + r) * IND + k;
            float4 vh = *(const float4*)(g_wih_hi + off);
            float4 vl = *(const float4*)(g_wih_lo + off);
            sBhi[kq*4+0][r] = vh.x; sBhi[kq*4+1][r] = vh.y; sBhi[kq*4+2][r] = vh.z; sBhi[kq*4+3][r] = vh.w;
            sBlo[kq*4+0][r] = vl.x; sBlo[kq*4+1][r] = vl.y; sBlo[kq*4+2][r] = vl.z; sBlo[kq*4+3][r] = vl.w;
        }
        __syncthreads();
#pragma unroll
        for (int kk = 0; kk < 2; kk++) {
            int k0 = kk * 8;
            uint32_t ahi[2][4], alo[2][4];
#pragma unroll
            for (int mt = 0; mt < 2; mt++) {
                int row = warpM + mt * 16 + gid;
                ahi[mt][0] = FB(sAhi[k0+tig  ][row  ]); ahi[mt][1] = FB(sAhi[k0+tig  ][row+8]);
                ahi[mt][2] = FB(sAhi[k0+tig+4][row  ]); ahi[mt][3] = FB(sAhi[k0+tig+4][row+8]);
                alo[mt][0] = FB(sAlo[k0+tig  ][row  ]); alo[mt][1] = FB(sAlo[k0+tig  ][row+8]);
                alo[mt][2] = FB(sAlo[k0+tig+4][row  ]); alo[mt][3] = FB(sAlo[k0+tig+4][row+8]);
            }
            uint32_t bhi[4][2], blo[4][2];
#pragma unroll
            for (int nt = 0; nt < 4; nt++) {
                int cn = warpN + nt * 8 + gid;
                bhi[nt][0] = FB(sBhi[k0+tig][cn]); bhi[nt][1] = FB(sBhi[k0+tig+4][cn]);
                blo[nt][0] = FB(sBlo[k0+tig][cn]); blo[nt][1] = FB(sBlo[k0+tig+4][cn]);
            }
#pragma unroll
            for (int mt = 0; mt < 2; mt++)
#pragma unroll
                for (int nt = 0; nt < 4; nt++) {
                    MMA8(acc[mt][nt], ahi[mt], bhi[nt]);
                    MMA8(acc[mt][nt], ahi[mt], blo[nt]);
                    MMA8(acc[mt][nt], alo[mt], bhi[nt]);
                }
        }
        __syncthreads();
    }
#pragma unroll
    for (int mt = 0; mt < 2; mt++)
#pragma unroll
        for (int nt = 0; nt < 4; nt++) {
            int r0 = mBase + warpM + mt * 16 + gid;
            int n0 = nBase + warpN + nt * 8 + 2 * tig;
            float bias0 = b_ih[n0] + b_hh[n0];
            float bias1 = b_ih[n0+1] + b_hh[n0+1];
            g_xw[(size_t)r0 * G4D + n0]       = acc[mt][nt][0] + bias0;
            g_xw[(size_t)r0 * G4D + n0 + 1]   = acc[mt][nt][1] + bias1;
            g_xw[(size_t)(r0+8) * G4D + n0]   = acc[mt][nt][2] + bias0;
            g_xw[(size_t)(r0+8) * G4D + n0+1] = acc[mt][nt][3] + bias1;
        }
}

// ---------------------------------------------------------------------------
// K-step: one LSTM step via 3xTF32. gates = h@whh^T + xw; update c, h.
//         Block tile: 64 b x 32 j (x4 gates). grid 8x16=128 CTAs. KC=16.
// ---------------------------------------------------------------------------
__global__ void k_step(int s) {
    __shared__ float sHhi[16][68],  sHlo[16][68];       // [k][b]
    __shared__ float sWhi[4][16][36], sWlo[4][16][36];  // [g][k][j]

    const int tid = threadIdx.x;
    const int lane = tid & 31, wid = tid >> 5;
    const int gid = lane >> 2, tig = lane & 3;
    const int bBase = blockIdx.x * 64, jBase = blockIdx.y * 32;
    const int warpB = (wid >> 2) * 32, warpJ = (wid & 3) * 8;

    const float* __restrict__ hh = g_hhi[s & 1];
    const float* __restrict__ hl = g_hlo[s & 1];

    float acc[4][2][4];
#pragma unroll
    for (int g = 0; g < 4; g++)
#pragma unroll
        for (int mt = 0; mt < 2; mt++)
#pragma unroll
            for (int r = 0; r < 4; r++) acc[g][mt][r] = 0.0f;

    for (int cb = 0; cb < 32; cb++) {
        int kb = cb * 16;
        // H tile: 64 b x 16 k
        {
            int r = tid >> 2, kq = tid & 3;
            int k = kb + kq * 4;
            size_t off = (size_t)(bBase + r) * HD + k;
            float4 vh = *(const float4*)(hh + off);
            float4 vl = *(const float4*)(hl + off);
            sHhi[kq*4+0][r] = vh.x; sHhi[kq*4+1][r] = vh.y; sHhi[kq*4+2][r] = vh.z; sHhi[kq*4+3][r] = vh.w;
            sHlo[kq*4+0][r] = vl.x; sHlo[kq*4+1][r] = vl.y; sHlo[kq*4+2][r] = vl.z; sHlo[kq*4+3][r] = vl.w;
        }
        // W tile: 4 gates x 32 j x 16 k
#pragma unroll
        for (int it = 0; it < 2; it++) {
            int idx = tid + it * 256;
            int g = idx >> 7;
            int rem = idx & 127;
            int j = rem >> 2, kq = rem & 3;
            int k = kb + kq * 4;
            size_t off = (size_t)(g * HD + jBase + j) * HD + k;
            float4 vh = *(const float4*)(g_whh_hi + off);
            float4 vl = *(const float4*)(g_whh_lo + off);
            sWhi[g][kq*4+0][j] = vh.x; sWhi[g][kq*4+1][j] = vh.y; sWhi[g][kq*4+2][j] = vh.z; sWhi[g][kq*4+3][j] = vh.w;
            sWlo[g][kq*4+0][j] = vl.x; sWlo[g][kq*4+1][j] = vl.y; sWlo[g][kq*4+2][j] = vl.z; sWlo[g][kq*4+3][j] = vl.w;
        }
        __syncthreads();
#pragma unroll
        for (int kk = 0; kk < 2; kk++) {
            int k0 = kk * 8;
            uint32_t ahi[2][4], alo[2][4];
#pragma unroll
            for (int mt = 0; mt < 2; mt++) {
                int row = warpB + mt * 16 + gid;
                ahi[mt][0] = FB(sHhi[k0+tig  ][row  ]); ahi[mt][1] = FB(sHhi[k0+tig  ][row+8]);
                ahi[mt][2] = FB(sHhi[k0+tig+4][row  ]); ahi[mt][3] = FB(sHhi[k0+tig+4][row+8]);
                alo[mt][0] = FB(sHlo[k0+tig  ][row  ]); alo[mt][1] = FB(sHlo[k0+tig  ][row+8]);
                alo[mt][2] = FB(sHlo[k0+tig+4][row  ]); alo[mt][3] = FB(sHlo[k0+tig+4][row+8]);
            }
            uint32_t bhi[4][2], blo[4][2];
#pragma unroll
            for (int g = 0; g < 4; g++) {
                int cn = warpJ + gid;
                bhi[g][0] = FB(sWhi[g][k0+tig][cn]); bhi[g][1] = FB(sWhi[g][k0+tig+4][cn]);
                blo[g][0] = FB(sWlo[g][k0+tig][cn]); blo[g][1] = FB(sWlo[g][k0+tig+4][cn]);
            }
#pragma unroll
            for (int g = 0; g < 4; g++)
#pragma unroll
                for (int mt = 0; mt < 2; mt++) {
                    MMA8(acc[g][mt], ahi[mt], bhi[g]);
                    MMA8(acc[g][mt], ahi[mt], blo[g]);
                    MMA8(acc[g][mt], alo[mt], bhi[g]);
                }
        }
        __syncthreads();
    }

    float* __restrict__ hho = g_hhi[(s + 1) & 1];
    float* __restrict__ hlo_ = g_hlo[(s + 1) & 1];
#pragma unroll
    for (int mt = 0; mt < 2; mt++) {
#pragma unroll
        for (int rr = 0; rr < 2; rr++) {
            int b = bBase + warpB + mt * 16 + gid + rr * 8;
#pragma unroll
            for (int cc = 0; cc < 2; cc++) {
                int j = jBase + warpJ + 2 * tig + cc;
                int reg = rr * 2 + cc;
                size_t xo = ((size_t)s * BD + b) * G4D + j;
                float gi = acc[0][mt][reg] + g_xw[xo];
                float gf = acc[1][mt][reg] + g_xw[xo + HD];
                float gg = acc[2][mt][reg] + g_xw[xo + 2 * HD];
                float go = acc[3][mt][reg] + g_xw[xo + 3 * HD];
                float co = g_c[b * HD + j];
                float cn = sigmf(gf) * co + sigmf(gi) * tanhf(gg);
                g_c[b * HD + j] = cn;
                float h = sigmf(go) * tanhf(cn);
                g_hfp[b * HD + j] = h;
                float hi_, lo_;
                tf32_split(h, hi_, lo_);
                hho[b * HD + j] = hi_;
                hlo_[b * HD + j] = lo_;
            }
        }
    }
}

// ---------------------------------------------------------------------------
// MLP layers (fp32, small): z = relu(A @ W^T + b)
// ---------------------------------------------------------------------------
__global__ void k_mlp(int which, const float* __restrict__ W, const float* __restrict__ bias) {
    __shared__ float sa[32][33];
    __shared__ float swm[32][33];
    const int tid = threadIdx.x;
    const int tx = tid & 15, ty = tid >> 4;
    const int mBase = blockIdx.x * 32;
    const int nBase = blockIdx.y * 32;
    const float* __restrict__ A = (which == 0) ? g_hfp : g_z1;
    float* __restrict__ out = (which == 0) ? g_z1 : g_z2;

    float acc[4] = {0.f, 0.f, 0.f, 0.f};
    for (int kb = 0; kb < HD; kb += 32) {
#pragma unroll
        for (int i = 0; i < 4; i++) {
            int idx = tid + i * 256;
            int r = idx >> 5, c = idx & 31;
            sa[r][c]  = A[(mBase + r) * HD + kb + c];
            swm[r][c] = W[(nBase + r) * HD + kb + c];
        }
        __syncthreads();
#pragma unroll
        for (int kk = 0; kk < 32; kk++) {
            float a0 = sa[ty][kk], a1 = sa[ty + 16][kk];
            float w0 = swm[tx][kk], w1 = swm[tx + 16][kk];
            acc[0] += a0 * w0; acc[1] += a0 * w1;
            acc[2] += a1 * w0; acc[3] += a1 * w1;
        }
        __syncthreads();
    }
#pragma unroll
    for (int bi = 0; bi < 2; bi++)
#pragma unroll
        for (int ni = 0; ni < 2; ni++) {
            int m = mBase + ty + bi * 16;
            int n = nBase + tx + ni * 16;
            float v = acc[bi * 2 + ni] + bias[n];
            out[m * HD + n] = fmaxf(v, 0.0f);
        }
}

__global__ void k_logits(const float* __restrict__ W3, const float* __restrict__ b3) {
    int idx = blockIdx.x * blockDim.x + threadIdx.x;
    if (idx >= BD * NDD) return;
    int b = idx >> 3, n = idx & 7;
    const float4* z = (const float4*)(g_z2 + b * HD);
    const float4* w = (const float4*)(W3 + n * HD);
    float acc = b3[n];
#pragma unroll 4
    for (int k = 0; k < HD / 4; k++) {
        float4 zv = z[k], wv = w[k];
        acc += zv.x * wv.x + zv.y * wv.y + zv.z * wv.z + zv.w * wv.w;
    }
    g_logits[idx] = acc;
}

// ---------------------------------------------------------------------------
// Head: double log_softmax, top-2, loss, dc, query; pred_d passthrough
// ---------------------------------------------------------------------------
__global__ void k_head(const int* __restrict__ inputs, const int* __restrict__ goal,
                       const int* __restrict__ locd, const float* __restrict__ link,
                       const float* __restrict__ dire, const float* __restrict__ pdr,
                       float* __restrict__ out) {
    int b = threadIdx.x;
    float p[NDD];
    float mx = -1e30f;
#pragma unroll
    for (int n = 0; n < NDD; n++) { p[n] = g_logits[b * NDD + n]; mx = fmaxf(mx, p[n]); }
    float se = 0.0f;
#pragma unroll
    for (int n = 0; n < NDD; n++) se += expf(p[n] - mx);
    float lse = mx + logf(se);
#pragma unroll
    for (int n = 0; n < NDD; n++) p[n] -= lse;

    float mx2 = -1e30f;
#pragma unroll
    for (int n = 0; n < NDD; n++) mx2 = fmaxf(mx2, p[n]);
    float se2 = 0.0f;
#pragma unroll
    for (int n = 0; n < NDD; n++) se2 += expf(p[n] - mx2);
    float lse2 = mx2 + logf(se2);

    int i0 = 0; float v0 = p[0];
#pragma unroll
    for (int n = 1; n < NDD; n++) if (p[n] > v0) { v0 = p[n]; i0 = n; }
    int i1 = -1; float v1 = -1e30f;
#pragma unroll
    for (int n = 0; n < NDD; n++) if (n != i0 && p[n] > v1) { v1 = p[n]; i1 = n; }

    int last = inputs[b * SD + SD - 1];
    int lbl = locd[(size_t)(last - 1) * NED + goal[b]];
    float lossi = -(p[lbl] - lse2);
    int corr = (i0 == lbl) || (i1 == lbl);

    const float* le = link + (size_t)last * EDD;
    const float* d0 = dire + (i0 + 1) * DDD;
    const float* d1 = dire + (i1 + 1) * DDD;
#pragma unroll 4
    for (int k = 0; k < EDD; k++) {
        float q = le[k];
        if (k < DDD) q += 0.5f * (d0[k] + d1[k]);
        g_query[b * EDD + k] = q;
    }

    __shared__ float sl[BD];
    __shared__ int sc[BD];
    sl[b] = lossi; sc[b] = corr;
    __syncthreads();
    for (int st = BD / 2; st > 0; st >>= 1) {
        if (b < st) { sl[b] += sl[b + st]; sc[b] += sc[b + st]; }
        __syncthreads();
    }
    if (b == 0) {
        out[OUT_LOSS] = sl[0] * (5.0f / (float)BD);
        out[OUT_DC] = (float)sc[0];
    }
    for (int i = b; i < BD * NDD * PLD; i += BD) out[OUT_PRED_D + i] = pdr[i];
}

// ---------------------------------------------------------------------------
// Sim GEMM: sim[b][e] = query[b] . link[e+1], tiled x5 into pred_hard
// ---------------------------------------------------------------------------
__global__ void k_sim(const float* __restrict__ link, float* __restrict__ out) {
    __shared__ float sq[64][17];
    __shared__ float sl[16][65];
    const int tid = threadIdx.x;
    const int tx = tid & 15, ty = tid >> 4;
    const int eBase = blockIdx.x * 64;
    const int mBase = blockIdx.y * 64;

    float acc[16];
#pragma unroll
    for (int i = 0; i < 16; i++) acc[i] = 0.0f;

    for (int kb = 0; kb < EDD; kb += 16) {
#pragma unroll
        for (int i = 0; i < 4; i++) {
            int idx = tid + i * 256;
            int r = idx >> 4, c = idx & 15;
            sq[r][c] = g_query[(mBase + r) * EDD + kb + c];
            sl[c][r] = link[((size_t)(eBase + r + 1)) * EDD + kb + c];
        }
        __syncthreads();
#pragma unroll
        for (int kk = 0; kk < 16; kk++) {
            float a0 = sq[ty][kk],      a1 = sq[ty + 16][kk];
            float a2 = sq[ty + 32][kk], a3 = sq[ty + 48][kk];
            float w0 = sl[kk][tx],      w1 = sl[kk][tx + 16];
            float w2 = sl[kk][tx + 32], w3 = sl[kk][tx + 48];
            acc[0]  += a0 * w0; acc[1]  += a0 * w1; acc[2]  += a0 * w2; acc[3]  += a0 * w3;
            acc[4]  += a1 * w0; acc[5]  += a1 * w1; acc[6]  += a1 * w2; acc[7]  += a1 * w3;
            acc[8]  += a2 * w0; acc[9]  += a2 * w1; acc[10] += a2 * w2; acc[11] += a2 * w3;
            acc[12] += a3 * w0; acc[13] += a3 * w1; acc[14] += a3 * w2; acc[15] += a3 * w3;
        }
        __syncthreads();
    }
#pragma unroll
    for (int mi = 0; mi < 4; mi++)
#pragma unroll
        for (int ni = 0; ni < 4; ni++) {
            int b = mBase + ty + mi * 16;
            int e = eBase + tx + ni * 16;
            float v = acc[mi * 4 + ni];
            size_t base = (size_t)b * (NED * PLD) + e;
#pragma unroll
            for (int pl = 0; pl < PLD; pl++) out[base + (size_t)pl * NED] = v;
        }
}

// ---------------------------------------------------------------------------
// Launcher
// ---------------------------------------------------------------------------
extern "C" void kernel_launch(void* const* d_in, const int* in_sizes, int n_in,
                              void* d_out, int out_size) {
    const int*   inputs = (const int*)d_in[0];
    const int*   dirs   = (const int*)d_in[1];
    const int*   goal   = (const int*)d_in[2];
    const int*   locd   = (const int*)d_in[3];
    const float* pdr    = (const float*)d_in[4];
    const float* link   = (const float*)d_in[5];
    const float* dire   = (const float*)d_in[6];
    const float* w_ih   = (const float*)d_in[7];
    const float* b_ih   = (const float*)d_in[8];
    const float* w_hh   = (const float*)d_in[9];
    const float* b_hh   = (const float*)d_in[10];
    const float* W1     = (const float*)d_in[11];
    const float* b1     = (const float*)d_in[12];
    const float* W2     = (const float*)d_in[13];
    const float* b2     = (const float*)d_in[14];
    const float* W3     = (const float*)d_in[15];
    const float* b3     = (const float*)d_in[16];
    float* out = (float*)d_out;

    k_init<<<(BD * HD + 255) / 256, 256>>>();
    k_split<<<512, 256>>>(w_hh, w_ih, link, dire);

    // Input projection via 3xTF32: grid (65536/128, 2048/64)
    k_xw<<<dim3(512, 32), 256>>>(inputs, dirs, b_ih, b_hh);

    // Recurrence: 128 sequential 3xTF32 steps, grid 8x16 = 128 CTAs
    for (int s = 0; s < SD; s++)
        k_step<<<dim3(8, 16), 256>>>(s);

    // Head (fp32)
    k_mlp<<<dim3(BD / 32, HD / 32), 256>>>(0, W1, b1);
    k_mlp<<<dim3(BD / 32, HD / 32), 256>>>(1, W2, b2);
    k_logits<<<(BD * NDD + 255) / 256, 256>>>(W3, b3);
    k_head<<<1, BD>>>(inputs, goal, locd, link, dire, pdr, out);
    k_sim<<<dim3(NED / 64, BD / 64), 256>>>(link, out);
}

// round 3
// speedup vs baseline: 1.1890x; 1.0065x over previous
#include <cuda_runtime.h>
#include <math.h>
#include <stdint.h>

// Problem dims
#define BD   512
#define SD   128
#define NED  8192
#define EDD  128
#define DDD  32
#define IND  160
#define HD   512
#define G4D  2048
#define NDD  8
#define PLD  5

#define OUT_PRED_D (512u*8192u*5u)
#define OUT_LOSS   (OUT_PRED_D + 512u*8u*5u)
#define OUT_DC     (OUT_LOSS + 1u)

// ---------------- device scratch (no allocation allowed) ----------------
__device__ float g_xw[134217728];                 // [s][b][2048]
__device__ float g_whh_hi[G4D*HD], g_whh_lo[G4D*HD];
__device__ float g_wih_hi[G4D*IND], g_wih_lo[G4D*IND];
__device__ float g_link_hi[(NED+1)*EDD], g_link_lo[(NED+1)*EDD];
__device__ float g_dir_hi[(NDD+1)*DDD], g_dir_lo[(NDD+1)*DDD];
__device__ float g_hhi[2][BD*HD], g_hlo[2][BD*HD];
__device__ float g_c[BD*HD], g_hfp[BD*HD];
__device__ float g_z1[BD*HD], g_z2[BD*HD];
__device__ float g_logits[BD*NDD], g_query[BD*EDD];

__device__ __forceinline__ float sigmf(float x) { return 1.0f / (1.0f + expf(-x)); }

__device__ __forceinline__ void tf32_split(float v, float& hi, float& lo) {
    unsigned hb; asm("cvt.rna.tf32.f32 %0, %1;" : "=r"(hb) : "f"(v));
    hi = __uint_as_float(hb);
    float r = v - hi;
    unsigned lb; asm("cvt.rna.tf32.f32 %0, %1;" : "=r"(lb) : "f"(r));
    lo = __uint_as_float(lb);
}

#define FB(x) __float_as_uint(x)
#define MMA8(d, a, b) \
    asm volatile("mma.sync.aligned.m16n8k8.row.col.f32.tf32.tf32.f32 " \
                 "{%0,%1,%2,%3},{%4,%5,%6,%7},{%8,%9},{%0,%1,%2,%3};" \
                 : "+f"(d[0]), "+f"(d[1]), "+f"(d[2]), "+f"(d[3]) \
                 : "r"(a[0]), "r"(a[1]), "r"(a[2]), "r"(a[3]), "r"(b[0]), "r"(b[1]))

// ---------------------------------------------------------------------------
// K-init: zero h0(hi/lo), c  (inside the graph: replays must reset state)
// ---------------------------------------------------------------------------
__global__ void k_init() {
    int i = blockIdx.x * blockDim.x + threadIdx.x;
    if (i < BD * HD) { g_hhi[0][i] = 0.0f; g_hlo[0][i] = 0.0f; g_c[i] = 0.0f; }
}

// ---------------------------------------------------------------------------
// K-split: split weights + embeddings into tf32 hi/lo parts
// ---------------------------------------------------------------------------
__global__ void k_split(const float* __restrict__ whh, const float* __restrict__ wih,
                        const float* __restrict__ link, const float* __restrict__ dire) {
    int i = blockIdx.x * blockDim.x + threadIdx.x;
    int stride = gridDim.x * blockDim.x;
    for (int idx = i; idx < G4D*HD; idx += stride) tf32_split(whh[idx], g_whh_hi[idx], g_whh_lo[idx]);
    for (int idx = i; idx < G4D*IND; idx += stride) tf32_split(wih[idx], g_wih_hi[idx], g_wih_lo[idx]);
    for (int idx = i; idx < (NED+1)*EDD; idx += stride) tf32_split(link[idx], g_link_hi[idx], g_link_lo[idx]);
    for (int idx = i; idx < (NDD+1)*DDD; idx += stride) tf32_split(dire[idx], g_dir_hi[idx], g_dir_lo[idx]);
}

// ---------------------------------------------------------------------------
// K-xw: g_xw[m][n] = x[m] @ w_ih^T + b_ih + b_hh  via 3xTF32 tensor cores.
//       M=65536 (m = s*512+b), N=2048, K=160. Block tile 128m x 64n, KC=16.
// ---------------------------------------------------------------------------
__global__ void k_xw(const int* __restrict__ inputs, const int* __restrict__ dirs,
                     const float* __restrict__ b_ih, const float* __restrict__ b_hh) {
    __shared__ float sAhi[16][132], sAlo[16][132];   // [k][m], stride%32==4
    __shared__ float sBhi[16][68],  sBlo[16][68];    // [k][n]
    __shared__ int sL[128], sDi[128];

    const int tid = threadIdx.x;
    const int lane = tid & 31, wid = tid >> 5;
    const int gid = lane >> 2, tig = lane & 3;
    const int mBase = blockIdx.x * 128, nBase = blockIdx.y * 64;
    const int warpM = (wid >> 1) * 32, warpN = (wid & 1) * 32;

    if (tid < 128) {
        int m = mBase + tid;
        int b = m & (BD - 1), s = m >> 9;
        sL[tid]  = inputs[b * SD + s];
        sDi[tid] = dirs[b * SD + s];
    }
    __syncthreads();

    float acc[2][4][4];
#pragma unroll
    for (int a = 0; a < 2; a++)
#pragma unroll
        for (int b = 0; b < 4; b++)
#pragma unroll
            for (int c = 0; c < 4; c++) acc[a][b][c] = 0.0f;

    for (int ch = 0; ch < 10; ch++) {
        int kb = ch * 16;
        // A tile: gather 128 rows x 16 k (hi+lo)
#pragma unroll
        for (int it = 0; it < 2; it++) {
            int idx = tid + it * 256;
            int r = idx >> 2, kq = idx & 3;
            int k = kb + kq * 4;
            float4 vh, vl;
            if (ch < 8) {
                size_t off = (size_t)sL[r] * EDD + k;
                vh = *(const float4*)(g_link_hi + off);
                vl = *(const float4*)(g_link_lo + off);
            } else {
                int off = sDi[r] * DDD + (k - EDD);
                vh = *(const float4*)(g_dir_hi + off);
                vl = *(const float4*)(g_dir_lo + off);
            }
            sAhi[kq*4+0][r] = vh.x; sAhi[kq*4+1][r] = vh.y; sAhi[kq*4+2][r] = vh.z; sAhi[kq*4+3][r] = vh.w;
            sAlo[kq*4+0][r] = vl.x; sAlo[kq*4+1][r] = vl.y; sAlo[kq*4+2][r] = vl.z; sAlo[kq*4+3][r] = vl.w;
        }
        // B tile: 64 n-rows x 16 k
        {
            int r = tid >> 2, kq = tid & 3;
            int k = kb + kq * 4;
            size_t off = (size_t)(nBase + r) * IND + k;
            float4 vh = *(const float4*)(g_wih_hi + off);
            float4 vl = *(const float4*)(g_wih_lo + off);
            sBhi[kq*4+0][r] = vh.x; sBhi[kq*4+1][r] = vh.y; sBhi[kq*4+2][r] = vh.z; sBhi[kq*4+3][r] = vh.w;
            sBlo[kq*4+0][r] = vl.x; sBlo[kq*4+1][r] = vl.y; sBlo[kq*4+2][r] = vl.z; sBlo[kq*4+3][r] = vl.w;
        }
        __syncthreads();
#pragma unroll
        for (int kk = 0; kk < 2; kk++) {
            int k0 = kk * 8;
            uint32_t ahi[2][4], alo[2][4];
#pragma unroll
            for (int mt = 0; mt < 2; mt++) {
                int row = warpM + mt * 16 + gid;
                ahi[mt][0] = FB(sAhi[k0+tig  ][row  ]); ahi[mt][1] = FB(sAhi[k0+tig  ][row+8]);
                ahi[mt][2] = FB(sAhi[k0+tig+4][row  ]); ahi[mt][3] = FB(sAhi[k0+tig+4][row+8]);
                alo[mt][0] = FB(sAlo[k0+tig  ][row  ]); alo[mt][1] = FB(sAlo[k0+tig  ][row+8]);
                alo[mt][2] = FB(sAlo[k0+tig+4][row  ]); alo[mt][3] = FB(sAlo[k0+tig+4][row+8]);
            }
            uint32_t bhi[4][2], blo[4][2];
#pragma unroll
            for (int nt = 0; nt < 4; nt++) {
                int cn = warpN + nt * 8 + gid;
                bhi[nt][0] = FB(sBhi[k0+tig][cn]); bhi[nt][1] = FB(sBhi[k0+tig+4][cn]);
                blo[nt][0] = FB(sBlo[k0+tig][cn]); blo[nt][1] = FB(sBlo[k0+tig+4][cn]);
            }
#pragma unroll
            for (int mt = 0; mt < 2; mt++)
#pragma unroll
                for (int nt = 0; nt < 4; nt++) {
                    MMA8(acc[mt][nt], ahi[mt], bhi[nt]);
                    MMA8(acc[mt][nt], ahi[mt], blo[nt]);
                    MMA8(acc[mt][nt], alo[mt], bhi[nt]);
                }
        }
        __syncthreads();
    }
#pragma unroll
    for (int mt = 0; mt < 2; mt++)
#pragma unroll
        for (int nt = 0; nt < 4; nt++) {
            int r0 = mBase + warpM + mt * 16 + gid;
            int n0 = nBase + warpN + nt * 8 + 2 * tig;
            float bias0 = b_ih[n0] + b_hh[n0];
            float bias1 = b_ih[n0+1] + b_hh[n0+1];
            g_xw[(size_t)r0 * G4D + n0]       = acc[mt][nt][0] + bias0;
            g_xw[(size_t)r0 * G4D + n0 + 1]   = acc[mt][nt][1] + bias1;
            g_xw[(size_t)(r0+8) * G4D + n0]   = acc[mt][nt][2] + bias0;
            g_xw[(size_t)(r0+8) * G4D + n0+1] = acc[mt][nt][3] + bias1;
        }
}

// ---------------------------------------------------------------------------
// K-step: one LSTM step via 3xTF32. gates = h@whh^T + xw; update c, h.
//         Block tile: 64 b x 32 j (x4 gates). grid 8x16=128 CTAs. KC=16.
// ---------------------------------------------------------------------------
__global__ void k_step(int s) {
    __shared__ float sHhi[16][68],  sHlo[16][68];       // [k][b]
    __shared__ float sWhi[4][16][36], sWlo[4][16][36];  // [g][k][j]

    const int tid = threadIdx.x;
    const int lane = tid & 31, wid = tid >> 5;
    const int gid = lane >> 2, tig = lane & 3;
    const int bBase = blockIdx.x * 64, jBase = blockIdx.y * 32;
    const int warpB = (wid >> 2) * 32, warpJ = (wid & 3) * 8;

    const float* __restrict__ hh = g_hhi[s & 1];
    const float* __restrict__ hl = g_hlo[s & 1];

    float acc[4][2][4];
#pragma unroll
    for (int g = 0; g < 4; g++)
#pragma unroll
        for (int mt = 0; mt < 2; mt++)
#pragma unroll
            for (int r = 0; r < 4; r++) acc[g][mt][r] = 0.0f;

    for (int cb = 0; cb < 32; cb++) {
        int kb = cb * 16;
        // H tile: 64 b x 16 k
        {
            int r = tid >> 2, kq = tid & 3;
            int k = kb + kq * 4;
            size_t off = (size_t)(bBase + r) * HD + k;
            float4 vh = *(const float4*)(hh + off);
            float4 vl = *(const float4*)(hl + off);
            sHhi[kq*4+0][r] = vh.x; sHhi[kq*4+1][r] = vh.y; sHhi[kq*4+2][r] = vh.z; sHhi[kq*4+3][r] = vh.w;
            sHlo[kq*4+0][r] = vl.x; sHlo[kq*4+1][r] = vl.y; sHlo[kq*4+2][r] = vl.z; sHlo[kq*4+3][r] = vl.w;
        }
        // W tile: 4 gates x 32 j x 16 k
#pragma unroll
        for (int it = 0; it < 2; it++) {
            int idx = tid + it * 256;
            int g = idx >> 7;
            int rem = idx & 127;
            int j = rem >> 2, kq = rem & 3;
            int k = kb + kq * 4;
            size_t off = (size_t)(g * HD + jBase + j) * HD + k;
            float4 vh = *(const float4*)(g_whh_hi + off);
            float4 vl = *(const float4*)(g_whh_lo + off);
            sWhi[g][kq*4+0][j] = vh.x; sWhi[g][kq*4+1][j] = vh.y; sWhi[g][kq*4+2][j] = vh.z; sWhi[g][kq*4+3][j] = vh.w;
            sWlo[g][kq*4+0][j] = vl.x; sWlo[g][kq*4+1][j] = vl.y; sWlo[g][kq*4+2][j] = vl.z; sWlo[g][kq*4+3][j] = vl.w;
        }
        __syncthreads();
#pragma unroll
        for (int kk = 0; kk < 2; kk++) {
            int k0 = kk * 8;
            uint32_t ahi[2][4], alo[2][4];
#pragma unroll
            for (int mt = 0; mt < 2; mt++) {
                int row = warpB + mt * 16 + gid;
                ahi[mt][0] = FB(sHhi[k0+tig  ][row  ]); ahi[mt][1] = FB(sHhi[k0+tig  ][row+8]);
                ahi[mt][2] = FB(sHhi[k0+tig+4][row  ]); ahi[mt][3] = FB(sHhi[k0+tig+4][row+8]);
                alo[mt][0] = FB(sHlo[k0+tig  ][row  ]); alo[mt][1] = FB(sHlo[k0+tig  ][row+8]);
                alo[mt][2] = FB(sHlo[k0+tig+4][row  ]); alo[mt][3] = FB(sHlo[k0+tig+4][row+8]);
            }
            uint32_t bhi[4][2], blo[4][2];
#pragma unroll
            for (int g = 0; g < 4; g++) {
                int cn = warpJ + gid;
                bhi[g][0] = FB(sWhi[g][k0+tig][cn]); bhi[g][1] = FB(sWhi[g][k0+tig+4][cn]);
                blo[g][0] = FB(sWlo[g][k0+tig][cn]); blo[g][1] = FB(sWlo[g][k0+tig+4][cn]);
            }
#pragma unroll
            for (int g = 0; g < 4; g++)
#pragma unroll
                for (int mt = 0; mt < 2; mt++) {
                    MMA8(acc[g][mt], ahi[mt], bhi[g]);
                    MMA8(acc[g][mt], ahi[mt], blo[g]);
                    MMA8(acc[g][mt], alo[mt], bhi[g]);
                }
        }
        __syncthreads();
    }

    float* __restrict__ hho = g_hhi[(s + 1) & 1];
    float* __restrict__ hlo_ = g_hlo[(s + 1) & 1];
#pragma unroll
    for (int mt = 0; mt < 2; mt++) {
#pragma unroll
        for (int rr = 0; rr < 2; rr++) {
            int b = bBase + warpB + mt * 16 + gid + rr * 8;
#pragma unroll
            for (int cc = 0; cc < 2; cc++) {
                int j = jBase + warpJ + 2 * tig + cc;
                int reg = rr * 2 + cc;
                size_t xo = ((size_t)s * BD + b) * G4D + j;
                float gi = acc[0][mt][reg] + g_xw[xo];
                float gf = acc[1][mt][reg] + g_xw[xo + HD];
                float gg = acc[2][mt][reg] + g_xw[xo + 2 * HD];
                float go = acc[3][mt][reg] + g_xw[xo + 3 * HD];
                float co = g_c[b * HD + j];
                float cn = sigmf(gf) * co + sigmf(gi) * tanhf(gg);
                g_c[b * HD + j] = cn;
                float h = sigmf(go) * tanhf(cn);
                g_hfp[b * HD + j] = h;
                float hi_, lo_;
                tf32_split(h, hi_, lo_);
                hho[b * HD + j] = hi_;
                hlo_[b * HD + j] = lo_;
            }
        }
    }
}

// ---------------------------------------------------------------------------
// MLP layers (fp32, small): z = relu(A @ W^T + b)
// ---------------------------------------------------------------------------
__global__ void k_mlp(int which, const float* __restrict__ W, const float* __restrict__ bias) {
    __shared__ float sa[32][33];
    __shared__ float swm[32][33];
    const int tid = threadIdx.x;
    const int tx = tid & 15, ty = tid >> 4;
    const int mBase = blockIdx.x * 32;
    const int nBase = blockIdx.y * 32;
    const float* __restrict__ A = (which == 0) ? g_hfp : g_z1;
    float* __restrict__ out = (which == 0) ? g_z1 : g_z2;

    float acc[4] = {0.f, 0.f, 0.f, 0.f};
    for (int kb = 0; kb < HD; kb += 32) {
#pragma unroll
        for (int i = 0; i < 4; i++) {
            int idx = tid + i * 256;
            int r = idx >> 5, c = idx & 31;
            sa[r][c]  = A[(mBase + r) * HD + kb + c];
            swm[r][c] = W[(nBase + r) * HD + kb + c];
        }
        __syncthreads();
#pragma unroll
        for (int kk = 0; kk < 32; kk++) {
            float a0 = sa[ty][kk], a1 = sa[ty + 16][kk];
            float w0 = swm[tx][kk], w1 = swm[tx + 16][kk];
            acc[0] += a0 * w0; acc[1] += a0 * w1;
            acc[2] += a1 * w0; acc[3] += a1 * w1;
        }
        __syncthreads();
    }
#pragma unroll
    for (int bi = 0; bi < 2; bi++)
#pragma unroll
        for (int ni = 0; ni < 2; ni++) {
            int m = mBase + ty + bi * 16;
            int n = nBase + tx + ni * 16;
            float v = acc[bi * 2 + ni] + bias[n];
            out[m * HD + n] = fmaxf(v, 0.0f);
        }
}

__global__ void k_logits(const float* __restrict__ W3, const float* __restrict__ b3) {
    int idx = blockIdx.x * blockDim.x + threadIdx.x;
    if (idx >= BD * NDD) return;
    int b = idx >> 3, n = idx & 7;
    const float4* z = (const float4*)(g_z2 + b * HD);
    const float4* w = (const float4*)(W3 + n * HD);
    float acc = b3[n];
#pragma unroll 4
    for (int k = 0; k < HD / 4; k++) {
        float4 zv = z[k], wv = w[k];
        acc += zv.x * wv.x + zv.y * wv.y + zv.z * wv.z + zv.w * wv.w;
    }
    g_logits[idx] = acc;
}

// ---------------------------------------------------------------------------
// Head: double log_softmax, top-2, loss, dc, query; pred_d passthrough
// ---------------------------------------------------------------------------
__global__ void k_head(const int* __restrict__ inputs, const int* __restrict__ goal,
                       const int* __restrict__ locd, const float* __restrict__ link,
                       const float* __restrict__ dire, const float* __restrict__ pdr,
                       float* __restrict__ out) {
    int b = threadIdx.x;
    float p[NDD];
    float mx = -1e30f;
#pragma unroll
    for (int n = 0; n < NDD; n++) { p[n] = g_logits[b * NDD + n]; mx = fmaxf(mx, p[n]); }
    float se = 0.0f;
#pragma unroll
    for (int n = 0; n < NDD; n++) se += expf(p[n] - mx);
    float lse = mx + logf(se);
#pragma unroll
    for (int n = 0; n < NDD; n++) p[n] -= lse;

    float mx2 = -1e30f;
#pragma unroll
    for (int n = 0; n < NDD; n++) mx2 = fmaxf(mx2, p[n]);
    float se2 = 0.0f;
#pragma unroll
    for (int n = 0; n < NDD; n++) se2 += expf(p[n] - mx2);
    float lse2 = mx2 + logf(se2);

    int i0 = 0; float v0 = p[0];
#pragma unroll
    for (int n = 1; n < NDD; n++) if (p[n] > v0) { v0 = p[n]; i0 = n; }
    int i1 = -1; float v1 = -1e30f;
#pragma unroll
    for (int n = 0; n < NDD; n++) if (n != i0 && p[n] > v1) { v1 = p[n]; i1 = n; }

    int last = inputs[b * SD + SD - 1];
    int lbl = locd[(size_t)(last - 1) * NED + goal[b]];
    float lossi = -(p[lbl] - lse2);
    int corr = (i0 == lbl) || (i1 == lbl);

    const float* le = link + (size_t)last * EDD;
    const float* d0 = dire + (i0 + 1) * DDD;
    const float* d1 = dire + (i1 + 1) * DDD;
#pragma unroll 4
    for (int k = 0; k < EDD; k++) {
        float q = le[k];
        if (k < DDD) q += 0.5f * (d0[k] + d1[k]);
        g_query[b * EDD + k] = q;
    }

    __shared__ float sl[BD];
    __shared__ int sc[BD];
    sl[b] = lossi; sc[b] = corr;
    __syncthreads();
    for (int st = BD / 2; st > 0; st >>= 1) {
        if (b < st) { sl[b] += sl[b + st]; sc[b] += sc[b + st]; }
        __syncthreads();
    }
    if (b == 0) {
        out[OUT_LOSS] = sl[0] * (5.0f / (float)BD);
        out[OUT_DC] = (float)sc[0];
    }
    for (int i = b; i < BD * NDD * PLD; i += BD) out[OUT_PRED_D + i] = pdr[i];
}

// ---------------------------------------------------------------------------
// Sim GEMM: sim[b][e] = query[b] . link[e+1], tiled x5 into pred_hard
// ---------------------------------------------------------------------------
__global__ void k_sim(const float* __restrict__ link, float* __restrict__ out) {
    __shared__ float sq[64][17];
    __shared__ float sl[16][65];
    const int tid = threadIdx.x;
    const int tx = tid & 15, ty = tid >> 4;
    const int eBase = blockIdx.x * 64;
    const int mBase = blockIdx.y * 64;

    float acc[16];
#pragma unroll
    for (int i = 0; i < 16; i++) acc[i] = 0.0f;

    for (int kb = 0; kb < EDD; kb += 16) {
#pragma unroll
        for (int i = 0; i < 4; i++) {
            int idx = tid + i * 256;
            int r = idx >> 4, c = idx & 15;
            sq[r][c] = g_query[(mBase + r) * EDD + kb + c];
            sl[c][r] = link[((size_t)(eBase + r + 1)) * EDD + kb + c];
        }
        __syncthreads();
#pragma unroll
        for (int kk = 0; kk < 16; kk++) {
            float a0 = sq[ty][kk],      a1 = sq[ty + 16][kk];
            float a2 = sq[ty + 32][kk], a3 = sq[ty + 48][kk];
            float w0 = sl[kk][tx],      w1 = sl[kk][tx + 16];
            float w2 = sl[kk][tx + 32], w3 = sl[kk][tx + 48];
            acc[0]  += a0 * w0; acc[1]  += a0 * w1; acc[2]  += a0 * w2; acc[3]  += a0 * w3;
            acc[4]  += a1 * w0; acc[5]  += a1 * w1; acc[6]  += a1 * w2; acc[7]  += a1 * w3;
            acc[8]  += a2 * w0; acc[9]  += a2 * w1; acc[10] += a2 * w2; acc[11] += a2 * w3;
            acc[12] += a3 * w0; acc[13] += a3 * w1; acc[14] += a3 * w2; acc[15] += a3 * w3;
        }
        __syncthreads();
    }
#pragma unroll
    for (int mi = 0; mi < 4; mi++)
#pragma unroll
        for (int ni = 0; ni < 4; ni++) {
            int b = mBase + ty + mi * 16;
            int e = eBase + tx + ni * 16;
            float v = acc[mi * 4 + ni];
            size_t base = (size_t)b * (NED * PLD) + e;
#pragma unroll
            for (int pl = 0; pl < PLD; pl++) out[base + (size_t)pl * NED] = v;
        }
}

// ---------------------------------------------------------------------------
// Launcher
// ---------------------------------------------------------------------------
extern "C" void kernel_launch(void* const* d_in, const int* in_sizes, int n_in,
                              void* d_out, int out_size) {
    const int*   inputs = (const int*)d_in[0];
    const int*   dirs   = (const int*)d_in[1];
    const int*   goal   = (const int*)d_in[2];
    const int*   locd   = (const int*)d_in[3];
    const float* pdr    = (const float*)d_in[4];
    const float* link   = (const float*)d_in[5];
    const float* dire   = (const float*)d_in[6];
    const float* w_ih   = (const float*)d_in[7];
    const float* b_ih   = (const float*)d_in[8];
    const float* w_hh   = (const float*)d_in[9];
    const float* b_hh   = (const float*)d_in[10];
    const float* W1     = (const float*)d_in[11];
    const float* b1     = (const float*)d_in[12];
    const float* W2     = (const float*)d_in[13];
    const float* b2     = (const float*)d_in[14];
    const float* W3     = (const float*)d_in[15];
    const float* b3     = (const float*)d_in[16];
    float* out = (float*)d_out;

    k_init<<<(BD * HD + 255) / 256, 256>>>();
    k_split<<<512, 256>>>(w_hh, w_ih, link, dire);

    // Input projection via 3xTF32: grid (65536/128, 2048/64)
    k_xw<<<dim3(512, 32), 256>>>(inputs, dirs, b_ih, b_hh);

    // Recurrence: 128 sequential 3xTF32 steps, grid 8x16 = 128 CTAs
    for (int s = 0; s < SD; s++)
        k_step<<<dim3(8, 16), 256>>>(s);

    // Head (fp32)
    k_mlp<<<dim3(BD / 32, HD / 32), 256>>>(0, W1, b1);
    k_mlp<<<dim3(BD / 32, HD / 32), 256>>>(1, W2, b2);
    k_logits<<<(BD * NDD + 255) / 256, 256>>>(W3, b3);
    k_head<<<1, BD>>>(inputs, goal, locd, link, dire, pdr, out);
    k_sim<<<dim3(NED / 64, BD / 64), 256>>>(link, out);
}

// round 5
// speedup vs baseline: 1.7254x; 1.4512x over previous
#include <cuda_runtime.h>
#include <math.h>
#include <stdint.h>

// Problem dims
#define BD   512
#define SD   128
#define NED  8192
#define EDD  128
#define DDD  32
#define IND  160
#define HD   512
#define G4D  2048
#define NDD  8
#define PLD  5

#define OUT_PRED_D (512u*8192u*5u)
#define OUT_LOSS   (OUT_PRED_D + 512u*8u*5u)
#define OUT_DC     (OUT_LOSS + 1u)

// ---------------- device scratch ----------------
__device__ float g_xw[134217728];                 // [s][b][2048]
__device__ float g_whh_hi[G4D*HD], g_whh_lo[G4D*HD];
__device__ float g_wih_hi[G4D*IND], g_wih_lo[G4D*IND];
__device__ float g_link_hi[(NED+1)*EDD], g_link_lo[(NED+1)*EDD];
__device__ float g_dir_hi[(NDD+1)*DDD], g_dir_lo[(NDD+1)*DDD];
__device__ float g_hhi[2][BD*HD], g_hlo[2][BD*HD];
__device__ float g_c[BD*HD], g_hfp[BD*HD];
__device__ float g_z1[BD*HD], g_z2[BD*HD];
__device__ float g_logits[BD*NDD], g_query[BD*EDD];

__device__ __forceinline__ float sigmf(float x) { return 1.0f / (1.0f + expf(-x)); }

__device__ __forceinline__ void tf32_split(float v, float& hi, float& lo) {
    unsigned hb; asm("cvt.rna.tf32.f32 %0, %1;" : "=r"(hb) : "f"(v));
    hi = __uint_as_float(hb);
    float r = v - hi;
    unsigned lb; asm("cvt.rna.tf32.f32 %0, %1;" : "=r"(lb) : "f"(r));
    lo = __uint_as_float(lb);
}

__device__ __forceinline__ uint32_t smem_u32(const void* p) {
    uint32_t a;
    asm("{ .reg .u64 t; cvta.to.shared.u64 t, %1; cvt.u32.u64 %0, t; }" : "=r"(a) : "l"(p));
    return a;
}
__device__ __forceinline__ void cp16(uint32_t dst, const void* src) {
    asm volatile("cp.async.cg.shared.global [%0], [%1], 16;" :: "r"(dst), "l"(src));
}
#define CP_COMMIT() asm volatile("cp.async.commit_group;" ::: "memory")
#define CP_WAIT0()  asm volatile("cp.async.wait_group 0;" ::: "memory")

#define FB(x) __float_as_uint(x)
#define MMA8(d, a, b) \
    asm volatile("mma.sync.aligned.m16n8k8.row.col.f32.tf32.tf32.f32 " \
                 "{%0,%1,%2,%3},{%4,%5,%6,%7},{%8,%9},{%0,%1,%2,%3};" \
                 : "+f"(d[0]), "+f"(d[1]), "+f"(d[2]), "+f"(d[3]) \
                 : "r"(a[0]), "r"(a[1]), "r"(a[2]), "r"(a[3]), "r"(b[0]), "r"(b[1]))

// ---------------------------------------------------------------------------
__global__ void k_init() {
    int i = blockIdx.x * blockDim.x + threadIdx.x;
    if (i < BD * HD) { g_hhi[0][i] = 0.0f; g_hlo[0][i] = 0.0f; g_c[i] = 0.0f; }
}

__global__ void k_split(const float* __restrict__ whh, const float* __restrict__ wih,
                        const float* __restrict__ link, const float* __restrict__ dire) {
    int i = blockIdx.x * blockDim.x + threadIdx.x;
    int stride = gridDim.x * blockDim.x;
    for (int idx = i; idx < G4D*HD; idx += stride) tf32_split(whh[idx], g_whh_hi[idx], g_whh_lo[idx]);
    for (int idx = i; idx < G4D*IND; idx += stride) tf32_split(wih[idx], g_wih_hi[idx], g_wih_lo[idx]);
    for (int idx = i; idx < (NED+1)*EDD; idx += stride) tf32_split(link[idx], g_link_hi[idx], g_link_lo[idx]);
    for (int idx = i; idx < (NDD+1)*DDD; idx += stride) tf32_split(dire[idx], g_dir_hi[idx], g_dir_lo[idx]);
}

// ---------------------------------------------------------------------------
// K-xw (mma.sync 3xTF32): g_xw = x @ w_ih^T + b_ih + b_hh (unpermuted)
// ---------------------------------------------------------------------------
__global__ void k_xw(const int* __restrict__ inputs, const int* __restrict__ dirs,
                     const float* __restrict__ b_ih, const float* __restrict__ b_hh) {
    __shared__ float sAhi[16][132], sAlo[16][132];
    __shared__ float sBhi[16][68],  sBlo[16][68];
    __shared__ int sL[128], sDi[128];

    const int tid = threadIdx.x;
    const int lane = tid & 31, wid = tid >> 5;
    const int gid = lane >> 2, tig = lane & 3;
    const int mBase = blockIdx.x * 128, nBase = blockIdx.y * 64;
    const int warpM = (wid >> 1) * 32, warpN = (wid & 1) * 32;

    if (tid < 128) {
        int m = mBase + tid;
        int b = m & (BD - 1), s = m >> 9;
        sL[tid]  = inputs[b * SD + s];
        sDi[tid] = dirs[b * SD + s];
    }
    __syncthreads();

    float acc[2][4][4];
#pragma unroll
    for (int a = 0; a < 2; a++)
#pragma unroll
        for (int b = 0; b < 4; b++)
#pragma unroll
            for (int c = 0; c < 4; c++) acc[a][b][c] = 0.0f;

    for (int ch = 0; ch < 10; ch++) {
        int kb = ch * 16;
#pragma unroll
        for (int it = 0; it < 2; it++) {
            int idx = tid + it * 256;
            int r = idx >> 2, kq = idx & 3;
            int k = kb + kq * 4;
            float4 vh, vl;
            if (ch < 8) {
                size_t off = (size_t)sL[r] * EDD + k;
                vh = *(const float4*)(g_link_hi + off);
                vl = *(const float4*)(g_link_lo + off);
            } else {
                int off = sDi[r] * DDD + (k - EDD);
                vh = *(const float4*)(g_dir_hi + off);
                vl = *(const float4*)(g_dir_lo + off);
            }
            sAhi[kq*4+0][r] = vh.x; sAhi[kq*4+1][r] = vh.y; sAhi[kq*4+2][r] = vh.z; sAhi[kq*4+3][r] = vh.w;
            sAlo[kq*4+0][r] = vl.x; sAlo[kq*4+1][r] = vl.y; sAlo[kq*4+2][r] = vl.z; sAlo[kq*4+3][r] = vl.w;
        }
        {
            int r = tid >> 2, kq = tid & 3;
            int k = kb + kq * 4;
            size_t off = (size_t)(nBase + r) * IND + k;
            float4 vh = *(const float4*)(g_wih_hi + off);
            float4 vl = *(const float4*)(g_wih_lo + off);
            sBhi[kq*4+0][r] = vh.x; sBhi[kq*4+1][r] = vh.y; sBhi[kq*4+2][r] = vh.z; sBhi[kq*4+3][r] = vh.w;
            sBlo[kq*4+0][r] = vl.x; sBlo[kq*4+1][r] = vl.y; sBlo[kq*4+2][r] = vl.z; sBlo[kq*4+3][r] = vl.w;
        }
        __syncthreads();
#pragma unroll
        for (int kk = 0; kk < 2; kk++) {
            int k0 = kk * 8;
            uint32_t ahi[2][4], alo[2][4];
#pragma unroll
            for (int mt = 0; mt < 2; mt++) {
                int row = warpM + mt * 16 + gid;
                ahi[mt][0] = FB(sAhi[k0+tig  ][row  ]); ahi[mt][1] = FB(sAhi[k0+tig  ][row+8]);
                ahi[mt][2] = FB(sAhi[k0+tig+4][row  ]); ahi[mt][3] = FB(sAhi[k0+tig+4][row+8]);
                alo[mt][0] = FB(sAlo[k0+tig  ][row  ]); alo[mt][1] = FB(sAlo[k0+tig  ][row+8]);
                alo[mt][2] = FB(sAlo[k0+tig+4][row  ]); alo[mt][3] = FB(sAlo[k0+tig+4][row+8]);
            }
            uint32_t bhi[4][2], blo[4][2];
#pragma unroll
            for (int nt = 0; nt < 4; nt++) {
                int cn = warpN + nt * 8 + gid;
                bhi[nt][0] = FB(sBhi[k0+tig][cn]); bhi[nt][1] = FB(sBhi[k0+tig+4][cn]);
                blo[nt][0] = FB(sBlo[k0+tig][cn]); blo[nt][1] = FB(sBlo[k0+tig+4][cn]);
            }
#pragma unroll
            for (int mt = 0; mt < 2; mt++)
#pragma unroll
                for (int nt = 0; nt < 4; nt++) {
                    MMA8(acc[mt][nt], ahi[mt], bhi[nt]);
                    MMA8(acc[mt][nt], ahi[mt], blo[nt]);
                    MMA8(acc[mt][nt], alo[mt], bhi[nt]);
                }
        }
        __syncthreads();
    }
#pragma unroll
    for (int mt = 0; mt < 2; mt++)
#pragma unroll
        for (int nt = 0; nt < 4; nt++) {
            int r0 = mBase + warpM + mt * 16 + gid;
            int n0 = nBase + warpN + nt * 8 + 2 * tig;
            float bias0 = b_ih[n0] + b_hh[n0];
            float bias1 = b_ih[n0+1] + b_hh[n0+1];
            g_xw[(size_t)r0 * G4D + n0]       = acc[mt][nt][0] + bias0;
            g_xw[(size_t)r0 * G4D + n0 + 1]   = acc[mt][nt][1] + bias1;
            g_xw[(size_t)(r0+8) * G4D + n0]   = acc[mt][nt][2] + bias0;
            g_xw[(size_t)(r0+8) * G4D + n0+1] = acc[mt][nt][3] + bias1;
        }
}

// ---------------------------------------------------------------------------
// K-step v3: mma.sync 3xTF32 + cp.async double-buffered pipeline.
//   CTA tile: 64 b x 32 j (x4 gates = 128 N cols). Grid (8,16) = 128 CTAs.
//   8 warps: warpM (2) x warpJ (4); warp tile 32b x 8j x 4gates.
//   K=512 in 16 chunks of 32, depth-2 cp.async pipeline.
//   Fused LSTM cell epilogue (thread owns all 4 gates of its (b,j) pairs).
// ---------------------------------------------------------------------------
#define ASTR 36
#define A_HI 0
#define A_LO 2304
#define B_HI 4608
#define B_LO 9216
#define BUFFL 13824
#define K_STEP_SMEM (2 * BUFFL * 4)

__global__ void __launch_bounds__(256, 1) k_step(int s) {
    extern __shared__ float sm[];
    const uint32_t sbase = smem_u32(sm);
    const int tid = threadIdx.x;
    const int lane = tid & 31, wid = tid >> 5;
    const int gid = lane >> 2, tig = lane & 3;
    const int bBase = blockIdx.x * 64;
    const int jBase = blockIdx.y * 32;
    const int warpM = (wid >> 2) * 32;      // 0 or 32
    const int jW = (wid & 3) * 8;           // 0,8,16,24

    const float* __restrict__ hh = g_hhi[s & 1];
    const float* __restrict__ hl = g_hlo[s & 1];

    float acc[4][2][4];
#pragma unroll
    for (int g = 0; g < 4; g++)
#pragma unroll
        for (int mt = 0; mt < 2; mt++)
#pragma unroll
            for (int r = 0; r < 4; r++) acc[g][mt][r] = 0.0f;

    // ---- chunk loader (cp.async): 3072 x 16B per chunk, 12 per thread ----
    auto load_chunk = [&](int c, int buf) {
        const int kb = c * 32;
        const uint32_t bu = sbase + (uint32_t)buf * (BUFFL * 4);
#pragma unroll
        for (int t = 0; t < 12; t++) {
            int id = tid + t * 256;
            if (id < 1024) {
                int isLo = id >> 9;
                int r = (id & 511) >> 3;
                int g16 = id & 7;
                const float* src = (isLo ? hl : hh) + (size_t)(bBase + r) * HD + kb + g16 * 4;
                uint32_t dst = bu + (uint32_t)(((isLo ? A_LO : A_HI) + r * ASTR + g16 * 4) * 4);
                cp16(dst, src);
            } else {
                int id2 = id - 1024;
                int isLo = id2 >> 10;
                int r = (id2 & 1023) >> 3;          // 0..127: gate*32 + jj
                int g16 = id2 & 7;
                int n = (r >> 5) * HD + jBase + (r & 31);
                const float* src = (isLo ? g_whh_lo : g_whh_hi) + (size_t)n * HD + kb + g16 * 4;
                uint32_t dst = bu + (uint32_t)(((isLo ? B_LO : B_HI) + r * ASTR + g16 * 4) * 4);
                cp16(dst, src);
            }
        }
        CP_COMMIT();
    };

    load_chunk(0, 0);

#pragma unroll 1
    for (int c = 0; c < 16; c++) {
        const int buf = c & 1;
        CP_WAIT0();
        __syncthreads();
        if (c < 15) load_chunk(c + 1, buf ^ 1);

        const float* Ahi = sm + buf * BUFFL + A_HI;
        const float* Alo = sm + buf * BUFFL + A_LO;
        const float* Bhi = sm + buf * BUFFL + B_HI;
        const float* Blo = sm + buf * BUFFL + B_LO;

#pragma unroll
        for (int ksub = 0; ksub < 4; ksub++) {
            const int k0 = ksub * 8;
            uint32_t ahi[2][4], alo[2][4];
#pragma unroll
            for (int mt = 0; mt < 2; mt++) {
                int row = warpM + mt * 16 + gid;
                ahi[mt][0] = FB(Ahi[row * ASTR + k0 + tig]);
                ahi[mt][1] = FB(Ahi[(row + 8) * ASTR + k0 + tig]);
                ahi[mt][2] = FB(Ahi[row * ASTR + k0 + tig + 4]);
                ahi[mt][3] = FB(Ahi[(row + 8) * ASTR + k0 + tig + 4]);
                alo[mt][0] = FB(Alo[row * ASTR + k0 + tig]);
                alo[mt][1] = FB(Alo[(row + 8) * ASTR + k0 + tig]);
                alo[mt][2] = FB(Alo[row * ASTR + k0 + tig + 4]);
                alo[mt][3] = FB(Alo[(row + 8) * ASTR + k0 + tig + 4]);
            }
            uint32_t bhi[4][2], blo[4][2];
#pragma unroll
            for (int g = 0; g < 4; g++) {
                int rn = g * 32 + jW + gid;
                bhi[g][0] = FB(Bhi[rn * ASTR + k0 + tig]);
                bhi[g][1] = FB(Bhi[rn * ASTR + k0 + tig + 4]);
                blo[g][0] = FB(Blo[rn * ASTR + k0 + tig]);
                blo[g][1] = FB(Blo[rn * ASTR + k0 + tig + 4]);
            }
#pragma unroll
            for (int g = 0; g < 4; g++)
#pragma unroll
                for (int mt = 0; mt < 2; mt++) {
                    MMA8(acc[g][mt], ahi[mt], bhi[g]);
                    MMA8(acc[g][mt], ahi[mt], blo[g]);
                    MMA8(acc[g][mt], alo[mt], bhi[g]);
                }
        }
    }

    // ---- fused LSTM cell epilogue ----
    float* __restrict__ hho = g_hhi[(s + 1) & 1];
    float* __restrict__ hlo_ = g_hlo[(s + 1) & 1];
    const int j = jBase + jW + 2 * tig;
#pragma unroll
    for (int mt = 0; mt < 2; mt++) {
#pragma unroll
        for (int rr = 0; rr < 2; rr++) {
            const int b = bBase + warpM + mt * 16 + gid + rr * 8;
            const size_t xrow = ((size_t)s * BD + b) * G4D;
            float2 xi = *(const float2*)(g_xw + xrow + j);
            float2 xf = *(const float2*)(g_xw + xrow + HD + j);
            float2 xg = *(const float2*)(g_xw + xrow + 2 * HD + j);
            float2 xo = *(const float2*)(g_xw + xrow + 3 * HD + j);
            float2 cold = *(const float2*)(g_c + b * HD + j);

            float gi0 = acc[0][mt][rr * 2 + 0] + xi.x, gi1 = acc[0][mt][rr * 2 + 1] + xi.y;
            float gf0 = acc[1][mt][rr * 2 + 0] + xf.x, gf1 = acc[1][mt][rr * 2 + 1] + xf.y;
            float gg0 = acc[2][mt][rr * 2 + 0] + xg.x, gg1 = acc[2][mt][rr * 2 + 1] + xg.y;
            float go0 = acc[3][mt][rr * 2 + 0] + xo.x, go1 = acc[3][mt][rr * 2 + 1] + xo.y;

            float cn0 = sigmf(gf0) * cold.x + sigmf(gi0) * tanhf(gg0);
            float cn1 = sigmf(gf1) * cold.y + sigmf(gi1) * tanhf(gg1);
            float h0 = sigmf(go0) * tanhf(cn0);
            float h1 = sigmf(go1) * tanhf(cn1);

            *(float2*)(g_c + b * HD + j) = make_float2(cn0, cn1);
            float h0h, h0l, h1h, h1l;
            tf32_split(h0, h0h, h0l);
            tf32_split(h1, h1h, h1l);
            *(float2*)(hho + b * HD + j)  = make_float2(h0h, h1h);
            *(float2*)(hlo_ + b * HD + j) = make_float2(h0l, h1l);
            if (s == SD - 1) *(float2*)(g_hfp + b * HD + j) = make_float2(h0, h1);
        }
    }
}

// ---------------------------------------------------------------------------
// MLP layers (fp32)
// ---------------------------------------------------------------------------
__global__ void k_mlp(int which, const float* __restrict__ W, const float* __restrict__ bias) {
    __shared__ float sa[32][33];
    __shared__ float swm[32][33];
    const int tid = threadIdx.x;
    const int tx = tid & 15, ty = tid >> 4;
    const int mBase = blockIdx.x * 32;
    const int nBase = blockIdx.y * 32;
    const float* __restrict__ A = (which == 0) ? g_hfp : g_z1;
    float* __restrict__ out = (which == 0) ? g_z1 : g_z2;

    float acc[4] = {0.f, 0.f, 0.f, 0.f};
    for (int kb = 0; kb < HD; kb += 32) {
#pragma unroll
        for (int i = 0; i < 4; i++) {
            int idx = tid + i * 256;
            int r = idx >> 5, c = idx & 31;
            sa[r][c]  = A[(mBase + r) * HD + kb + c];
            swm[r][c] = W[(nBase + r) * HD + kb + c];
        }
        __syncthreads();
#pragma unroll
        for (int kk = 0; kk < 32; kk++) {
            float a0 = sa[ty][kk], a1 = sa[ty + 16][kk];
            float w0 = swm[tx][kk], w1 = swm[tx + 16][kk];
            acc[0] += a0 * w0; acc[1] += a0 * w1;
            acc[2] += a1 * w0; acc[3] += a1 * w1;
        }
        __syncthreads();
    }
#pragma unroll
    for (int bi = 0; bi < 2; bi++)
#pragma unroll
        for (int ni = 0; ni < 2; ni++) {
            int m = mBase + ty + bi * 16;
            int n = nBase + tx + ni * 16;
            float v = acc[bi * 2 + ni] + bias[n];
            out[m * HD + n] = fmaxf(v, 0.0f);
        }
}

__global__ void k_logits(const float* __restrict__ W3, const float* __restrict__ b3) {
    int idx = blockIdx.x * blockDim.x + threadIdx.x;
    if (idx >= BD * NDD) return;
    int b = idx >> 3, n = idx & 7;
    const float4* z = (const float4*)(g_z2 + b * HD);
    const float4* w = (const float4*)(W3 + n * HD);
    float acc = b3[n];
#pragma unroll 4
    for (int k = 0; k < HD / 4; k++) {
        float4 zv = z[k], wv = w[k];
        acc += zv.x * wv.x + zv.y * wv.y + zv.z * wv.z + zv.w * wv.w;
    }
    g_logits[idx] = acc;
}

// ---------------------------------------------------------------------------
// Head
// ---------------------------------------------------------------------------
__global__ void k_head(const int* __restrict__ inputs, const int* __restrict__ goal,
                       const int* __restrict__ locd, const float* __restrict__ link,
                       const float* __restrict__ dire, const float* __restrict__ pdr,
                       float* __restrict__ out) {
    int b = threadIdx.x;
    float p[NDD];
    float mx = -1e30f;
#pragma unroll
    for (int n = 0; n < NDD; n++) { p[n] = g_logits[b * NDD + n]; mx = fmaxf(mx, p[n]); }
    float se = 0.0f;
#pragma unroll
    for (int n = 0; n < NDD; n++) se += expf(p[n] - mx);
    float lse = mx + logf(se);
#pragma unroll
    for (int n = 0; n < NDD; n++) p[n] -= lse;

    float mx2 = -1e30f;
#pragma unroll
    for (int n = 0; n < NDD; n++) mx2 = fmaxf(mx2, p[n]);
    float se2 = 0.0f;
#pragma unroll
    for (int n = 0; n < NDD; n++) se2 += expf(p[n] - mx2);
    float lse2 = mx2 + logf(se2);

    int i0 = 0; float v0 = p[0];
#pragma unroll
    for (int n = 1; n < NDD; n++) if (p[n] > v0) { v0 = p[n]; i0 = n; }
    int i1 = -1; float v1 = -1e30f;
#pragma unroll
    for (int n = 0; n < NDD; n++) if (n != i0 && p[n] > v1) { v1 = p[n]; i1 = n; }

    int last = inputs[b * SD + SD - 1];
    int lbl = locd[(size_t)(last - 1) * NED + goal[b]];
    float lossi = -(p[lbl] - lse2);
    int corr = (i0 == lbl) || (i1 == lbl);

    const float* le = link + (size_t)last * EDD;
    const float* d0 = dire + (i0 + 1) * DDD;
    const float* d1 = dire + (i1 + 1) * DDD;
#pragma unroll 4
    for (int k = 0; k < EDD; k++) {
        float q = le[k];
        if (k < DDD) q += 0.5f * (d0[k] + d1[k]);
        g_query[b * EDD + k] = q;
    }

    __shared__ float sl[BD];
    __shared__ int sc[BD];
    sl[b] = lossi; sc[b] = corr;
    __syncthreads();
    for (int st = BD / 2; st > 0; st >>= 1) {
        if (b < st) { sl[b] += sl[b + st]; sc[b] += sc[b + st]; }
        __syncthreads();
    }
    if (b == 0) {
        out[OUT_LOSS] = sl[0] * (5.0f / (float)BD);
        out[OUT_DC] = (float)sc[0];
    }
    for (int i = b; i < BD * NDD * PLD; i += BD) out[OUT_PRED_D + i] = pdr[i];
}

// ---------------------------------------------------------------------------
// Sim GEMM
// ---------------------------------------------------------------------------
__global__ void k_sim(const float* __restrict__ link, float* __restrict__ out) {
    __shared__ float sq[64][17];
    __shared__ float sl[16][65];
    const int tid = threadIdx.x;
    const int tx = tid & 15, ty = tid >> 4;
    const int eBase = blockIdx.x * 64;
    const int mBase = blockIdx.y * 64;

    float acc[16];
#pragma unroll
    for (int i = 0; i < 16; i++) acc[i] = 0.0f;

    for (int kb = 0; kb < EDD; kb += 16) {
#pragma unroll
        for (int i = 0; i < 4; i++) {
            int idx = tid + i * 256;
            int r = idx >> 4, c = idx & 15;
            sq[r][c] = g_query[(mBase + r) * EDD + kb + c];
            sl[c][r] = link[((size_t)(eBase + r + 1)) * EDD + kb + c];
        }
        __syncthreads();
#pragma unroll
        for (int kk = 0; kk < 16; kk++) {
            float a0 = sq[ty][kk],      a1 = sq[ty + 16][kk];
            float a2 = sq[ty + 32][kk], a3 = sq[ty + 48][kk];
            float w0 = sl[kk][tx],      w1 = sl[kk][tx + 16];
            float w2 = sl[kk][tx + 32], w3 = sl[kk][tx + 48];
            acc[0]  += a0 * w0; acc[1]  += a0 * w1; acc[2]  += a0 * w2; acc[3]  += a0 * w3;
            acc[4]  += a1 * w0; acc[5]  += a1 * w1; acc[6]  += a1 * w2; acc[7]  += a1 * w3;
            acc[8]  += a2 * w0; acc[9]  += a2 * w1; acc[10] += a2 * w2; acc[11] += a2 * w3;
            acc[12] += a3 * w0; acc[13] += a3 * w1; acc[14] += a3 * w2; acc[15] += a3 * w3;
        }
        __syncthreads();
    }
#pragma unroll
    for (int mi = 0; mi < 4; mi++)
#pragma unroll
        for (int ni = 0; ni < 4; ni++) {
            int b = mBase + ty + mi * 16;
            int e = eBase + tx + ni * 16;
            float v = acc[mi * 4 + ni];
            size_t base = (size_t)b * (NED * PLD) + e;
#pragma unroll
            for (int pl = 0; pl < PLD; pl++) out[base + (size_t)pl * NED] = v;
        }
}

// ---------------------------------------------------------------------------
// Launcher
// ---------------------------------------------------------------------------
extern "C" void kernel_launch(void* const* d_in, const int* in_sizes, int n_in,
                              void* d_out, int out_size) {
    const int*   inputs = (const int*)d_in[0];
    const int*   dirs   = (const int*)d_in[1];
    const int*   goal   = (const int*)d_in[2];
    const int*   locd   = (const int*)d_in[3];
    const float* pdr    = (const float*)d_in[4];
    const float* link   = (const float*)d_in[5];
    const float* dire   = (const float*)d_in[6];
    const float* w_ih   = (const float*)d_in[7];
    const float* b_ih   = (const float*)d_in[8];
    const float* w_hh   = (const float*)d_in[9];
    const float* b_hh   = (const float*)d_in[10];
    const float* W1     = (const float*)d_in[11];
    const float* b1     = (const float*)d_in[12];
    const float* W2     = (const float*)d_in[13];
    const float* b2     = (const float*)d_in[14];
    const float* W3     = (const float*)d_in[15];
    const float* b3     = (const float*)d_in[16];
    float* out = (float*)d_out;

    static int smem_set = 0;
    if (!smem_set) {
        cudaFuncSetAttribute(k_step, cudaFuncAttributeMaxDynamicSharedMemorySize, K_STEP_SMEM);
        smem_set = 1;
    }

    k_init<<<(BD * HD + 255) / 256, 256>>>();
    k_split<<<512, 256>>>(w_hh, w_ih, link, dire);

    k_xw<<<dim3(512, 32), 256>>>(inputs, dirs, b_ih, b_hh);

    for (int s = 0; s < SD; s++)
        k_step<<<dim3(8, 16), 256, K_STEP_SMEM>>>(s);

    k_mlp<<<dim3(BD / 32, HD / 32), 256>>>(0, W1, b1);
    k_mlp<<<dim3(BD / 32, HD / 32), 256>>>(1, W2, b2);
    k_logits<<<(BD * NDD + 255) / 256, 256>>>(W3, b3);
    k_head<<<1, BD>>>(inputs, goal, locd, link, dire, pdr, out);
    k_sim<<<dim3(NED / 64, BD / 64), 256>>>(link, out);
}

// round 6
// speedup vs baseline: 2.2311x; 1.2931x over previous
#include <cuda_runtime.h>
#include <math.h>
#include <stdint.h>

// Problem dims
#define BD   512
#define SD   128
#define NED  8192
#define EDD  128
#define DDD  32
#define IND  160
#define HD   512
#define G4D  2048
#define NDD  8
#define PLD  5

#define OUT_PRED_D (512u*8192u*5u)
#define OUT_LOSS   (OUT_PRED_D + 512u*8u*5u)
#define OUT_DC     (OUT_LOSS + 1u)

// ---------------- device scratch ----------------
__device__ float g_P[(NED+1)*G4D];                // link_emb @ Wih_link^T  (67MB)
__device__ float g_Q[(NDD+1)*G4D];                // dir_emb @ Wih_dir^T + biases
__device__ float g_whh_hi[G4D*HD], g_whh_lo[G4D*HD];
__device__ float g_wih_hi[G4D*IND], g_wih_lo[G4D*IND];
__device__ float g_link_hi[(NED+1)*EDD], g_link_lo[(NED+1)*EDD];
__device__ float g_hhi[2][BD*HD], g_hlo[2][BD*HD];
__device__ float g_c[BD*HD], g_hfp[BD*HD];
__device__ float g_z1[BD*HD], g_z2[BD*HD];
__device__ float g_logits[BD*NDD], g_query[BD*EDD];

__device__ __forceinline__ float sigmf(float x) { return 1.0f / (1.0f + expf(-x)); }

__device__ __forceinline__ void tf32_split(float v, float& hi, float& lo) {
    unsigned hb; asm("cvt.rna.tf32.f32 %0, %1;" : "=r"(hb) : "f"(v));
    hi = __uint_as_float(hb);
    float r = v - hi;
    unsigned lb; asm("cvt.rna.tf32.f32 %0, %1;" : "=r"(lb) : "f"(r));
    lo = __uint_as_float(lb);
}

__device__ __forceinline__ uint32_t smem_u32(const void* p) {
    uint32_t a;
    asm("{ .reg .u64 t; cvta.to.shared.u64 t, %1; cvt.u32.u64 %0, t; }" : "=r"(a) : "l"(p));
    return a;
}
__device__ __forceinline__ void cp16(uint32_t dst, const void* src) {
    asm volatile("cp.async.cg.shared.global [%0], [%1], 16;" :: "r"(dst), "l"(src));
}
#define CP_COMMIT() asm volatile("cp.async.commit_group;" ::: "memory")
#define CP_WAIT0()  asm volatile("cp.async.wait_group 0;" ::: "memory")
#define BARN(id, n) asm volatile("bar.sync %0, %1;" :: "r"(id), "r"(n) : "memory")

#define FB(x) __float_as_uint(x)
#define MMA8(d, a, b) \
    asm volatile("mma.sync.aligned.m16n8k8.row.col.f32.tf32.tf32.f32 " \
                 "{%0,%1,%2,%3},{%4,%5,%6,%7},{%8,%9},{%0,%1,%2,%3};" \
                 : "+f"(d[0]), "+f"(d[1]), "+f"(d[2]), "+f"(d[3]) \
                 : "r"(a[0]), "r"(a[1]), "r"(a[2]), "r"(a[3]), "r"(b[0]), "r"(b[1]))

// ---------------------------------------------------------------------------
__global__ void k_init() {
    int i = blockIdx.x * blockDim.x + threadIdx.x;
    if (i < BD * HD) { g_hhi[0][i] = 0.0f; g_hlo[0][i] = 0.0f; g_c[i] = 0.0f; }
}

__global__ void k_split(const float* __restrict__ whh, const float* __restrict__ wih,
                        const float* __restrict__ link) {
    int i = blockIdx.x * blockDim.x + threadIdx.x;
    int stride = gridDim.x * blockDim.x;
    for (int idx = i; idx < G4D*HD; idx += stride) tf32_split(whh[idx], g_whh_hi[idx], g_whh_lo[idx]);
    for (int idx = i; idx < G4D*IND; idx += stride) tf32_split(wih[idx], g_wih_hi[idx], g_wih_lo[idx]);
    for (int idx = i; idx < (NED+1)*EDD; idx += stride) tf32_split(link[idx], g_link_hi[idx], g_link_lo[idx]);
}

// Q[d][n] = dir_emb[d] . wih[n][128:160] + b_ih[n] + b_hh[n]   (exact fp32)
__global__ void k_q(const float* __restrict__ dire, const float* __restrict__ wih,
                    const float* __restrict__ bih, const float* __restrict__ bhh) {
    int idx = blockIdx.x * blockDim.x + threadIdx.x;
    if (idx >= (NDD+1) * G4D) return;
    int d = idx / G4D, n = idx - d * G4D;
    float acc = bih[n] + bhh[n];
#pragma unroll 8
    for (int k = 0; k < DDD; k++) acc += dire[d * DDD + k] * wih[n * IND + EDD + k];
    g_Q[idx] = acc;
}

// ---------------------------------------------------------------------------
// K-pe: P = link_emb @ Wih_link^T via 3xTF32 mma.sync.
//   M=8193 (65 tiles of 128, guarded), N=2048, K=128.
// ---------------------------------------------------------------------------
__global__ void k_pe() {
    __shared__ float sAhi[16][132], sAlo[16][132];
    __shared__ float sBhi[16][68],  sBlo[16][68];

    const int tid = threadIdx.x;
    const int lane = tid & 31, wid = tid >> 5;
    const int gid = lane >> 2, tig = lane & 3;
    const int mBase = blockIdx.x * 128, nBase = blockIdx.y * 64;
    const int warpM = (wid >> 1) * 32, warpN = (wid & 1) * 32;

    float acc[2][4][4];
#pragma unroll
    for (int a = 0; a < 2; a++)
#pragma unroll
        for (int b = 0; b < 4; b++)
#pragma unroll
            for (int c = 0; c < 4; c++) acc[a][b][c] = 0.0f;

    for (int ch = 0; ch < 8; ch++) {
        int kb = ch * 16;
#pragma unroll
        for (int it = 0; it < 2; it++) {
            int idx = tid + it * 256;
            int r = idx >> 2, kq = idx & 3;
            int k = kb + kq * 4;
            int rr = mBase + r; if (rr > NED) rr = NED;
            size_t off = (size_t)rr * EDD + k;
            float4 vh = *(const float4*)(g_link_hi + off);
            float4 vl = *(const float4*)(g_link_lo + off);
            sAhi[kq*4+0][r] = vh.x; sAhi[kq*4+1][r] = vh.y; sAhi[kq*4+2][r] = vh.z; sAhi[kq*4+3][r] = vh.w;
            sAlo[kq*4+0][r] = vl.x; sAlo[kq*4+1][r] = vl.y; sAlo[kq*4+2][r] = vl.z; sAlo[kq*4+3][r] = vl.w;
        }
        {
            int r = tid >> 2, kq = tid & 3;
            int k = kb + kq * 4;
            size_t off = (size_t)(nBase + r) * IND + k;
            float4 vh = *(const float4*)(g_wih_hi + off);
            float4 vl = *(const float4*)(g_wih_lo + off);
            sBhi[kq*4+0][r] = vh.x; sBhi[kq*4+1][r] = vh.y; sBhi[kq*4+2][r] = vh.z; sBhi[kq*4+3][r] = vh.w;
            sBlo[kq*4+0][r] = vl.x; sBlo[kq*4+1][r] = vl.y; sBlo[kq*4+2][r] = vl.z; sBlo[kq*4+3][r] = vl.w;
        }
        __syncthreads();
#pragma unroll
        for (int kk = 0; kk < 2; kk++) {
            int k0 = kk * 8;
            uint32_t ahi[2][4], alo[2][4];
#pragma unroll
            for (int mt = 0; mt < 2; mt++) {
                int row = warpM + mt * 16 + gid;
                ahi[mt][0] = FB(sAhi[k0+tig  ][row  ]); ahi[mt][1] = FB(sAhi[k0+tig  ][row+8]);
                ahi[mt][2] = FB(sAhi[k0+tig+4][row  ]); ahi[mt][3] = FB(sAhi[k0+tig+4][row+8]);
                alo[mt][0] = FB(sAlo[k0+tig  ][row  ]); alo[mt][1] = FB(sAlo[k0+tig  ][row+8]);
                alo[mt][2] = FB(sAlo[k0+tig+4][row  ]); alo[mt][3] = FB(sAlo[k0+tig+4][row+8]);
            }
            uint32_t bhi[4][2], blo[4][2];
#pragma unroll
            for (int nt = 0; nt < 4; nt++) {
                int cn = warpN + nt * 8 + gid;
                bhi[nt][0] = FB(sBhi[k0+tig][cn]); bhi[nt][1] = FB(sBhi[k0+tig+4][cn]);
                blo[nt][0] = FB(sBlo[k0+tig][cn]); blo[nt][1] = FB(sBlo[k0+tig+4][cn]);
            }
#pragma unroll
            for (int mt = 0; mt < 2; mt++)
#pragma unroll
                for (int nt = 0; nt < 4; nt++) {
                    MMA8(acc[mt][nt], ahi[mt], bhi[nt]);
                    MMA8(acc[mt][nt], ahi[mt], blo[nt]);
                    MMA8(acc[mt][nt], alo[mt], bhi[nt]);
                }
        }
        __syncthreads();
    }
#pragma unroll
    for (int mt = 0; mt < 2; mt++)
#pragma unroll
        for (int nt = 0; nt < 4; nt++) {
            int r0 = mBase + warpM + mt * 16 + gid;
            int n0 = nBase + warpN + nt * 8 + 2 * tig;
            if (r0 < NED + 1) {
                g_P[(size_t)r0 * G4D + n0]     = acc[mt][nt][0];
                g_P[(size_t)r0 * G4D + n0 + 1] = acc[mt][nt][1];
            }
            if (r0 + 8 < NED + 1) {
                g_P[(size_t)(r0+8) * G4D + n0]   = acc[mt][nt][2];
                g_P[(size_t)(r0+8) * G4D + n0+1] = acc[mt][nt][3];
            }
        }
}

// ---------------------------------------------------------------------------
// K-step v4: split-K, 512 threads (2 K-groups x 8 warps), cp.async pipelines.
//   CTA tile: 64 b x 32 j (x4 gates). Grid (8,16). Each kgroup: K half (256).
//   Epilogue: kg0 reduces partials, gathers P/Q rows, fused LSTM cell update.
// ---------------------------------------------------------------------------
#define ASTR 36
#define A_HI 0
#define A_LO 2304
#define B_HI 4608
#define B_LO 9216
#define BUFFL 13824
#define K_STEP_SMEM (4 * BUFFL * 4)

__global__ void __launch_bounds__(512, 1) k_step(int s, const int* __restrict__ inputs,
                                                 const int* __restrict__ dirs) {
    extern __shared__ float sm[];
    const uint32_t sbase = smem_u32(sm);
    const int tid = threadIdx.x;
    const int lane = tid & 31, wid = tid >> 5;
    const int gid = lane >> 2, tig = lane & 3;
    const int kg = wid >> 3;                 // 0/1 K-group
    const int lt = tid & 255;                // thread id within kgroup
    const int wid8 = wid & 7;
    const int bBase = blockIdx.x * 64;
    const int jBase = blockIdx.y * 32;
    const int warpM = (wid8 >> 2) * 32;
    const int jW = (wid8 & 3) * 8;

    const float* __restrict__ hh = g_hhi[s & 1];
    const float* __restrict__ hl = g_hlo[s & 1];

    float acc[4][2][4];
#pragma unroll
    for (int g = 0; g < 4; g++)
#pragma unroll
        for (int mt = 0; mt < 2; mt++)
#pragma unroll
            for (int r = 0; r < 4; r++) acc[g][mt][r] = 0.0f;

    const uint32_t kgbase = sbase + (uint32_t)kg * (2 * BUFFL * 4);

    auto load_chunk = [&](int cc, int buf) {
        const int kb = (kg * 8 + cc) * 32;
        const uint32_t bu = kgbase + (uint32_t)buf * (BUFFL * 4);
#pragma unroll
        for (int t = 0; t < 12; t++) {
            int id = lt + t * 256;
            if (id < 1024) {
                int isLo = id >> 9;
                int r = (id & 511) >> 3;
                int g16 = id & 7;
                const float* src = (isLo ? hl : hh) + (size_t)(bBase + r) * HD + kb + g16 * 4;
                uint32_t dst = bu + (uint32_t)(((isLo ? A_LO : A_HI) + r * ASTR + g16 * 4) * 4);
                cp16(dst, src);
            } else {
                int id2 = id - 1024;
                int isLo = id2 >> 10;
                int r = (id2 & 1023) >> 3;
                int g16 = id2 & 7;
                int n = (r >> 5) * HD + jBase + (r & 31);
                const float* src = (isLo ? g_whh_lo : g_whh_hi) + (size_t)n * HD + kb + g16 * 4;
                uint32_t dst = bu + (uint32_t)(((isLo ? B_LO : B_HI) + r * ASTR + g16 * 4) * 4);
                cp16(dst, src);
            }
        }
        CP_COMMIT();
    };

    load_chunk(0, 0);

#pragma unroll 1
    for (int cc = 0; cc < 8; cc++) {
        const int buf = cc & 1;
        CP_WAIT0();
        BARN(1 + kg, 256);
        if (cc < 7) load_chunk(cc + 1, buf ^ 1);

        const float* base = sm + kg * (2 * BUFFL) + buf * BUFFL;
        const float* Ahi = base + A_HI;
        const float* Alo = base + A_LO;
        const float* Bhi = base + B_HI;
        const float* Blo = base + B_LO;

#pragma unroll
        for (int ksub = 0; ksub < 4; ksub++) {
            const int k0 = ksub * 8;
            uint32_t ahi[2][4], alo[2][4];
#pragma unroll
            for (int mt = 0; mt < 2; mt++) {
                int row = warpM + mt * 16 + gid;
                ahi[mt][0] = FB(Ahi[row * ASTR + k0 + tig]);
                ahi[mt][1] = FB(Ahi[(row + 8) * ASTR + k0 + tig]);
                ahi[mt][2] = FB(Ahi[row * ASTR + k0 + tig + 4]);
                ahi[mt][3] = FB(Ahi[(row + 8) * ASTR + k0 + tig + 4]);
                alo[mt][0] = FB(Alo[row * ASTR + k0 + tig]);
                alo[mt][1] = FB(Alo[(row + 8) * ASTR + k0 + tig]);
                alo[mt][2] = FB(Alo[row * ASTR + k0 + tig + 4]);
                alo[mt][3] = FB(Alo[(row + 8) * ASTR + k0 + tig + 4]);
            }
            uint32_t bhi[4][2], blo[4][2];
#pragma unroll
            for (int g = 0; g < 4; g++) {
                int rn = g * 32 + jW + gid;
                bhi[g][0] = FB(Bhi[rn * ASTR + k0 + tig]);
                bhi[g][1] = FB(Bhi[rn * ASTR + k0 + tig + 4]);
                blo[g][0] = FB(Blo[rn * ASTR + k0 + tig]);
                blo[g][1] = FB(Blo[rn * ASTR + k0 + tig + 4]);
            }
#pragma unroll
            for (int g = 0; g < 4; g++)
#pragma unroll
                for (int mt = 0; mt < 2; mt++) {
                    MMA8(acc[g][mt], ahi[mt], bhi[g]);
                    MMA8(acc[g][mt], ahi[mt], blo[g]);
                    MMA8(acc[g][mt], alo[mt], bhi[g]);
                }
        }
    }

    // ---- cross-kgroup reduction through smem ----
    __syncthreads();
    if (kg == 1) {
        float* red = sm + lt * 32;
#pragma unroll
        for (int g = 0; g < 4; g++)
#pragma unroll
            for (int mt = 0; mt < 2; mt++)
#pragma unroll
                for (int r = 0; r < 4; r++)
                    red[g * 8 + mt * 4 + r] = acc[g][mt][r];
    }
    __syncthreads();
    if (kg == 1) return;

    {
        const float* red = sm + lt * 32;
#pragma unroll
        for (int g = 0; g < 4; g++)
#pragma unroll
            for (int mt = 0; mt < 2; mt++)
#pragma unroll
                for (int r = 0; r < 4; r++)
                    acc[g][mt][r] += red[g * 8 + mt * 4 + r];
    }

    // ---- fused LSTM cell epilogue (kg0 only) ----
    float* __restrict__ hho = g_hhi[(s + 1) & 1];
    float* __restrict__ hlo_ = g_hlo[(s + 1) & 1];
    const int j = jBase + jW + 2 * tig;
#pragma unroll
    for (int mt = 0; mt < 2; mt++) {
#pragma unroll
        for (int rr = 0; rr < 2; rr++) {
            const int b = bBase + warpM + mt * 16 + gid + rr * 8;
            const int inp = inputs[b * SD + s];
            const int dr  = dirs[b * SD + s];
            const float* Pr = g_P + (size_t)inp * G4D + j;
            const float* Qr = g_Q + (size_t)dr * G4D + j;
            float2 pi = *(const float2*)(Pr);
            float2 pf = *(const float2*)(Pr + HD);
            float2 pg = *(const float2*)(Pr + 2 * HD);
            float2 po = *(const float2*)(Pr + 3 * HD);
            float2 qi = *(const float2*)(Qr);
            float2 qf = *(const float2*)(Qr + HD);
            float2 qg = *(const float2*)(Qr + 2 * HD);
            float2 qo = *(const float2*)(Qr + 3 * HD);
            float2 cold = *(const float2*)(g_c + b * HD + j);

            float gi0 = acc[0][mt][rr * 2 + 0] + pi.x + qi.x, gi1 = acc[0][mt][rr * 2 + 1] + pi.y + qi.y;
            float gf0 = acc[1][mt][rr * 2 + 0] + pf.x + qf.x, gf1 = acc[1][mt][rr * 2 + 1] + pf.y + qf.y;
            float gg0 = acc[2][mt][rr * 2 + 0] + pg.x + qg.x, gg1 = acc[2][mt][rr * 2 + 1] + pg.y + qg.y;
            float go0 = acc[3][mt][rr * 2 + 0] + po.x + qo.x, go1 = acc[3][mt][rr * 2 + 1] + po.y + qo.y;

            float cn0 = sigmf(gf0) * cold.x + sigmf(gi0) * tanhf(gg0);
            float cn1 = sigmf(gf1) * cold.y + sigmf(gi1) * tanhf(gg1);
            float h0 = sigmf(go0) * tanhf(cn0);
            float h1 = sigmf(go1) * tanhf(cn1);

            *(float2*)(g_c + b * HD + j) = make_float2(cn0, cn1);
            float h0h, h0l, h1h, h1l;
            tf32_split(h0, h0h, h0l);
            tf32_split(h1, h1h, h1l);
            *(float2*)(hho + b * HD + j)  = make_float2(h0h, h1h);
            *(float2*)(hlo_ + b * HD + j) = make_float2(h0l, h1l);
            if (s == SD - 1) *(float2*)(g_hfp + b * HD + j) = make_float2(h0, h1);
        }
    }
}

// ---------------------------------------------------------------------------
// MLP layers (fp32)
// ---------------------------------------------------------------------------
__global__ void k_mlp(int which, const float* __restrict__ W, const float* __restrict__ bias) {
    __shared__ float sa[32][33];
    __shared__ float swm[32][33];
    const int tid = threadIdx.x;
    const int tx = tid & 15, ty = tid >> 4;
    const int mBase = blockIdx.x * 32;
    const int nBase = blockIdx.y * 32;
    const float* __restrict__ A = (which == 0) ? g_hfp : g_z1;
    float* __restrict__ out = (which == 0) ? g_z1 : g_z2;

    float acc[4] = {0.f, 0.f, 0.f, 0.f};
    for (int kb = 0; kb < HD; kb += 32) {
#pragma unroll
        for (int i = 0; i < 4; i++) {
            int idx = tid + i * 256;
            int r = idx >> 5, c = idx & 31;
            sa[r][c]  = A[(mBase + r) * HD + kb + c];
            swm[r][c] = W[(nBase + r) * HD + kb + c];
        }
        __syncthreads();
#pragma unroll
        for (int kk = 0; kk < 32; kk++) {
            float a0 = sa[ty][kk], a1 = sa[ty + 16][kk];
            float w0 = swm[tx][kk], w1 = swm[tx + 16][kk];
            acc[0] += a0 * w0; acc[1] += a0 * w1;
            acc[2] += a1 * w0; acc[3] += a1 * w1;
        }
        __syncthreads();
    }
#pragma unroll
    for (int bi = 0; bi < 2; bi++)
#pragma unroll
        for (int ni = 0; ni < 2; ni++) {
            int m = mBase + ty + bi * 16;
            int n = nBase + tx + ni * 16;
            float v = acc[bi * 2 + ni] + bias[n];
            out[m * HD + n] = fmaxf(v, 0.0f);
        }
}

__global__ void k_logits(const float* __restrict__ W3, const float* __restrict__ b3) {
    int idx = blockIdx.x * blockDim.x + threadIdx.x;
    if (idx >= BD * NDD) return;
    int b = idx >> 3, n = idx & 7;
    const float4* z = (const float4*)(g_z2 + b * HD);
    const float4* w = (const float4*)(W3 + n * HD);
    float acc = b3[n];
#pragma unroll 4
    for (int k = 0; k < HD / 4; k++) {
        float4 zv = z[k], wv = w[k];
        acc += zv.x * wv.x + zv.y * wv.y + zv.z * wv.z + zv.w * wv.w;
    }
    g_logits[idx] = acc;
}

// ---------------------------------------------------------------------------
// Head
// ---------------------------------------------------------------------------
__global__ void k_head(const int* __restrict__ inputs, const int* __restrict__ goal,
                       const int* __restrict__ locd, const float* __restrict__ link,
                       const float* __restrict__ dire, const float* __restrict__ pdr,
                       float* __restrict__ out) {
    int b = threadIdx.x;
    float p[NDD];
    float mx = -1e30f;
#pragma unroll
    for (int n = 0; n < NDD; n++) { p[n] = g_logits[b * NDD + n]; mx = fmaxf(mx, p[n]); }
    float se = 0.0f;
#pragma unroll
    for (int n = 0; n < NDD; n++) se += expf(p[n] - mx);
    float lse = mx + logf(se);
#pragma unroll
    for (int n = 0; n < NDD; n++) p[n] -= lse;

    float mx2 = -1e30f;
#pragma unroll
    for (int n = 0; n < NDD; n++) mx2 = fmaxf(mx2, p[n]);
    float se2 = 0.0f;
#pragma unroll
    for (int n = 0; n < NDD; n++) se2 += expf(p[n] - mx2);
    float lse2 = mx2 + logf(se2);

    int i0 = 0; float v0 = p[0];
#pragma unroll
    for (int n = 1; n < NDD; n++) if (p[n] > v0) { v0 = p[n]; i0 = n; }
    int i1 = -1; float v1 = -1e30f;
#pragma unroll
    for (int n = 0; n < NDD; n++) if (n != i0 && p[n] > v1) { v1 = p[n]; i1 = n; }

    int last = inputs[b * SD + SD - 1];
    int lbl = locd[(size_t)(last - 1) * NED + goal[b]];
    float lossi = -(p[lbl] - lse2);
    int corr = (i0 == lbl) || (i1 == lbl);

    const float* le = link + (size_t)last * EDD;
    const float* d0 = dire + (i0 + 1) * DDD;
    const float* d1 = dire + (i1 + 1) * DDD;
#pragma unroll 4
    for (int k = 0; k < EDD; k++) {
        float q = le[k];
        if (k < DDD) q += 0.5f * (d0[k] + d1[k]);
        g_query[b * EDD + k] = q;
    }

    __shared__ float sl[BD];
    __shared__ int sc[BD];
    sl[b] = lossi; sc[b] = corr;
    __syncthreads();
    for (int st = BD / 2; st > 0; st >>= 1) {
        if (b < st) { sl[b] += sl[b + st]; sc[b] += sc[b + st]; }
        __syncthreads();
    }
    if (b == 0) {
        out[OUT_LOSS] = sl[0] * (5.0f / (float)BD);
        out[OUT_DC] = (float)sc[0];
    }
    for (int i = b; i < BD * NDD * PLD; i += BD) out[OUT_PRED_D + i] = pdr[i];
}

// ---------------------------------------------------------------------------
// Sim GEMM
// ---------------------------------------------------------------------------
__global__ void k_sim(const float* __restrict__ link, float* __restrict__ out) {
    __shared__ float sq[64][17];
    __shared__ float sl[16][65];
    const int tid = threadIdx.x;
    const int tx = tid & 15, ty = tid >> 4;
    const int eBase = blockIdx.x * 64;
    const int mBase = blockIdx.y * 64;

    float acc[16];
#pragma unroll
    for (int i = 0; i < 16; i++) acc[i] = 0.0f;

    for (int kb = 0; kb < EDD; kb += 16) {
#pragma unroll
        for (int i = 0; i < 4; i++) {
            int idx = tid + i * 256;
            int r = idx >> 4, c = idx & 15;
            sq[r][c] = g_query[(mBase + r) * EDD + kb + c];
            sl[c][r] = link[((size_t)(eBase + r + 1)) * EDD + kb + c];
        }
        __syncthreads();
#pragma unroll
        for (int kk = 0; kk < 16; kk++) {
            float a0 = sq[ty][kk],      a1 = sq[ty + 16][kk];
            float a2 = sq[ty + 32][kk], a3 = sq[ty + 48][kk];
            float w0 = sl[kk][tx],      w1 = sl[kk][tx + 16];
            float w2 = sl[kk][tx + 32], w3 = sl[kk][tx + 48];
            acc[0]  += a0 * w0; acc[1]  += a0 * w1; acc[2]  += a0 * w2; acc[3]  += a0 * w3;
            acc[4]  += a1 * w0; acc[5]  += a1 * w1; acc[6]  += a1 * w2; acc[7]  += a1 * w3;
            acc[8]  += a2 * w0; acc[9]  += a2 * w1; acc[10] += a2 * w2; acc[11] += a2 * w3;
            acc[12] += a3 * w0; acc[13] += a3 * w1; acc[14] += a3 * w2; acc[15] += a3 * w3;
        }
        __syncthreads();
    }
#pragma unroll
    for (int mi = 0; mi < 4; mi++)
#pragma unroll
        for (int ni = 0; ni < 4; ni++) {
            int b = mBase + ty + mi * 16;
            int e = eBase + tx + ni * 16;
            float v = acc[mi * 4 + ni];
            size_t base = (size_t)b * (NED * PLD) + e;
#pragma unroll
            for (int pl = 0; pl < PLD; pl++) out[base + (size_t)pl * NED] = v;
        }
}

// ---------------------------------------------------------------------------
// Launcher
// ---------------------------------------------------------------------------
extern "C" void kernel_launch(void* const* d_in, const int* in_sizes, int n_in,
                              void* d_out, int out_size) {
    const int*   inputs = (const int*)d_in[0];
    const int*   dirs   = (const int*)d_in[1];
    const int*   goal   = (const int*)d_in[2];
    const int*   locd   = (const int*)d_in[3];
    const float* pdr    = (const float*)d_in[4];
    const float* link   = (const float*)d_in[5];
    const float* dire   = (const float*)d_in[6];
    const float* w_ih   = (const float*)d_in[7];
    const float* b_ih   = (const float*)d_in[8];
    const float* w_hh   = (const float*)d_in[9];
    const float* b_hh   = (const float*)d_in[10];
    const float* W1     = (const float*)d_in[11];
    const float* b1     = (const float*)d_in[12];
    const float* W2     = (const float*)d_in[13];
    const float* b2     = (const float*)d_in[14];
    const float* W3     = (const float*)d_in[15];
    const float* b3     = (const float*)d_in[16];
    float* out = (float*)d_out;

    static int smem_set = 0;
    if (!smem_set) {
        cudaFuncSetAttribute(k_step, cudaFuncAttributeMaxDynamicSharedMemorySize, K_STEP_SMEM);
        smem_set = 1;
    }

    k_init<<<(BD * HD + 255) / 256, 256>>>();
    k_split<<<512, 256>>>(w_hh, w_ih, link);
    k_q<<<((NDD+1) * G4D + 255) / 256, 256>>>(dire, w_ih, b_ih, b_hh);

    // P = link_emb @ Wih_link^T : M=8193, N=2048, K=128
    k_pe<<<dim3(65, 32), 256>>>();

    for (int s = 0; s < SD; s++)
        k_step<<<dim3(8, 16), 512, K_STEP_SMEM>>>(s, inputs, dirs);

    k_mlp<<<dim3(BD / 32, HD / 32), 256>>>(0, W1, b1);
    k_mlp<<<dim3(BD / 32, HD / 32), 256>>>(1, W2, b2);
    k_logits<<<(BD * NDD + 255) / 256, 256>>>(W3, b3);
    k_head<<<1, BD>>>(inputs, goal, locd, link, dire, pdr, out);
    k_sim<<<dim3(NED / 64, BD / 64), 256>>>(link, out);
}

// round 7
// speedup vs baseline: 3.0374x; 1.3614x over previous
#include <cuda_runtime.h>
#include <cuda_fp16.h>
#include <math.h>
#include <stdint.h>

// Problem dims
#define BD   512
#define SD   128
#define NED  8192
#define EDD  128
#define DDD  32
#define IND  160
#define HD   512
#define G4D  2048
#define NDD  8
#define PLD  5

#define OUT_PRED_D (512u*8192u*5u)
#define OUT_LOSS   (OUT_PRED_D + 512u*8u*5u)
#define OUT_DC     (OUT_LOSS + 1u)

// ---------------- device scratch ----------------
__device__ float g_P[(NED+1)*G4D];                // link_emb @ Wih_link^T
__device__ float g_Q[(NDD+1)*G4D];                // dir_emb @ Wih_dir^T + biases
__device__ __half g_whh_fhi[G4D*HD], g_whh_flo[G4D*HD];   // fp16 split (lo *1024)
__device__ __half g_hh[2][BD*HD], g_hl[2][BD*HD];          // fp16 split h
__device__ float g_wih_hi[G4D*IND], g_wih_lo[G4D*IND];     // tf32 split (k_pe)
__device__ float g_link_hi[(NED+1)*EDD], g_link_lo[(NED+1)*EDD];
__device__ float g_c[BD*HD], g_hfp[BD*HD];
__device__ float g_z1[BD*HD], g_z2[BD*HD];
__device__ float g_logits[BD*NDD], g_query[BD*EDD];

__device__ __forceinline__ float sigmf(float x) { return 1.0f / (1.0f + expf(-x)); }

__device__ __forceinline__ void tf32_split(float v, float& hi, float& lo) {
    unsigned hb; asm("cvt.rna.tf32.f32 %0, %1;" : "=r"(hb) : "f"(v));
    hi = __uint_as_float(hb);
    float r = v - hi;
    unsigned lb; asm("cvt.rna.tf32.f32 %0, %1;" : "=r"(lb) : "f"(r));
    lo = __uint_as_float(lb);
}
__device__ __forceinline__ void h16_split(float v, __half& hi, __half& lo) {
    hi = __float2half_rn(v);
    float r = v - __half2float(hi);
    lo = __float2half_rn(r * 1024.0f);
}

__device__ __forceinline__ uint32_t smem_u32(const void* p) {
    uint32_t a;
    asm("{ .reg .u64 t; cvta.to.shared.u64 t, %1; cvt.u32.u64 %0, t; }" : "=r"(a) : "l"(p));
    return a;
}
__device__ __forceinline__ void cp16(uint32_t dst, const void* src) {
    asm volatile("cp.async.cg.shared.global [%0], [%1], 16;" :: "r"(dst), "l"(src));
}
#define CP_COMMIT() asm volatile("cp.async.commit_group;" ::: "memory")
#define CP_WAIT0()  asm volatile("cp.async.wait_group 0;" ::: "memory")
#define BARN(id, n) asm volatile("bar.sync %0, %1;" :: "r"(id), "r"(n) : "memory")

#define FB(x) __float_as_uint(x)
// tf32 m16n8k8 (k_pe)
#define MMA8(d, a, b) \
    asm volatile("mma.sync.aligned.m16n8k8.row.col.f32.tf32.tf32.f32 " \
                 "{%0,%1,%2,%3},{%4,%5,%6,%7},{%8,%9},{%0,%1,%2,%3};" \
                 : "+f"(d[0]), "+f"(d[1]), "+f"(d[2]), "+f"(d[3]) \
                 : "r"(a[0]), "r"(a[1]), "r"(a[2]), "r"(a[3]), "r"(b[0]), "r"(b[1]))
// fp16 m16n8k16 (k_step)
#define MMAH(d, a, b) \
    asm volatile("mma.sync.aligned.m16n8k16.row.col.f32.f16.f16.f32 " \
                 "{%0,%1,%2,%3},{%4,%5,%6,%7},{%8,%9},{%0,%1,%2,%3};" \
                 : "+f"(d[0]), "+f"(d[1]), "+f"(d[2]), "+f"(d[3]) \
                 : "r"(a[0]), "r"(a[1]), "r"(a[2]), "r"(a[3]), "r"(b[0]), "r"(b[1]))

// ---------------------------------------------------------------------------
__global__ void k_init() {
    int i = blockIdx.x * blockDim.x + threadIdx.x;
    if (i < BD * HD) {
        g_hh[0][i] = __float2half(0.0f); g_hl[0][i] = __float2half(0.0f);
        g_c[i] = 0.0f;
    }
}

__global__ void k_split(const float* __restrict__ whh, const float* __restrict__ wih,
                        const float* __restrict__ link) {
    int i = blockIdx.x * blockDim.x + threadIdx.x;
    int stride = gridDim.x * blockDim.x;
    for (int idx = i; idx < G4D*HD; idx += stride) {
        __half hi, lo; h16_split(whh[idx], hi, lo);
        g_whh_fhi[idx] = hi; g_whh_flo[idx] = lo;
    }
    for (int idx = i; idx < G4D*IND; idx += stride) tf32_split(wih[idx], g_wih_hi[idx], g_wih_lo[idx]);
    for (int idx = i; idx < (NED+1)*EDD; idx += stride) tf32_split(link[idx], g_link_hi[idx], g_link_lo[idx]);
}

// Q[d][n] = dir_emb[d] . wih[n][128:160] + b_ih[n] + b_hh[n]   (exact fp32)
__global__ void k_q(const float* __restrict__ dire, const float* __restrict__ wih,
                    const float* __restrict__ bih, const float* __restrict__ bhh) {
    int idx = blockIdx.x * blockDim.x + threadIdx.x;
    if (idx >= (NDD+1) * G4D) return;
    int d = idx / G4D, n = idx - d * G4D;
    float acc = bih[n] + bhh[n];
#pragma unroll 8
    for (int k = 0; k < DDD; k++) acc += dire[d * DDD + k] * wih[n * IND + EDD + k];
    g_Q[idx] = acc;
}

// ---------------------------------------------------------------------------
// K-pe: P = link_emb @ Wih_link^T via 3xTF32 mma.sync. M=8193, N=2048, K=128.
// ---------------------------------------------------------------------------
__global__ void k_pe() {
    __shared__ float sAhi[16][132], sAlo[16][132];
    __shared__ float sBhi[16][68],  sBlo[16][68];

    const int tid = threadIdx.x;
    const int lane = tid & 31, wid = tid >> 5;
    const int gid = lane >> 2, tig = lane & 3;
    const int mBase = blockIdx.x * 128, nBase = blockIdx.y * 64;
    const int warpM = (wid >> 1) * 32, warpN = (wid & 1) * 32;

    float acc[2][4][4];
#pragma unroll
    for (int a = 0; a < 2; a++)
#pragma unroll
        for (int b = 0; b < 4; b++)
#pragma unroll
            for (int c = 0; c < 4; c++) acc[a][b][c] = 0.0f;

    for (int ch = 0; ch < 8; ch++) {
        int kb = ch * 16;
#pragma unroll
        for (int it = 0; it < 2; it++) {
            int idx = tid + it * 256;
            int r = idx >> 2, kq = idx & 3;
            int k = kb + kq * 4;
            int rr = mBase + r; if (rr > NED) rr = NED;
            size_t off = (size_t)rr * EDD + k;
            float4 vh = *(const float4*)(g_link_hi + off);
            float4 vl = *(const float4*)(g_link_lo + off);
            sAhi[kq*4+0][r] = vh.x; sAhi[kq*4+1][r] = vh.y; sAhi[kq*4+2][r] = vh.z; sAhi[kq*4+3][r] = vh.w;
            sAlo[kq*4+0][r] = vl.x; sAlo[kq*4+1][r] = vl.y; sAlo[kq*4+2][r] = vl.z; sAlo[kq*4+3][r] = vl.w;
        }
        {
            int r = tid >> 2, kq = tid & 3;
            int k = kb + kq * 4;
            size_t off = (size_t)(nBase + r) * IND + k;
            float4 vh = *(const float4*)(g_wih_hi + off);
            float4 vl = *(const float4*)(g_wih_lo + off);
            sBhi[kq*4+0][r] = vh.x; sBhi[kq*4+1][r] = vh.y; sBhi[kq*4+2][r] = vh.z; sBhi[kq*4+3][r] = vh.w;
            sBlo[kq*4+0][r] = vl.x; sBlo[kq*4+1][r] = vl.y; sBlo[kq*4+2][r] = vl.z; sBlo[kq*4+3][r] = vl.w;
        }
        __syncthreads();
#pragma unroll
        for (int kk = 0; kk < 2; kk++) {
            int k0 = kk * 8;
            uint32_t ahi[2][4], alo[2][4];
#pragma unroll
            for (int mt = 0; mt < 2; mt++) {
                int row = warpM + mt * 16 + gid;
                ahi[mt][0] = FB(sAhi[k0+tig  ][row  ]); ahi[mt][1] = FB(sAhi[k0+tig  ][row+8]);
                ahi[mt][2] = FB(sAhi[k0+tig+4][row  ]); ahi[mt][3] = FB(sAhi[k0+tig+4][row+8]);
                alo[mt][0] = FB(sAlo[k0+tig  ][row  ]); alo[mt][1] = FB(sAlo[k0+tig  ][row+8]);
                alo[mt][2] = FB(sAlo[k0+tig+4][row  ]); alo[mt][3] = FB(sAlo[k0+tig+4][row+8]);
            }
            uint32_t bhi[4][2], blo[4][2];
#pragma unroll
            for (int nt = 0; nt < 4; nt++) {
                int cn = warpN + nt * 8 + gid;
                bhi[nt][0] = FB(sBhi[k0+tig][cn]); bhi[nt][1] = FB(sBhi[k0+tig+4][cn]);
                blo[nt][0] = FB(sBlo[k0+tig][cn]); blo[nt][1] = FB(sBlo[k0+tig+4][cn]);
            }
#pragma unroll
            for (int mt = 0; mt < 2; mt++)
#pragma unroll
                for (int nt = 0; nt < 4; nt++) {
                    MMA8(acc[mt][nt], ahi[mt], bhi[nt]);
                    MMA8(acc[mt][nt], ahi[mt], blo[nt]);
                    MMA8(acc[mt][nt], alo[mt], bhi[nt]);
                }
        }
        __syncthreads();
    }
#pragma unroll
    for (int mt = 0; mt < 2; mt++)
#pragma unroll
        for (int nt = 0; nt < 4; nt++) {
            int r0 = mBase + warpM + mt * 16 + gid;
            int n0 = nBase + warpN + nt * 8 + 2 * tig;
            if (r0 < NED + 1) {
                g_P[(size_t)r0 * G4D + n0]     = acc[mt][nt][0];
                g_P[(size_t)r0 * G4D + n0 + 1] = acc[mt][nt][1];
            }
            if (r0 + 8 < NED + 1) {
                g_P[(size_t)(r0+8) * G4D + n0]   = acc[mt][nt][2];
                g_P[(size_t)(r0+8) * G4D + n0+1] = acc[mt][nt][3];
            }
        }
}

// ---------------------------------------------------------------------------
// K-step v5: fp16 2-term split, 3-pass m16n8k16, split-K 512 threads.
//   CTA tile: 64 b x 32 j (x4 gates). Grid (8,16). kgroup = K half (256).
//   Twin accumulators: D = hi*hi ; E = hi*lo + lo*hi (lo scaled by 2^10).
//   Epilogue: reduce partials, gather P/Q rows, fused LSTM cell update.
// ---------------------------------------------------------------------------
#define ASTR 20          // words (fp16x2) per row incl. pad
#define AW_HI 0
#define AW_LO 1280
#define BW_HI 2560
#define BW_LO 5120
#define BUFW  7680       // words per buffer
#define K_STEP_SMEM (4 * BUFW * 4)

__global__ void __launch_bounds__(512, 1) k_step(int s, const int* __restrict__ inputs,
                                                 const int* __restrict__ dirs) {
    extern __shared__ float sm[];
    const uint32_t sbase = smem_u32(sm);
    const uint32_t* smw = (const uint32_t*)sm;
    const int tid = threadIdx.x;
    const int lane = tid & 31, wid = tid >> 5;
    const int gid = lane >> 2, tig = lane & 3;
    const int kg = wid >> 3;
    const int lt = tid & 255;
    const int wid8 = wid & 7;
    const int bBase = blockIdx.x * 64;
    const int jBase = blockIdx.y * 32;
    const int warpM = (wid8 >> 2) * 32;
    const int jW = (wid8 & 3) * 8;

    const __half* __restrict__ hh = g_hh[s & 1];
    const __half* __restrict__ hl = g_hl[s & 1];

    float D[4][2][4], E[4][2][4];
#pragma unroll
    for (int g = 0; g < 4; g++)
#pragma unroll
        for (int mt = 0; mt < 2; mt++)
#pragma unroll
            for (int r = 0; r < 4; r++) { D[g][mt][r] = 0.0f; E[g][mt][r] = 0.0f; }

    const uint32_t kgbase = sbase + (uint32_t)kg * (2 * BUFW * 4);

    // per chunk per kgroup: A 128 rows x 64B (hi+lo), B 256 rows x 64B = 1536 x 16B
    auto load_chunk = [&](int cc, int buf) {
        const int kb = (kg * 8 + cc) * 32;
        const uint32_t bu = kgbase + (uint32_t)buf * (BUFW * 4);
#pragma unroll
        for (int t = 0; t < 6; t++) {
            int id = lt + t * 256;
            if (id < 512) {
                int isLo = id >> 8;
                int rem = id & 255;
                int r = rem >> 2, t4 = rem & 3;
                const __half* src = (isLo ? hl : hh) + (size_t)(bBase + r) * HD + kb + t4 * 8;
                uint32_t dst = bu + (uint32_t)(((isLo ? AW_LO : AW_HI) + r * ASTR + t4 * 4) * 4);
                cp16(dst, src);
            } else {
                int id2 = id - 512;
                int isLo = id2 >> 9;
                int rem = id2 & 511;
                int r = rem >> 2, t4 = rem & 3;
                int n = (r >> 5) * HD + jBase + (r & 31);
                const __half* src = (isLo ? g_whh_flo : g_whh_fhi) + (size_t)n * HD + kb + t4 * 8;
                uint32_t dst = bu + (uint32_t)(((isLo ? BW_LO : BW_HI) + r * ASTR + t4 * 4) * 4);
                cp16(dst, src);
            }
        }
        CP_COMMIT();
    };

    load_chunk(0, 0);

#pragma unroll 1
    for (int cc = 0; cc < 8; cc++) {
        const int buf = cc & 1;
        CP_WAIT0();
        BARN(1 + kg, 256);
        if (cc < 7) load_chunk(cc + 1, buf ^ 1);

        const uint32_t* base = smw + kg * (2 * BUFW) + buf * BUFW;
        const uint32_t* Ahi = base + AW_HI;
        const uint32_t* Alo = base + AW_LO;
        const uint32_t* Bhi = base + BW_HI;
        const uint32_t* Blo = base + BW_LO;

#pragma unroll
        for (int ksub = 0; ksub < 2; ksub++) {
            const int k0 = ksub * 8;
            uint32_t ahi[2][4], alo[2][4];
#pragma unroll
            for (int mt = 0; mt < 2; mt++) {
                int row = warpM + mt * 16 + gid;
                ahi[mt][0] = Ahi[row * ASTR + k0 + tig];
                ahi[mt][1] = Ahi[(row + 8) * ASTR + k0 + tig];
                ahi[mt][2] = Ahi[row * ASTR + k0 + tig + 4];
                ahi[mt][3] = Ahi[(row + 8) * ASTR + k0 + tig + 4];
                alo[mt][0] = Alo[row * ASTR + k0 + tig];
                alo[mt][1] = Alo[(row + 8) * ASTR + k0 + tig];
                alo[mt][2] = Alo[row * ASTR + k0 + tig + 4];
                alo[mt][3] = Alo[(row + 8) * ASTR + k0 + tig + 4];
            }
            uint32_t bhi[4][2], blo[4][2];
#pragma unroll
            for (int g = 0; g < 4; g++) {
                int rn = g * 32 + jW + gid;
                bhi[g][0] = Bhi[rn * ASTR + k0 + tig];
                bhi[g][1] = Bhi[rn * ASTR + k0 + tig + 4];
                blo[g][0] = Blo[rn * ASTR + k0 + tig];
                blo[g][1] = Blo[rn * ASTR + k0 + tig + 4];
            }
#pragma unroll
            for (int g = 0; g < 4; g++)
#pragma unroll
                for (int mt = 0; mt < 2; mt++) {
                    MMAH(D[g][mt], ahi[mt], bhi[g]);
                    MMAH(E[g][mt], ahi[mt], blo[g]);
                    MMAH(E[g][mt], alo[mt], bhi[g]);
                }
        }
    }

    // fold E into D with 2^-10 scale
#pragma unroll
    for (int g = 0; g < 4; g++)
#pragma unroll
        for (int mt = 0; mt < 2; mt++)
#pragma unroll
            for (int r = 0; r < 4; r++)
                D[g][mt][r] += E[g][mt][r] * 0.0009765625f;

    // ---- cross-kgroup reduction through smem ----
    __syncthreads();
    if (kg == 1) {
        float* red = sm + lt * 32;
#pragma unroll
        for (int g = 0; g < 4; g++)
#pragma unroll
            for (int mt = 0; mt < 2; mt++)
#pragma unroll
                for (int r = 0; r < 4; r++)
                    red[g * 8 + mt * 4 + r] = D[g][mt][r];
    }
    __syncthreads();
    if (kg == 1) return;

    {
        const float* red = sm + lt * 32;
#pragma unroll
        for (int g = 0; g < 4; g++)
#pragma unroll
            for (int mt = 0; mt < 2; mt++)
#pragma unroll
                for (int r = 0; r < 4; r++)
                    D[g][mt][r] += red[g * 8 + mt * 4 + r];
    }

    // ---- fused LSTM cell epilogue (kg0 only) ----
    __half* __restrict__ hho = g_hh[(s + 1) & 1];
    __half* __restrict__ hlo_ = g_hl[(s + 1) & 1];
    const int j = jBase + jW + 2 * tig;
#pragma unroll
    for (int mt = 0; mt < 2; mt++) {
#pragma unroll
        for (int rr = 0; rr < 2; rr++) {
            const int b = bBase + warpM + mt * 16 + gid + rr * 8;
            const int inp = inputs[b * SD + s];
            const int dr  = dirs[b * SD + s];
            const float* Pr = g_P + (size_t)inp * G4D + j;
            const float* Qr = g_Q + (size_t)dr * G4D + j;
            float2 pi = *(const float2*)(Pr);
            float2 pf = *(const float2*)(Pr + HD);
            float2 pg = *(const float2*)(Pr + 2 * HD);
            float2 po = *(const float2*)(Pr + 3 * HD);
            float2 qi = *(const float2*)(Qr);
            float2 qf = *(const float2*)(Qr + HD);
            float2 qg = *(const float2*)(Qr + 2 * HD);
            float2 qo = *(const float2*)(Qr + 3 * HD);
            float2 cold = *(const float2*)(g_c + b * HD + j);

            float gi0 = D[0][mt][rr*2+0] + pi.x + qi.x, gi1 = D[0][mt][rr*2+1] + pi.y + qi.y;
            float gf0 = D[1][mt][rr*2+0] + pf.x + qf.x, gf1 = D[1][mt][rr*2+1] + pf.y + qf.y;
            float gg0 = D[2][mt][rr*2+0] + pg.x + qg.x, gg1 = D[2][mt][rr*2+1] + pg.y + qg.y;
            float go0 = D[3][mt][rr*2+0] + po.x + qo.x, go1 = D[3][mt][rr*2+1] + po.y + qo.y;

            float cn0 = sigmf(gf0) * cold.x + sigmf(gi0) * tanhf(gg0);
            float cn1 = sigmf(gf1) * cold.y + sigmf(gi1) * tanhf(gg1);
            float h0 = sigmf(go0) * tanhf(cn0);
            float h1 = sigmf(go1) * tanhf(cn1);

            *(float2*)(g_c + b * HD + j) = make_float2(cn0, cn1);
            __half h0h, h0l, h1h, h1l;
            h16_split(h0, h0h, h0l);
            h16_split(h1, h1h, h1l);
            *(__half2*)(hho + b * HD + j)  = __halves2half2(h0h, h1h);
            *(__half2*)(hlo_ + b * HD + j) = __halves2half2(h0l, h1l);
            if (s == SD - 1) *(float2*)(g_hfp + b * HD + j) = make_float2(h0, h1);
        }
    }
}

// ---------------------------------------------------------------------------
// MLP layers (fp32)
// ---------------------------------------------------------------------------
__global__ void k_mlp(int which, const float* __restrict__ W, const float* __restrict__ bias) {
    __shared__ float sa[32][33];
    __shared__ float swm[32][33];
    const int tid = threadIdx.x;
    const int tx = tid & 15, ty = tid >> 4;
    const int mBase = blockIdx.x * 32;
    const int nBase = blockIdx.y * 32;
    const float* __restrict__ A = (which == 0) ? g_hfp : g_z1;
    float* __restrict__ out = (which == 0) ? g_z1 : g_z2;

    float acc[4] = {0.f, 0.f, 0.f, 0.f};
    for (int kb = 0; kb < HD; kb += 32) {
#pragma unroll
        for (int i = 0; i < 4; i++) {
            int idx = tid + i * 256;
            int r = idx >> 5, c = idx & 31;
            sa[r][c]  = A[(mBase + r) * HD + kb + c];
            swm[r][c] = W[(nBase + r) * HD + kb + c];
        }
        __syncthreads();
#pragma unroll
        for (int kk = 0; kk < 32; kk++) {
            float a0 = sa[ty][kk], a1 = sa[ty + 16][kk];
            float w0 = swm[tx][kk], w1 = swm[tx + 16][kk];
            acc[0] += a0 * w0; acc[1] += a0 * w1;
            acc[2] += a1 * w0; acc[3] += a1 * w1;
        }
        __syncthreads();
    }
#pragma unroll
    for (int bi = 0; bi < 2; bi++)
#pragma unroll
        for (int ni = 0; ni < 2; ni++) {
            int m = mBase + ty + bi * 16;
            int n = nBase + tx + ni * 16;
            float v = acc[bi * 2 + ni] + bias[n];
            out[m * HD + n] = fmaxf(v, 0.0f);
        }
}

__global__ void k_logits(const float* __restrict__ W3, const float* __restrict__ b3) {
    int idx = blockIdx.x * blockDim.x + threadIdx.x;
    if (idx >= BD * NDD) return;
    int b = idx >> 3, n = idx & 7;
    const float4* z = (const float4*)(g_z2 + b * HD);
    const float4* w = (const float4*)(W3 + n * HD);
    float acc = b3[n];
#pragma unroll 4
    for (int k = 0; k < HD / 4; k++) {
        float4 zv = z[k], wv = w[k];
        acc += zv.x * wv.x + zv.y * wv.y + zv.z * wv.z + zv.w * wv.w;
    }
    g_logits[idx] = acc;
}

// ---------------------------------------------------------------------------
// Head
// ---------------------------------------------------------------------------
__global__ void k_head(const int* __restrict__ inputs, const int* __restrict__ goal,
                       const int* __restrict__ locd, const float* __restrict__ link,
                       const float* __restrict__ dire, const float* __restrict__ pdr,
                       float* __restrict__ out) {
    int b = threadIdx.x;
    float p[NDD];
    float mx = -1e30f;
#pragma unroll
    for (int n = 0; n < NDD; n++) { p[n] = g_logits[b * NDD + n]; mx = fmaxf(mx, p[n]); }
    float se = 0.0f;
#pragma unroll
    for (int n = 0; n < NDD; n++) se += expf(p[n] - mx);
    float lse = mx + logf(se);
#pragma unroll
    for (int n = 0; n < NDD; n++) p[n] -= lse;

    float mx2 = -1e30f;
#pragma unroll
    for (int n = 0; n < NDD; n++) mx2 = fmaxf(mx2, p[n]);
    float se2 = 0.0f;
#pragma unroll
    for (int n = 0; n < NDD; n++) se2 += expf(p[n] - mx2);
    float lse2 = mx2 + logf(se2);

    int i0 = 0; float v0 = p[0];
#pragma unroll
    for (int n = 1; n < NDD; n++) if (p[n] > v0) { v0 = p[n]; i0 = n; }
    int i1 = -1; float v1 = -1e30f;
#pragma unroll
    for (int n = 0; n < NDD; n++) if (n != i0 && p[n] > v1) { v1 = p[n]; i1 = n; }

    int last = inputs[b * SD + SD - 1];
    int lbl = locd[(size_t)(last - 1) * NED + goal[b]];
    float lossi = -(p[lbl] - lse2);
    int corr = (i0 == lbl) || (i1 == lbl);

    const float* le = link + (size_t)last * EDD;
    const float* d0 = dire + (i0 + 1) * DDD;
    const float* d1 = dire + (i1 + 1) * DDD;
#pragma unroll 4
    for (int k = 0; k < EDD; k++) {
        float q = le[k];
        if (k < DDD) q += 0.5f * (d0[k] + d1[k]);
        g_query[b * EDD + k] = q;
    }

    __shared__ float sl[BD];
    __shared__ int sc[BD];
    sl[b] = lossi; sc[b] = corr;
    __syncthreads();
    for (int st = BD / 2; st > 0; st >>= 1) {
        if (b < st) { sl[b] += sl[b + st]; sc[b] += sc[b + st]; }
        __syncthreads();
    }
    if (b == 0) {
        out[OUT_LOSS] = sl[0] * (5.0f / (float)BD);
        out[OUT_DC] = (float)sc[0];
    }
    for (int i = b; i < BD * NDD * PLD; i += BD) out[OUT_PRED_D + i] = pdr[i];
}

// ---------------------------------------------------------------------------
// Sim GEMM
// ---------------------------------------------------------------------------
__global__ void k_sim(const float* __restrict__ link, float* __restrict__ out) {
    __shared__ float sq[64][17];
    __shared__ float sl[16][65];
    const int tid = threadIdx.x;
    const int tx = tid & 15, ty = tid >> 4;
    const int eBase = blockIdx.x * 64;
    const int mBase = blockIdx.y * 64;

    float acc[16];
#pragma unroll
    for (int i = 0; i < 16; i++) acc[i] = 0.0f;

    for (int kb = 0; kb < EDD; kb += 16) {
#pragma unroll
        for (int i = 0; i < 4; i++) {
            int idx = tid + i * 256;
            int r = idx >> 4, c = idx & 15;
            sq[r][c] = g_query[(mBase + r) * EDD + kb + c];
            sl[c][r] = link[((size_t)(eBase + r + 1)) * EDD + kb + c];
        }
        __syncthreads();
#pragma unroll
        for (int kk = 0; kk < 16; kk++) {
            float a0 = sq[ty][kk],      a1 = sq[ty + 16][kk];
            float a2 = sq[ty + 32][kk], a3 = sq[ty + 48][kk];
            float w0 = sl[kk][tx],      w1 = sl[kk][tx + 16];
            float w2 = sl[kk][tx + 32], w3 = sl[kk][tx + 48];
            acc[0]  += a0 * w0; acc[1]  += a0 * w1; acc[2]  += a0 * w2; acc[3]  += a0 * w3;
            acc[4]  += a1 * w0; acc[5]  += a1 * w1; acc[6]  += a1 * w2; acc[7]  += a1 * w3;
            acc[8]  += a2 * w0; acc[9]  += a2 * w1; acc[10] += a2 * w2; acc[11] += a2 * w3;
            acc[12] += a3 * w0; acc[13] += a3 * w1; acc[14] += a3 * w2; acc[15] += a3 * w3;
        }
        __syncthreads();
    }
#pragma unroll
    for (int mi = 0; mi < 4; mi++)
#pragma unroll
        for (int ni = 0; ni < 4; ni++) {
            int b = mBase + ty + mi * 16;
            int e = eBase + tx + ni * 16;
            float v = acc[mi * 4 + ni];
            size_t base = (size_t)b * (NED * PLD) + e;
#pragma unroll
            for (int pl = 0; pl < PLD; pl++) out[base + (size_t)pl * NED] = v;
        }
}

// ---------------------------------------------------------------------------
// Launcher
// ---------------------------------------------------------------------------
extern "C" void kernel_launch(void* const* d_in, const int* in_sizes, int n_in,
                              void* d_out, int out_size) {
    const int*   inputs = (const int*)d_in[0];
    const int*   dirs   = (const int*)d_in[1];
    const int*   goal   = (const int*)d_in[2];
    const int*   locd   = (const int*)d_in[3];
    const float* pdr    = (const float*)d_in[4];
    const float* link   = (const float*)d_in[5];
    const float* dire   = (const float*)d_in[6];
    const float* w_ih   = (const float*)d_in[7];
    const float* b_ih   = (const float*)d_in[8];
    const float* w_hh   = (const float*)d_in[9];
    const float* b_hh   = (const float*)d_in[10];
    const float* W1     = (const float*)d_in[11];
    const float* b1     = (const float*)d_in[12];
    const float* W2     = (const float*)d_in[13];
    const float* b2     = (const float*)d_in[14];
    const float* W3     = (const float*)d_in[15];
    const float* b3     = (const float*)d_in[16];
    float* out = (float*)d_out;

    static int smem_set = 0;
    if (!smem_set) {
        cudaFuncSetAttribute(k_step, cudaFuncAttributeMaxDynamicSharedMemorySize, K_STEP_SMEM);
        smem_set = 1;
    }

    k_init<<<(BD * HD + 255) / 256, 256>>>();
    k_split<<<512, 256>>>(w_hh, w_ih, link);
    k_q<<<((NDD+1) * G4D + 255) / 256, 256>>>(dire, w_ih, b_ih, b_hh);

    // P = link_emb @ Wih_link^T : M=8193, N=2048, K=128
    k_pe<<<dim3(65, 32), 256>>>();

    for (int s = 0; s < SD; s++)
        k_step<<<dim3(8, 16), 512, K_STEP_SMEM>>>(s, inputs, dirs);

    k_mlp<<<dim3(BD / 32, HD / 32), 256>>>(0, W1, b1);
    k_mlp<<<dim3(BD / 32, HD / 32), 256>>>(1, W2, b2);
    k_logits<<<(BD * NDD + 255) / 256, 256>>>(W3, b3);
    k_head<<<1, BD>>>(inputs, goal, locd, link, dire, pdr, out);
    k_sim<<<dim3(NED / 64, BD / 64), 256>>>(link, out);
}

// round 8
// speedup vs baseline: 3.5491x; 1.1685x over previous
#include <cuda_runtime.h>
#include <cuda_fp16.h>
#include <math.h>
#include <stdint.h>

// Problem dims
#define BD   512
#define SD   128
#define NED  8192
#define EDD  128
#define DDD  32
#define IND  160
#define HD   512
#define G4D  2048
#define NDD  8
#define PLD  5

#define OUT_PRED_D (512u*8192u*5u)
#define OUT_LOSS   (OUT_PRED_D + 512u*8u*5u)
#define OUT_DC     (OUT_LOSS + 1u)

#define GRID_CTAS 128

// ---------------- device scratch ----------------
__device__ float g_P[(NED+1)*G4D];                // link_emb @ Wih_link^T
__device__ float g_Q[(NDD+1)*G4D];                // dir_emb @ Wih_dir^T + biases
__device__ __half g_whh_fhi[G4D*HD], g_whh_flo[G4D*HD];   // fp16 split (lo *1024)
__device__ __half g_hh[2][BD*HD], g_hl[2][BD*HD];          // fp16 split h
__device__ float g_wih_hi[G4D*IND], g_wih_lo[G4D*IND];     // tf32 split (k_pe)
__device__ float g_link_hi[(NED+1)*EDD], g_link_lo[(NED+1)*EDD];
__device__ float g_hfp[BD*HD];
__device__ float g_z1[BD*HD], g_z2[BD*HD];
__device__ float g_logits[BD*NDD], g_query[BD*EDD];
__device__ unsigned g_barc;
__device__ volatile unsigned g_barg;

__device__ __forceinline__ float sigmf(float x) { return 1.0f / (1.0f + expf(-x)); }

__device__ __forceinline__ void tf32_split(float v, float& hi, float& lo) {
    unsigned hb; asm("cvt.rna.tf32.f32 %0, %1;" : "=r"(hb) : "f"(v));
    hi = __uint_as_float(hb);
    float r = v - hi;
    unsigned lb; asm("cvt.rna.tf32.f32 %0, %1;" : "=r"(lb) : "f"(r));
    lo = __uint_as_float(lb);
}
__device__ __forceinline__ void h16_split(float v, __half& hi, __half& lo) {
    hi = __float2half_rn(v);
    float r = v - __half2float(hi);
    lo = __float2half_rn(r * 1024.0f);
}

__device__ __forceinline__ uint32_t smem_u32(const void* p) {
    uint32_t a;
    asm("{ .reg .u64 t; cvta.to.shared.u64 t, %1; cvt.u32.u64 %0, t; }" : "=r"(a) : "l"(p));
    return a;
}
__device__ __forceinline__ void cp16(uint32_t dst, const void* src) {
    asm volatile("cp.async.cg.shared.global [%0], [%1], 16;" :: "r"(dst), "l"(src));
}
#define CP_COMMIT() asm volatile("cp.async.commit_group;" ::: "memory")
#define CP_WAIT0()  asm volatile("cp.async.wait_group 0;" ::: "memory")
#define BARN(id, n) asm volatile("bar.sync %0, %1;" :: "r"(id), "r"(n) : "memory")

#define FB(x) __float_as_uint(x)
#define MMA8(d, a, b) \
    asm volatile("mma.sync.aligned.m16n8k8.row.col.f32.tf32.tf32.f32 " \
                 "{%0,%1,%2,%3},{%4,%5,%6,%7},{%8,%9},{%0,%1,%2,%3};" \
                 : "+f"(d[0]), "+f"(d[1]), "+f"(d[2]), "+f"(d[3]) \
                 : "r"(a[0]), "r"(a[1]), "r"(a[2]), "r"(a[3]), "r"(b[0]), "r"(b[1]))
#define MMAH(d, a, b) \
    asm volatile("mma.sync.aligned.m16n8k16.row.col.f32.f16.f16.f32 " \
                 "{%0,%1,%2,%3},{%4,%5,%6,%7},{%8,%9},{%0,%1,%2,%3};" \
                 : "+f"(d[0]), "+f"(d[1]), "+f"(d[2]), "+f"(d[3]) \
                 : "r"(a[0]), "r"(a[1]), "r"(a[2]), "r"(a[3]), "r"(b[0]), "r"(b[1]))

// ---------------------------------------------------------------------------
__global__ void k_init() {
    if (threadIdx.x == 0 && blockIdx.x == 0) { g_barc = 0u; g_barg = 0u; }
}

__global__ void k_split(const float* __restrict__ whh, const float* __restrict__ wih,
                        const float* __restrict__ link) {
    int i = blockIdx.x * blockDim.x + threadIdx.x;
    int stride = gridDim.x * blockDim.x;
    for (int idx = i; idx < G4D*HD; idx += stride) {
        __half hi, lo; h16_split(whh[idx], hi, lo);
        g_whh_fhi[idx] = hi; g_whh_flo[idx] = lo;
    }
    for (int idx = i; idx < G4D*IND; idx += stride) tf32_split(wih[idx], g_wih_hi[idx], g_wih_lo[idx]);
    for (int idx = i; idx < (NED+1)*EDD; idx += stride) tf32_split(link[idx], g_link_hi[idx], g_link_lo[idx]);
}

__global__ void k_q(const float* __restrict__ dire, const float* __restrict__ wih,
                    const float* __restrict__ bih, const float* __restrict__ bhh) {
    int idx = blockIdx.x * blockDim.x + threadIdx.x;
    if (idx >= (NDD+1) * G4D) return;
    int d = idx / G4D, n = idx - d * G4D;
    float acc = bih[n] + bhh[n];
#pragma unroll 8
    for (int k = 0; k < DDD; k++) acc += dire[d * DDD + k] * wih[n * IND + EDD + k];
    g_Q[idx] = acc;
}

// ---------------------------------------------------------------------------
// K-pe: P = link_emb @ Wih_link^T via 3xTF32 mma.sync. M=8193, N=2048, K=128.
// ---------------------------------------------------------------------------
__global__ void k_pe() {
    __shared__ float sAhi[16][132], sAlo[16][132];
    __shared__ float sBhi[16][68],  sBlo[16][68];

    const int tid = threadIdx.x;
    const int lane = tid & 31, wid = tid >> 5;
    const int gid = lane >> 2, tig = lane & 3;
    const int mBase = blockIdx.x * 128, nBase = blockIdx.y * 64;
    const int warpM = (wid >> 1) * 32, warpN = (wid & 1) * 32;

    float acc[2][4][4];
#pragma unroll
    for (int a = 0; a < 2; a++)
#pragma unroll
        for (int b = 0; b < 4; b++)
#pragma unroll
            for (int c = 0; c < 4; c++) acc[a][b][c] = 0.0f;

    for (int ch = 0; ch < 8; ch++) {
        int kb = ch * 16;
#pragma unroll
        for (int it = 0; it < 2; it++) {
            int idx = tid + it * 256;
            int r = idx >> 2, kq = idx & 3;
            int k = kb + kq * 4;
            int rr = mBase + r; if (rr > NED) rr = NED;
            size_t off = (size_t)rr * EDD + k;
            float4 vh = *(const float4*)(g_link_hi + off);
            float4 vl = *(const float4*)(g_link_lo + off);
            sAhi[kq*4+0][r] = vh.x; sAhi[kq*4+1][r] = vh.y; sAhi[kq*4+2][r] = vh.z; sAhi[kq*4+3][r] = vh.w;
            sAlo[kq*4+0][r] = vl.x; sAlo[kq*4+1][r] = vl.y; sAlo[kq*4+2][r] = vl.z; sAlo[kq*4+3][r] = vl.w;
        }
        {
            int r = tid >> 2, kq = tid & 3;
            int k = kb + kq * 4;
            size_t off = (size_t)(nBase + r) * IND + k;
            float4 vh = *(const float4*)(g_wih_hi + off);
            float4 vl = *(const float4*)(g_wih_lo + off);
            sBhi[kq*4+0][r] = vh.x; sBhi[kq*4+1][r] = vh.y; sBhi[kq*4+2][r] = vh.z; sBhi[kq*4+3][r] = vh.w;
            sBlo[kq*4+0][r] = vl.x; sBlo[kq*4+1][r] = vl.y; sBlo[kq*4+2][r] = vl.z; sBlo[kq*4+3][r] = vl.w;
        }
        __syncthreads();
#pragma unroll
        for (int kk = 0; kk < 2; kk++) {
            int k0 = kk * 8;
            uint32_t ahi[2][4], alo[2][4];
#pragma unroll
            for (int mt = 0; mt < 2; mt++) {
                int row = warpM + mt * 16 + gid;
                ahi[mt][0] = FB(sAhi[k0+tig  ][row  ]); ahi[mt][1] = FB(sAhi[k0+tig  ][row+8]);
                ahi[mt][2] = FB(sAhi[k0+tig+4][row  ]); ahi[mt][3] = FB(sAhi[k0+tig+4][row+8]);
                alo[mt][0] = FB(sAlo[k0+tig  ][row  ]); alo[mt][1] = FB(sAlo[k0+tig  ][row+8]);
                alo[mt][2] = FB(sAlo[k0+tig+4][row  ]); alo[mt][3] = FB(sAlo[k0+tig+4][row+8]);
            }
            uint32_t bhi[4][2], blo[4][2];
#pragma unroll
            for (int nt = 0; nt < 4; nt++) {
                int cn = warpN + nt * 8 + gid;
                bhi[nt][0] = FB(sBhi[k0+tig][cn]); bhi[nt][1] = FB(sBhi[k0+tig+4][cn]);
                blo[nt][0] = FB(sBlo[k0+tig][cn]); blo[nt][1] = FB(sBlo[k0+tig+4][cn]);
            }
#pragma unroll
            for (int mt = 0; mt < 2; mt++)
#pragma unroll
                for (int nt = 0; nt < 4; nt++) {
                    MMA8(acc[mt][nt], ahi[mt], bhi[nt]);
                    MMA8(acc[mt][nt], ahi[mt], blo[nt]);
                    MMA8(acc[mt][nt], alo[mt], bhi[nt]);
                }
        }
        __syncthreads();
    }
#pragma unroll
    for (int mt = 0; mt < 2; mt++)
#pragma unroll
        for (int nt = 0; nt < 4; nt++) {
            int r0 = mBase + warpM + mt * 16 + gid;
            int n0 = nBase + warpN + nt * 8 + 2 * tig;
            if (r0 < NED + 1) {
                g_P[(size_t)r0 * G4D + n0]     = acc[mt][nt][0];
                g_P[(size_t)r0 * G4D + n0 + 1] = acc[mt][nt][1];
            }
            if (r0 + 8 < NED + 1) {
                g_P[(size_t)(r0+8) * G4D + n0]   = acc[mt][nt][2];
                g_P[(size_t)(r0+8) * G4D + n0+1] = acc[mt][nt][3];
            }
        }
}

// ---------------------------------------------------------------------------
// K-rnn: PERSISTENT recurrence kernel. Grid (4 bTile x 32 jTile) = 128 CTAs,
//   512 threads. B tile (W_hh slice, 64 n-rows = 16 j x 4 gates interleaved,
//   K=512, fp16 hi/lo) resident in smem across all 128 steps. c-state in regs.
//   Per step: stream h (hi/lo fp16) via cp.async, split-K 2 kgroups x 8 warps,
//   warp tile 32b x 32n, twin accumulators D/E; reduce via smem; fused LSTM
//   epilogue with P/Q gather; software grid barrier.
// ---------------------------------------------------------------------------
#define BSTR 260
#define BW_LO 16640
#define AW0   33280
#define AKG   10240
#define ABUF  5120
#define A_LOW 2560
#define ASTR  20
#define PK_SMEM (53760 * 4)

__global__ void __launch_bounds__(512, 1) k_rnn(const int* __restrict__ inputs,
                                                const int* __restrict__ dirs) {
    extern __shared__ float sm[];
    uint32_t* smw = (uint32_t*)sm;
    const uint32_t sbase = smem_u32(sm);
    const int tid = threadIdx.x;
    const int lane = tid & 31, wid = tid >> 5;
    const int gid = lane >> 2, tig = lane & 3;
    const int kg = wid >> 3, wid8 = wid & 7;
    const int lt = tid & 255;
    const int bBase = blockIdx.x * 128;
    const int jBase = blockIdx.y * 16;
    const int warpM = (wid8 >> 1) * 32, warpN = (wid8 & 1) * 32;

    // ---- one-time B load: n_local = j_local*4 + g  <-  W_hh row g*512 + jBase + j_local
    for (int i = tid; i < 64 * 64; i += 512) {
        int r = i >> 6, q = i & 63;
        int g = r & 3, jl = r >> 2;
        size_t src = ((size_t)(g * HD + jBase + jl)) * HD + q * 8;
        uint4 vh = *(const uint4*)(g_whh_fhi + src);
        uint4 vl = *(const uint4*)(g_whh_flo + src);
        *(uint4*)(smw + r * BSTR + q * 4) = vh;
        *(uint4*)(smw + BW_LO + r * BSTR + q * 4) = vl;
    }
    __syncthreads();

    // epilogue ownership: b fixed, 4 consecutive j
    const int bl_ep = tid >> 2;
    const int b_ep = bBase + bl_ep;
    const int j0 = (tid & 3) * 4;
    float cst[4] = {0.f, 0.f, 0.f, 0.f};

    for (int s = 0; s < SD; s++) {
        float D[2][4][4], E[2][4][4];
#pragma unroll
        for (int mt = 0; mt < 2; mt++)
#pragma unroll
            for (int nt = 0; nt < 4; nt++)
#pragma unroll
                for (int r = 0; r < 4; r++) { D[mt][nt][r] = 0.f; E[mt][nt][r] = 0.f; }

        if (s > 0) {
            const __half* __restrict__ hh = g_hh[s & 1];
            const __half* __restrict__ hl = g_hl[s & 1];
            auto load_chunk = [&](int cc, int buf) {
                const int kb = kg * 256 + cc * 32;
                const uint32_t bu = sbase + (uint32_t)((AW0 + kg * AKG + buf * ABUF) * 4);
#pragma unroll
                for (int t = 0; t < 4; t++) {
                    int id = lt + t * 256;
                    int isLo = id >> 9;
                    int rem = id & 511;
                    int r = rem >> 2, t4 = rem & 3;
                    const __half* src = (isLo ? hl : hh) + (size_t)(bBase + r) * HD + kb + t4 * 8;
                    uint32_t dst = bu + (uint32_t)(((isLo ? A_LOW : 0) + r * ASTR + t4 * 4) * 4);
                    cp16(dst, src);
                }
                CP_COMMIT();
            };

            load_chunk(0, 0);
#pragma unroll 1
            for (int cc = 0; cc < 8; cc++) {
                const int buf = cc & 1;
                CP_WAIT0();
                BARN(1 + kg, 256);
                if (cc < 7) load_chunk(cc + 1, buf ^ 1);

                const uint32_t* Ah = smw + AW0 + kg * AKG + buf * ABUF;
                const uint32_t* Al = Ah + A_LOW;
                const int kwBase = kg * 128 + cc * 16;
#pragma unroll
                for (int ksub = 0; ksub < 2; ksub++) {
                    const int k0 = ksub * 8;
                    uint32_t ahi[2][4], alo[2][4];
#pragma unroll
                    for (int mt = 0; mt < 2; mt++) {
                        int row = warpM + mt * 16 + gid;
                        ahi[mt][0] = Ah[row * ASTR + k0 + tig];
                        ahi[mt][1] = Ah[(row + 8) * ASTR + k0 + tig];
                        ahi[mt][2] = Ah[row * ASTR + k0 + tig + 4];
                        ahi[mt][3] = Ah[(row + 8) * ASTR + k0 + tig + 4];
                        alo[mt][0] = Al[row * ASTR + k0 + tig];
                        alo[mt][1] = Al[(row + 8) * ASTR + k0 + tig];
                        alo[mt][2] = Al[row * ASTR + k0 + tig + 4];
                        alo[mt][3] = Al[(row + 8) * ASTR + k0 + tig + 4];
                    }
                    uint32_t bhi[4][2], blo[4][2];
                    const int kw = kwBase + k0;
#pragma unroll
                    for (int nt = 0; nt < 4; nt++) {
                        int rn = warpN + nt * 8 + gid;
                        bhi[nt][0] = smw[rn * BSTR + kw + tig];
                        bhi[nt][1] = smw[rn * BSTR + kw + tig + 4];
                        blo[nt][0] = smw[BW_LO + rn * BSTR + kw + tig];
                        blo[nt][1] = smw[BW_LO + rn * BSTR + kw + tig + 4];
                    }
#pragma unroll
                    for (int mt = 0; mt < 2; mt++)
#pragma unroll
                        for (int nt = 0; nt < 4; nt++) {
                            MMAH(D[mt][nt], ahi[mt], bhi[nt]);
                            MMAH(E[mt][nt], ahi[mt], blo[nt]);
                            MMAH(E[mt][nt], alo[mt], bhi[nt]);
                        }
                }
            }
#pragma unroll
            for (int mt = 0; mt < 2; mt++)
#pragma unroll
                for (int nt = 0; nt < 4; nt++)
#pragma unroll
                    for (int r = 0; r < 4; r++)
                        D[mt][nt][r] += E[mt][nt][r] * 0.0009765625f;
        }

        __syncthreads();
        float* red = sm + AW0;
        if (s > 0) {
            if (kg == 1) {
#pragma unroll
                for (int mt = 0; mt < 2; mt++)
#pragma unroll
                    for (int nt = 0; nt < 4; nt++) {
                        int r0 = warpM + mt * 16 + gid;
                        int n0 = warpN + nt * 8 + 2 * tig;
                        red[r0 * 68 + n0]           = D[mt][nt][0];
                        red[r0 * 68 + n0 + 1]       = D[mt][nt][1];
                        red[(r0 + 8) * 68 + n0]     = D[mt][nt][2];
                        red[(r0 + 8) * 68 + n0 + 1] = D[mt][nt][3];
                    }
            }
            __syncthreads();
            if (kg == 0) {
#pragma unroll
                for (int mt = 0; mt < 2; mt++)
#pragma unroll
                    for (int nt = 0; nt < 4; nt++) {
                        int r0 = warpM + mt * 16 + gid;
                        int n0 = warpN + nt * 8 + 2 * tig;
                        red[r0 * 68 + n0]           += D[mt][nt][0];
                        red[r0 * 68 + n0 + 1]       += D[mt][nt][1];
                        red[(r0 + 8) * 68 + n0]     += D[mt][nt][2];
                        red[(r0 + 8) * 68 + n0 + 1] += D[mt][nt][3];
                    }
            }
            __syncthreads();
        }

        // ---- fused LSTM epilogue: thread owns (b_ep, j0..j0+3) ----
        {
            const int inp = inputs[b_ep * SD + s];
            const int dr  = dirs[b_ep * SD + s];
            float4 pv[4], qv[4];
#pragma unroll
            for (int g = 0; g < 4; g++) {
                pv[g] = *(const float4*)(g_P + (size_t)inp * G4D + g * HD + jBase + j0);
                qv[g] = *(const float4*)(g_Q + (size_t)dr * G4D + g * HD + jBase + j0);
            }
            __half hhi[4], hlo[4];
            float hf[4];
#pragma unroll
            for (int jj = 0; jj < 4; jj++) {
                float gi = ((const float*)&pv[0])[jj] + ((const float*)&qv[0])[jj];
                float gf = ((const float*)&pv[1])[jj] + ((const float*)&qv[1])[jj];
                float gg = ((const float*)&pv[2])[jj] + ((const float*)&qv[2])[jj];
                float go = ((const float*)&pv[3])[jj] + ((const float*)&qv[3])[jj];
                if (s > 0) {
                    int nb = (j0 + jj) * 4;
                    gi += red[bl_ep * 68 + nb + 0];
                    gf += red[bl_ep * 68 + nb + 1];
                    gg += red[bl_ep * 68 + nb + 2];
                    go += red[bl_ep * 68 + nb + 3];
                }
                float cn = sigmf(gf) * cst[jj] + sigmf(gi) * tanhf(gg);
                cst[jj] = cn;
                float h = sigmf(go) * tanhf(cn);
                hf[jj] = h;
                h16_split(h, hhi[jj], hlo[jj]);
            }
            __half* hho = g_hh[(s + 1) & 1];
            __half* hlo_ = g_hl[(s + 1) & 1];
            size_t off = (size_t)b_ep * HD + jBase + j0;
            *(__half2*)(hho + off)     = __halves2half2(hhi[0], hhi[1]);
            *(__half2*)(hho + off + 2) = __halves2half2(hhi[2], hhi[3]);
            *(__half2*)(hlo_ + off)     = __halves2half2(hlo[0], hlo[1]);
            *(__half2*)(hlo_ + off + 2) = __halves2half2(hlo[2], hlo[3]);
            if (s == SD - 1)
                *(float4*)(g_hfp + off) = make_float4(hf[0], hf[1], hf[2], hf[3]);
        }

        // ---- grid barrier ----
        __threadfence();
        __syncthreads();
        if (tid == 0) {
            unsigned target = (unsigned)(s + 1);
            unsigned a = atomicAdd(&g_barc, 1u);
            if (a == GRID_CTAS - 1) {
                g_barc = 0u;
                __threadfence();
                g_barg = target;
            } else {
                while (g_barg < target) { }
                __threadfence();
            }
        }
        __syncthreads();
    }
}

// ---------------------------------------------------------------------------
// MLP layers (fp32)
// ---------------------------------------------------------------------------
__global__ void k_mlp(int which, const float* __restrict__ W, const float* __restrict__ bias) {
    __shared__ float sa[32][33];
    __shared__ float swm[32][33];
    const int tid = threadIdx.x;
    const int tx = tid & 15, ty = tid >> 4;
    const int mBase = blockIdx.x * 32;
    const int nBase = blockIdx.y * 32;
    const float* __restrict__ A = (which == 0) ? g_hfp : g_z1;
    float* __restrict__ out = (which == 0) ? g_z1 : g_z2;

    float acc[4] = {0.f, 0.f, 0.f, 0.f};
    for (int kb = 0; kb < HD; kb += 32) {
#pragma unroll
        for (int i = 0; i < 4; i++) {
            int idx = tid + i * 256;
            int r = idx >> 5, c = idx & 31;
            sa[r][c]  = A[(mBase + r) * HD + kb + c];
            swm[r][c] = W[(nBase + r) * HD + kb + c];
        }
        __syncthreads();
#pragma unroll
        for (int kk = 0; kk < 32; kk++) {
            float a0 = sa[ty][kk], a1 = sa[ty + 16][kk];
            float w0 = swm[tx][kk], w1 = swm[tx + 16][kk];
            acc[0] += a0 * w0; acc[1] += a0 * w1;
            acc[2] += a1 * w0; acc[3] += a1 * w1;
        }
        __syncthreads();
    }
#pragma unroll
    for (int bi = 0; bi < 2; bi++)
#pragma unroll
        for (int ni = 0; ni < 2; ni++) {
            int m = mBase + ty + bi * 16;
            int n = nBase + tx + ni * 16;
            float v = acc[bi * 2 + ni] + bias[n];
            out[m * HD + n] = fmaxf(v, 0.0f);
        }
}

__global__ void k_logits(const float* __restrict__ W3, const float* __restrict__ b3) {
    int idx = blockIdx.x * blockDim.x + threadIdx.x;
    if (idx >= BD * NDD) return;
    int b = idx >> 3, n = idx & 7;
    const float4* z = (const float4*)(g_z2 + b * HD);
    const float4* w = (const float4*)(W3 + n * HD);
    float acc = b3[n];
#pragma unroll 4
    for (int k = 0; k < HD / 4; k++) {
        float4 zv = z[k], wv = w[k];
        acc += zv.x * wv.x + zv.y * wv.y + zv.z * wv.z + zv.w * wv.w;
    }
    g_logits[idx] = acc;
}

// ---------------------------------------------------------------------------
// Head
// ---------------------------------------------------------------------------
__global__ void k_head(const int* __restrict__ inputs, const int* __restrict__ goal,
                       const int* __restrict__ locd, const float* __restrict__ link,
                       const float* __restrict__ dire, const float* __restrict__ pdr,
                       float* __restrict__ out) {
    int b = threadIdx.x;
    float p[NDD];
    float mx = -1e30f;
#pragma unroll
    for (int n = 0; n < NDD; n++) { p[n] = g_logits[b * NDD + n]; mx = fmaxf(mx, p[n]); }
    float se = 0.0f;
#pragma unroll
    for (int n = 0; n < NDD; n++) se += expf(p[n] - mx);
    float lse = mx + logf(se);
#pragma unroll
    for (int n = 0; n < NDD; n++) p[n] -= lse;

    float mx2 = -1e30f;
#pragma unroll
    for (int n = 0; n < NDD; n++) mx2 = fmaxf(mx2, p[n]);
    float se2 = 0.0f;
#pragma unroll
    for (int n = 0; n < NDD; n++) se2 += expf(p[n] - mx2);
    float lse2 = mx2 + logf(se2);

    int i0 = 0; float v0 = p[0];
#pragma unroll
    for (int n = 1; n < NDD; n++) if (p[n] > v0) { v0 = p[n]; i0 = n; }
    int i1 = -1; float v1 = -1e30f;
#pragma unroll
    for (int n = 0; n < NDD; n++) if (n != i0 && p[n] > v1) { v1 = p[n]; i1 = n; }

    int last = inputs[b * SD + SD - 1];
    int lbl = locd[(size_t)(last - 1) * NED + goal[b]];
    float lossi = -(p[lbl] - lse2);
    int corr = (i0 == lbl) || (i1 == lbl);

    const float* le = link + (size_t)last * EDD;
    const float* d0 = dire + (i0 + 1) * DDD;
    const float* d1 = dire + (i1 + 1) * DDD;
#pragma unroll 4
    for (int k = 0; k < EDD; k++) {
        float q = le[k];
        if (k < DDD) q += 0.5f * (d0[k] + d1[k]);
        g_query[b * EDD + k] = q;
    }

    __shared__ float sl[BD];
    __shared__ int sc[BD];
    sl[b] = lossi; sc[b] = corr;
    __syncthreads();
    for (int st = BD / 2; st > 0; st >>= 1) {
        if (b < st) { sl[b] += sl[b + st]; sc[b] += sc[b + st]; }
        __syncthreads();
    }
    if (b == 0) {
        out[OUT_LOSS] = sl[0] * (5.0f / (float)BD);
        out[OUT_DC] = (float)sc[0];
    }
    for (int i = b; i < BD * NDD * PLD; i += BD) out[OUT_PRED_D + i] = pdr[i];
}

// ---------------------------------------------------------------------------
// Sim GEMM
// ---------------------------------------------------------------------------
__global__ void k_sim(const float* __restrict__ link, float* __restrict__ out) {
    __shared__ float sq[64][17];
    __shared__ float sl[16][65];
    const int tid = threadIdx.x;
    const int tx = tid & 15, ty = tid >> 4;
    const int eBase = blockIdx.x * 64;
    const int mBase = blockIdx.y * 64;

    float acc[16];
#pragma unroll
    for (int i = 0; i < 16; i++) acc[i] = 0.0f;

    for (int kb = 0; kb < EDD; kb += 16) {
#pragma unroll
        for (int i = 0; i < 4; i++) {
            int idx = tid + i * 256;
            int r = idx >> 4, c = idx & 15;
            sq[r][c] = g_query[(mBase + r) * EDD + kb + c];
            sl[c][r] = link[((size_t)(eBase + r + 1)) * EDD + kb + c];
        }
        __syncthreads();
#pragma unroll
        for (int kk = 0; kk < 16; kk++) {
            float a0 = sq[ty][kk],      a1 = sq[ty + 16][kk];
            float a2 = sq[ty + 32][kk], a3 = sq[ty + 48][kk];
            float w0 = sl[kk][tx],      w1 = sl[kk][tx + 16];
            float w2 = sl[kk][tx + 32], w3 = sl[kk][tx + 48];
            acc[0]  += a0 * w0; acc[1]  += a0 * w1; acc[2]  += a0 * w2; acc[3]  += a0 * w3;
            acc[4]  += a1 * w0; acc[5]  += a1 * w1; acc[6]  += a1 * w2; acc[7]  += a1 * w3;
            acc[8]  += a2 * w0; acc[9]  += a2 * w1; acc[10] += a2 * w2; acc[11] += a2 * w3;
            acc[12] += a3 * w0; acc[13] += a3 * w1; acc[14] += a3 * w2; acc[15] += a3 * w3;
        }
        __syncthreads();
    }
#pragma unroll
    for (int mi = 0; mi < 4; mi++)
#pragma unroll
        for (int ni = 0; ni < 4; ni++) {
            int b = mBase + ty + mi * 16;
            int e = eBase + tx + ni * 16;
            float v = acc[mi * 4 + ni];
            size_t base = (size_t)b * (NED * PLD) + e;
#pragma unroll
            for (int pl = 0; pl < PLD; pl++) out[base + (size_t)pl * NED] = v;
        }
}

// ---------------------------------------------------------------------------
// Launcher
// ---------------------------------------------------------------------------
extern "C" void kernel_launch(void* const* d_in, const int* in_sizes, int n_in,
                              void* d_out, int out_size) {
    const int*   inputs = (const int*)d_in[0];
    const int*   dirs   = (const int*)d_in[1];
    const int*   goal   = (const int*)d_in[2];
    const int*   locd   = (const int*)d_in[3];
    const float* pdr    = (const float*)d_in[4];
    const float* link   = (const float*)d_in[5];
    const float* dire   = (const float*)d_in[6];
    const float* w_ih   = (const float*)d_in[7];
    const float* b_ih   = (const float*)d_in[8];
    const float* w_hh   = (const float*)d_in[9];
    const float* b_hh   = (const float*)d_in[10];
    const float* W1     = (const float*)d_in[11];
    const float* b1     = (const float*)d_in[12];
    const float* W2     = (const float*)d_in[13];
    const float* b2     = (const float*)d_in[14];
    const float* W3     = (const float*)d_in[15];
    const float* b3     = (const float*)d_in[16];
    float* out = (float*)d_out;

    static int smem_set = 0;
    if (!smem_set) {
        cudaFuncSetAttribute(k_rnn, cudaFuncAttributeMaxDynamicSharedMemorySize, PK_SMEM);
        smem_set = 1;
    }

    k_init<<<1, 32>>>();
    k_split<<<512, 256>>>(w_hh, w_ih, link);
    k_q<<<((NDD+1) * G4D + 255) / 256, 256>>>(dire, w_ih, b_ih, b_hh);

    // P = link_emb @ Wih_link^T : M=8193, N=2048, K=128
    k_pe<<<dim3(65, 32), 256>>>();

    // Persistent recurrence: 128 CTAs, all co-resident, software grid barrier
    k_rnn<<<dim3(4, 32), 512, PK_SMEM>>>(inputs, dirs);

    k_mlp<<<dim3(BD / 32, HD / 32), 256>>>(0, W1, b1);
    k_mlp<<<dim3(BD / 32, HD / 32), 256>>>(1, W2, b2);
    k_logits<<<(BD * NDD + 255) / 256, 256>>>(W3, b3);
    k_head<<<1, BD>>>(inputs, goal, locd, link, dire, pdr, out);
    k_sim<<<dim3(NED / 64, BD / 64), 256>>>(link, out);
}

// round 9
// speedup vs baseline: 3.7272x; 1.0502x over previous
#include <cuda_runtime.h>
#include <cuda_fp16.h>
#include <math.h>
#include <stdint.h>

// Problem dims
#define BD   512
#define SD   128
#define NED  8192
#define EDD  128
#define DDD  32
#define IND  160
#define HD   512
#define G4D  2048
#define NDD  8
#define PLD  5

#define OUT_PRED_D (512u*8192u*5u)
#define OUT_LOSS   (OUT_PRED_D + 512u*8u*5u)
#define OUT_DC     (OUT_LOSS + 1u)

// ---------------- device scratch ----------------
__device__ float g_P[(NED+1)*G4D];
__device__ float g_Q[(NDD+1)*G4D];
__device__ __half g_whh_fhi[G4D*HD], g_whh_flo[G4D*HD];
__device__ __half g_hh[2][BD*HD], g_hl[2][BD*HD];
__device__ float g_wih_hi[G4D*IND], g_wih_lo[G4D*IND];
__device__ float g_link_hi[(NED+1)*EDD], g_link_lo[(NED+1)*EDD];
__device__ float g_hfp[BD*HD];
__device__ float g_z1[BD*HD], g_z2[BD*HD];
__device__ float g_logits[BD*NDD], g_query[BD*EDD];
// per-b-group barriers (4 groups x 32 CTAs), padded to separate cachelines
__device__ unsigned g_barc[4*32];
__device__ volatile unsigned g_barg[4*32];

__device__ __forceinline__ float sigmf(float x) { return 1.0f / (1.0f + expf(-x)); }

__device__ __forceinline__ void tf32_split(float v, float& hi, float& lo) {
    unsigned hb; asm("cvt.rna.tf32.f32 %0, %1;" : "=r"(hb) : "f"(v));
    hi = __uint_as_float(hb);
    float r = v - hi;
    unsigned lb; asm("cvt.rna.tf32.f32 %0, %1;" : "=r"(lb) : "f"(r));
    lo = __uint_as_float(lb);
}
__device__ __forceinline__ void h16_split(float v, __half& hi, __half& lo) {
    hi = __float2half_rn(v);
    float r = v - __half2float(hi);
    lo = __float2half_rn(r * 1024.0f);
}

__device__ __forceinline__ uint32_t smem_u32(const void* p) {
    uint32_t a;
    asm("{ .reg .u64 t; cvta.to.shared.u64 t, %1; cvt.u32.u64 %0, t; }" : "=r"(a) : "l"(p));
    return a;
}
__device__ __forceinline__ void cp16(uint32_t dst, const void* src) {
    asm volatile("cp.async.cg.shared.global [%0], [%1], 16;" :: "r"(dst), "l"(src));
}
__device__ __forceinline__ void ldsm4(uint32_t* r, uint32_t addr) {
    asm volatile("ldmatrix.sync.aligned.m8n8.x4.shared.b16 {%0,%1,%2,%3}, [%4];"
                 : "=r"(r[0]), "=r"(r[1]), "=r"(r[2]), "=r"(r[3]) : "r"(addr));
}
__device__ __forceinline__ void pref_l2(const void* p) {
    asm volatile("prefetch.global.L2 [%0];" :: "l"(p));
}
#define CP_COMMIT() asm volatile("cp.async.commit_group;" ::: "memory")
#define CP_WAIT0()  asm volatile("cp.async.wait_group 0;" ::: "memory")
#define BARN(id, n) asm volatile("bar.sync %0, %1;" :: "r"(id), "r"(n) : "memory")

#define FB(x) __float_as_uint(x)
#define MMA8(d, a, b) \
    asm volatile("mma.sync.aligned.m16n8k8.row.col.f32.tf32.tf32.f32 " \
                 "{%0,%1,%2,%3},{%4,%5,%6,%7},{%8,%9},{%0,%1,%2,%3};" \
                 : "+f"(d[0]), "+f"(d[1]), "+f"(d[2]), "+f"(d[3]) \
                 : "r"(a[0]), "r"(a[1]), "r"(a[2]), "r"(a[3]), "r"(b[0]), "r"(b[1]))
#define MMAH(d, a, b) \
    asm volatile("mma.sync.aligned.m16n8k16.row.col.f32.f16.f16.f32 " \
                 "{%0,%1,%2,%3},{%4,%5,%6,%7},{%8,%9},{%0,%1,%2,%3};" \
                 : "+f"(d[0]), "+f"(d[1]), "+f"(d[2]), "+f"(d[3]) \
                 : "r"(a[0]), "r"(a[1]), "r"(a[2]), "r"(a[3]), "r"(b[0]), "r"(b[1]))

// ---------------------------------------------------------------------------
__global__ void k_init() {
    int i = threadIdx.x;
    if (blockIdx.x == 0 && i < 4 * 32) { g_barc[i] = 0u; g_barg[i] = 0u; }
}

__global__ void k_split(const float* __restrict__ whh, const float* __restrict__ wih,
                        const float* __restrict__ link) {
    int i = blockIdx.x * blockDim.x + threadIdx.x;
    int stride = gridDim.x * blockDim.x;
    for (int idx = i; idx < G4D*HD; idx += stride) {
        __half hi, lo; h16_split(whh[idx], hi, lo);
        g_whh_fhi[idx] = hi; g_whh_flo[idx] = lo;
    }
    for (int idx = i; idx < G4D*IND; idx += stride) tf32_split(wih[idx], g_wih_hi[idx], g_wih_lo[idx]);
    for (int idx = i; idx < (NED+1)*EDD; idx += stride) tf32_split(link[idx], g_link_hi[idx], g_link_lo[idx]);
}

__global__ void k_q(const float* __restrict__ dire, const float* __restrict__ wih,
                    const float* __restrict__ bih, const float* __restrict__ bhh) {
    int idx = blockIdx.x * blockDim.x + threadIdx.x;
    if (idx >= (NDD+1) * G4D) return;
    int d = idx / G4D, n = idx - d * G4D;
    float acc = bih[n] + bhh[n];
#pragma unroll 8
    for (int k = 0; k < DDD; k++) acc += dire[d * DDD + k] * wih[n * IND + EDD + k];
    g_Q[idx] = acc;
}

// ---------------------------------------------------------------------------
// K-pe: P = link_emb @ Wih_link^T via 3xTF32 mma.sync. M=8193, N=2048, K=128.
// ---------------------------------------------------------------------------
__global__ void k_pe() {
    __shared__ float sAhi[16][132], sAlo[16][132];
    __shared__ float sBhi[16][68],  sBlo[16][68];

    const int tid = threadIdx.x;
    const int lane = tid & 31, wid = tid >> 5;
    const int gid = lane >> 2, tig = lane & 3;
    const int mBase = blockIdx.x * 128, nBase = blockIdx.y * 64;
    const int warpM = (wid >> 1) * 32, warpN = (wid & 1) * 32;

    float acc[2][4][4];
#pragma unroll
    for (int a = 0; a < 2; a++)
#pragma unroll
        for (int b = 0; b < 4; b++)
#pragma unroll
            for (int c = 0; c < 4; c++) acc[a][b][c] = 0.0f;

    for (int ch = 0; ch < 8; ch++) {
        int kb = ch * 16;
#pragma unroll
        for (int it = 0; it < 2; it++) {
            int idx = tid + it * 256;
            int r = idx >> 2, kq = idx & 3;
            int k = kb + kq * 4;
            int rr = mBase + r; if (rr > NED) rr = NED;
            size_t off = (size_t)rr * EDD + k;
            float4 vh = *(const float4*)(g_link_hi + off);
            float4 vl = *(const float4*)(g_link_lo + off);
            sAhi[kq*4+0][r] = vh.x; sAhi[kq*4+1][r] = vh.y; sAhi[kq*4+2][r] = vh.z; sAhi[kq*4+3][r] = vh.w;
            sAlo[kq*4+0][r] = vl.x; sAlo[kq*4+1][r] = vl.y; sAlo[kq*4+2][r] = vl.z; sAlo[kq*4+3][r] = vl.w;
        }
        {
            int r = tid >> 2, kq = tid & 3;
            int k = kb + kq * 4;
            size_t off = (size_t)(nBase + r) * IND + k;
            float4 vh = *(const float4*)(g_wih_hi + off);
            float4 vl = *(const float4*)(g_wih_lo + off);
            sBhi[kq*4+0][r] = vh.x; sBhi[kq*4+1][r] = vh.y; sBhi[kq*4+2][r] = vh.z; sBhi[kq*4+3][r] = vh.w;
            sBlo[kq*4+0][r] = vl.x; sBlo[kq*4+1][r] = vl.y; sBlo[kq*4+2][r] = vl.z; sBlo[kq*4+3][r] = vl.w;
        }
        __syncthreads();
#pragma unroll
        for (int kk = 0; kk < 2; kk++) {
            int k0 = kk * 8;
            uint32_t ahi[2][4], alo[2][4];
#pragma unroll
            for (int mt = 0; mt < 2; mt++) {
                int row = warpM + mt * 16 + gid;
                ahi[mt][0] = FB(sAhi[k0+tig  ][row  ]); ahi[mt][1] = FB(sAhi[k0+tig  ][row+8]);
                ahi[mt][2] = FB(sAhi[k0+tig+4][row  ]); ahi[mt][3] = FB(sAhi[k0+tig+4][row+8]);
                alo[mt][0] = FB(sAlo[k0+tig  ][row  ]); alo[mt][1] = FB(sAlo[k0+tig  ][row+8]);
                alo[mt][2] = FB(sAlo[k0+tig+4][row  ]); alo[mt][3] = FB(sAlo[k0+tig+4][row+8]);
            }
            uint32_t bhi[4][2], blo[4][2];
#pragma unroll
            for (int nt = 0; nt < 4; nt++) {
                int cn = warpN + nt * 8 + gid;
                bhi[nt][0] = FB(sBhi[k0+tig][cn]); bhi[nt][1] = FB(sBhi[k0+tig+4][cn]);
                blo[nt][0] = FB(sBlo[k0+tig][cn]); blo[nt][1] = FB(sBlo[k0+tig+4][cn]);
            }
#pragma unroll
            for (int mt = 0; mt < 2; mt++)
#pragma unroll
                for (int nt = 0; nt < 4; nt++) {
                    MMA8(acc[mt][nt], ahi[mt], bhi[nt]);
                    MMA8(acc[mt][nt], ahi[mt], blo[nt]);
                    MMA8(acc[mt][nt], alo[mt], bhi[nt]);
                }
        }
        __syncthreads();
    }
#pragma unroll
    for (int mt = 0; mt < 2; mt++)
#pragma unroll
        for (int nt = 0; nt < 4; nt++) {
            int r0 = mBase + warpM + mt * 16 + gid;
            int n0 = nBase + warpN + nt * 8 + 2 * tig;
            if (r0 < NED + 1) {
                g_P[(size_t)r0 * G4D + n0]     = acc[mt][nt][0];
                g_P[(size_t)r0 * G4D + n0 + 1] = acc[mt][nt][1];
            }
            if (r0 + 8 < NED + 1) {
                g_P[(size_t)(r0+8) * G4D + n0]   = acc[mt][nt][2];
                g_P[(size_t)(r0+8) * G4D + n0+1] = acc[mt][nt][3];
            }
        }
}

// ---------------------------------------------------------------------------
// K-rnn: persistent recurrence. Grid (4 bTile x 32 jTile) = 128 CTAs, 512 thr.
//   W_hh slice smem-resident; c in regs; h streamed via cp.async; split-K;
//   ldmatrix.x4 fragment loads; per-b-group (32 CTA) software barriers.
// ---------------------------------------------------------------------------
#define BSTR 260
#define BW_LO 16640
#define AW0   33280
#define AKG   10240
#define ABUF  5120
#define A_LOW 2560
#define ASTR  20
#define PK_SMEM (53760 * 4)

__global__ void __launch_bounds__(512, 1) k_rnn(const int* __restrict__ inputs,
                                                const int* __restrict__ dirs) {
    extern __shared__ float sm[];
    uint32_t* smw = (uint32_t*)sm;
    const uint32_t sbase = smem_u32(sm);
    const int tid = threadIdx.x;
    const int lane = tid & 31, wid = tid >> 5;
    const int kg = wid >> 3, wid8 = wid & 7;
    const int lt = tid & 255;
    const int grp = blockIdx.x;
    const int bBase = blockIdx.x * 128;
    const int jBase = blockIdx.y * 16;
    const int warpM = (wid8 >> 1) * 32, warpN = (wid8 & 1) * 32;

    // ---- one-time B load: n_local = j_local*4 + g
    for (int i = tid; i < 64 * 64; i += 512) {
        int r = i >> 6, q = i & 63;
        int g = r & 3, jl = r >> 2;
        size_t src = ((size_t)(g * HD + jBase + jl)) * HD + q * 8;
        uint4 vh = *(const uint4*)(g_whh_fhi + src);
        uint4 vl = *(const uint4*)(g_whh_flo + src);
        *(uint4*)(smw + r * BSTR + q * 4) = vh;
        *(uint4*)(smw + BW_LO + r * BSTR + q * 4) = vl;
    }
    __syncthreads();

    // ldmatrix lane-address components (byte offsets)
    const uint32_t aOffL = (uint32_t)(((warpM + (lane & 7) + ((lane >> 3) & 1) * 8) * ASTR
                                      + (lane >> 4) * 4) * 4);
    const uint32_t bOffL = (uint32_t)(((warpN + (lane & 7) + ((lane >> 4) & 1) * 8) * BSTR
                                      + ((lane >> 3) & 1) * 4) * 4);
    const uint32_t bHiL = sbase + bOffL;
    const uint32_t bLoL = sbase + (uint32_t)(BW_LO * 4) + bOffL;

    // epilogue ownership: b fixed, 4 consecutive j
    const int bl_ep = tid >> 2;
    const int b_ep = bBase + bl_ep;
    const int j0 = (tid & 3) * 4;
    float cst[4] = {0.f, 0.f, 0.f, 0.f};

    for (int s = 0; s < SD; s++) {
        // prefetch epilogue gather rows into L2 early
        const int inp = inputs[b_ep * SD + s];
        const int dr  = dirs[b_ep * SD + s];
        {
            const float* Pr = g_P + (size_t)inp * G4D + jBase + j0;
            const float* Qr = g_Q + (size_t)dr * G4D + jBase + j0;
            pref_l2(Pr); pref_l2(Pr + HD); pref_l2(Pr + 2 * HD); pref_l2(Pr + 3 * HD);
            pref_l2(Qr); pref_l2(Qr + HD); pref_l2(Qr + 2 * HD); pref_l2(Qr + 3 * HD);
        }

        float D[2][4][4], E[2][4][4];
#pragma unroll
        for (int mt = 0; mt < 2; mt++)
#pragma unroll
            for (int nt = 0; nt < 4; nt++)
#pragma unroll
                for (int r = 0; r < 4; r++) { D[mt][nt][r] = 0.f; E[mt][nt][r] = 0.f; }

        if (s > 0) {
            const __half* __restrict__ hh = g_hh[s & 1];
            const __half* __restrict__ hl = g_hl[s & 1];
            auto load_chunk = [&](int cc, int buf) {
                const int kb = kg * 256 + cc * 32;
                const uint32_t bu = sbase + (uint32_t)((AW0 + kg * AKG + buf * ABUF) * 4);
#pragma unroll
                for (int t = 0; t < 4; t++) {
                    int id = lt + t * 256;
                    int isLo = id >> 9;
                    int rem = id & 511;
                    int r = rem >> 2, t4 = rem & 3;
                    const __half* src = (isLo ? hl : hh) + (size_t)(bBase + r) * HD + kb + t4 * 8;
                    uint32_t dst = bu + (uint32_t)(((isLo ? A_LOW : 0) + r * ASTR + t4 * 4) * 4);
                    cp16(dst, src);
                }
                CP_COMMIT();
            };

            load_chunk(0, 0);
#pragma unroll 1
            for (int cc = 0; cc < 8; cc++) {
                const int buf = cc & 1;
                CP_WAIT0();
                BARN(1 + kg, 256);
                if (cc < 7) load_chunk(cc + 1, buf ^ 1);

                const uint32_t aHiBase = sbase + (uint32_t)((AW0 + kg * AKG + buf * ABUF) * 4) + aOffL;
                const uint32_t aLoBase = aHiBase + (uint32_t)(A_LOW * 4);
                const int kwBase = kg * 128 + cc * 16;
#pragma unroll
                for (int ksub = 0; ksub < 2; ksub++) {
                    const int k0 = ksub * 8;
                    uint32_t ahi[2][4], alo[2][4];
                    ldsm4(ahi[0], aHiBase + k0 * 4);
                    ldsm4(ahi[1], aHiBase + k0 * 4 + 16 * ASTR * 4);
                    ldsm4(alo[0], aLoBase + k0 * 4);
                    ldsm4(alo[1], aLoBase + k0 * 4 + 16 * ASTR * 4);
                    uint32_t bhi[4][2], blo[4][2];
                    {
                        const uint32_t kwb = (uint32_t)((kwBase + k0) * 4);
                        uint32_t t4[4];
                        ldsm4(t4, bHiL + kwb);
                        bhi[0][0] = t4[0]; bhi[0][1] = t4[1]; bhi[1][0] = t4[2]; bhi[1][1] = t4[3];
                        ldsm4(t4, bHiL + kwb + 16 * BSTR * 4);
                        bhi[2][0] = t4[0]; bhi[2][1] = t4[1]; bhi[3][0] = t4[2]; bhi[3][1] = t4[3];
                        ldsm4(t4, bLoL + kwb);
                        blo[0][0] = t4[0]; blo[0][1] = t4[1]; blo[1][0] = t4[2]; blo[1][1] = t4[3];
                        ldsm4(t4, bLoL + kwb + 16 * BSTR * 4);
                        blo[2][0] = t4[0]; blo[2][1] = t4[1]; blo[3][0] = t4[2]; blo[3][1] = t4[3];
                    }
#pragma unroll
                    for (int mt = 0; mt < 2; mt++)
#pragma unroll
                        for (int nt = 0; nt < 4; nt++) {
                            MMAH(D[mt][nt], ahi[mt], bhi[nt]);
                            MMAH(E[mt][nt], ahi[mt], blo[nt]);
                            MMAH(E[mt][nt], alo[mt], bhi[nt]);
                        }
                }
            }
#pragma unroll
            for (int mt = 0; mt < 2; mt++)
#pragma unroll
                for (int nt = 0; nt < 4; nt++)
#pragma unroll
                    for (int r = 0; r < 4; r++)
                        D[mt][nt][r] += E[mt][nt][r] * 0.0009765625f;
        }

        __syncthreads();
        float* red = sm + AW0;
        if (s > 0) {
            const int gid = lane >> 2, tig = lane & 3;
            if (kg == 1) {
#pragma unroll
                for (int mt = 0; mt < 2; mt++)
#pragma unroll
                    for (int nt = 0; nt < 4; nt++) {
                        int r0 = warpM + mt * 16 + gid;
                        int n0 = warpN + nt * 8 + 2 * tig;
                        red[r0 * 68 + n0]           = D[mt][nt][0];
                        red[r0 * 68 + n0 + 1]       = D[mt][nt][1];
                        red[(r0 + 8) * 68 + n0]     = D[mt][nt][2];
                        red[(r0 + 8) * 68 + n0 + 1] = D[mt][nt][3];
                    }
            }
            __syncthreads();
            if (kg == 0) {
#pragma unroll
                for (int mt = 0; mt < 2; mt++)
#pragma unroll
                    for (int nt = 0; nt < 4; nt++) {
                        int r0 = warpM + mt * 16 + gid;
                        int n0 = warpN + nt * 8 + 2 * tig;
                        red[r0 * 68 + n0]           += D[mt][nt][0];
                        red[r0 * 68 + n0 + 1]       += D[mt][nt][1];
                        red[(r0 + 8) * 68 + n0]     += D[mt][nt][2];
                        red[(r0 + 8) * 68 + n0 + 1] += D[mt][nt][3];
                    }
            }
            __syncthreads();
        }

        // ---- fused LSTM epilogue: thread owns (b_ep, j0..j0+3) ----
        {
            float4 pv[4], qv[4];
#pragma unroll
            for (int g = 0; g < 4; g++) {
                pv[g] = *(const float4*)(g_P + (size_t)inp * G4D + g * HD + jBase + j0);
                qv[g] = *(const float4*)(g_Q + (size_t)dr * G4D + g * HD + jBase + j0);
            }
            __half hhi[4], hlo[4];
            float hf[4];
#pragma unroll
            for (int jj = 0; jj < 4; jj++) {
                float gi = ((const float*)&pv[0])[jj] + ((const float*)&qv[0])[jj];
                float gf = ((const float*)&pv[1])[jj] + ((const float*)&qv[1])[jj];
                float gg = ((const float*)&pv[2])[jj] + ((const float*)&qv[2])[jj];
                float go = ((const float*)&pv[3])[jj] + ((const float*)&qv[3])[jj];
                if (s > 0) {
                    int nb = (j0 + jj) * 4;
                    gi += red[bl_ep * 68 + nb + 0];
                    gf += red[bl_ep * 68 + nb + 1];
                    gg += red[bl_ep * 68 + nb + 2];
                    go += red[bl_ep * 68 + nb + 3];
                }
                float cn = sigmf(gf) * cst[jj] + sigmf(gi) * tanhf(gg);
                cst[jj] = cn;
                float h = sigmf(go) * tanhf(cn);
                hf[jj] = h;
                h16_split(h, hhi[jj], hlo[jj]);
            }
            __half* hho = g_hh[(s + 1) & 1];
            __half* hlo_ = g_hl[(s + 1) & 1];
            size_t off = (size_t)b_ep * HD + jBase + j0;
            *(__half2*)(hho + off)     = __halves2half2(hhi[0], hhi[1]);
            *(__half2*)(hho + off + 2) = __halves2half2(hhi[2], hhi[3]);
            *(__half2*)(hlo_ + off)     = __halves2half2(hlo[0], hlo[1]);
            *(__half2*)(hlo_ + off + 2) = __halves2half2(hlo[2], hlo[3]);
            if (s == SD - 1)
                *(float4*)(g_hfp + off) = make_float4(hf[0], hf[1], hf[2], hf[3]);
        }

        // ---- per-b-group barrier (32 CTAs) ----
        __threadfence();
        __syncthreads();
        if (tid == 0) {
            unsigned target = (unsigned)(s + 1);
            unsigned a = atomicAdd(&g_barc[grp * 32], 1u);
            if (a == 31u) {
                g_barc[grp * 32] = 0u;
                __threadfence();
                g_barg[grp * 32] = target;
            } else {
                while (g_barg[grp * 32] < target) { }
                __threadfence();
            }
        }
        __syncthreads();
    }
}

// ---------------------------------------------------------------------------
// MLP layers (fp32)
// ---------------------------------------------------------------------------
__global__ void k_mlp(int which, const float* __restrict__ W, const float* __restrict__ bias) {
    __shared__ float sa[32][33];
    __shared__ float swm[32][33];
    const int tid = threadIdx.x;
    const int tx = tid & 15, ty = tid >> 4;
    const int mBase = blockIdx.x * 32;
    const int nBase = blockIdx.y * 32;
    const float* __restrict__ A = (which == 0) ? g_hfp : g_z1;
    float* __restrict__ out = (which == 0) ? g_z1 : g_z2;

    float acc[4] = {0.f, 0.f, 0.f, 0.f};
    for (int kb = 0; kb < HD; kb += 32) {
#pragma unroll
        for (int i = 0; i < 4; i++) {
            int idx = tid + i * 256;
            int r = idx >> 5, c = idx & 31;
            sa[r][c]  = A[(mBase + r) * HD + kb + c];
            swm[r][c] = W[(nBase + r) * HD + kb + c];
        }
        __syncthreads();
#pragma unroll
        for (int kk = 0; kk < 32; kk++) {
            float a0 = sa[ty][kk], a1 = sa[ty + 16][kk];
            float w0 = swm[tx][kk], w1 = swm[tx + 16][kk];
            acc[0] += a0 * w0; acc[1] += a0 * w1;
            acc[2] += a1 * w0; acc[3] += a1 * w1;
        }
        __syncthreads();
    }
#pragma unroll
    for (int bi = 0; bi < 2; bi++)
#pragma unroll
        for (int ni = 0; ni < 2; ni++) {
            int m = mBase + ty + bi * 16;
            int n = nBase + tx + ni * 16;
            float v = acc[bi * 2 + ni] + bias[n];
            out[m * HD + n] = fmaxf(v, 0.0f);
        }
}

__global__ void k_logits(const float* __restrict__ W3, const float* __restrict__ b3) {
    int idx = blockIdx.x * blockDim.x + threadIdx.x;
    if (idx >= BD * NDD) return;
    int b = idx >> 3, n = idx & 7;
    const float4* z = (const float4*)(g_z2 + b * HD);
    const float4* w = (const float4*)(W3 + n * HD);
    float acc = b3[n];
#pragma unroll 4
    for (int k = 0; k < HD / 4; k++) {
        float4 zv = z[k], wv = w[k];
        acc += zv.x * wv.x + zv.y * wv.y + zv.z * wv.z + zv.w * wv.w;
    }
    g_logits[idx] = acc;
}

// ---------------------------------------------------------------------------
// Head
// ---------------------------------------------------------------------------
__global__ void k_head(const int* __restrict__ inputs, const int* __restrict__ goal,
                       const int* __restrict__ locd, const float* __restrict__ link,
                       const float* __restrict__ dire, const float* __restrict__ pdr,
                       float* __restrict__ out) {
    int b = threadIdx.x;
    float p[NDD];
    float mx = -1e30f;
#pragma unroll
    for (int n = 0; n < NDD; n++) { p[n] = g_logits[b * NDD + n]; mx = fmaxf(mx, p[n]); }
    float se = 0.0f;
#pragma unroll
    for (int n = 0; n < NDD; n++) se += expf(p[n] - mx);
    float lse = mx + logf(se);
#pragma unroll
    for (int n = 0; n < NDD; n++) p[n] -= lse;

    float mx2 = -1e30f;
#pragma unroll
    for (int n = 0; n < NDD; n++) mx2 = fmaxf(mx2, p[n]);
    float se2 = 0.0f;
#pragma unroll
    for (int n = 0; n < NDD; n++) se2 += expf(p[n] - mx2);
    float lse2 = mx2 + logf(se2);

    int i0 = 0; float v0 = p[0];
#pragma unroll
    for (int n = 1; n < NDD; n++) if (p[n] > v0) { v0 = p[n]; i0 = n; }
    int i1 = -1; float v1 = -1e30f;
#pragma unroll
    for (int n = 0; n < NDD; n++) if (n != i0 && p[n] > v1) { v1 = p[n]; i1 = n; }

    int last = inputs[b * SD + SD - 1];
    int lbl = locd[(size_t)(last - 1) * NED + goal[b]];
    float lossi = -(p[lbl] - lse2);
    int corr = (i0 == lbl) || (i1 == lbl);

    const float* le = link + (size_t)last * EDD;
    const float* d0 = dire + (i0 + 1) * DDD;
    const float* d1 = dire + (i1 + 1) * DDD;
#pragma unroll 4
    for (int k = 0; k < EDD; k++) {
        float q = le[k];
        if (k < DDD) q += 0.5f * (d0[k] + d1[k]);
        g_query[b * EDD + k] = q;
    }

    __shared__ float sl[BD];
    __shared__ int sc[BD];
    sl[b] = lossi; sc[b] = corr;
    __syncthreads();
    for (int st = BD / 2; st > 0; st >>= 1) {
        if (b < st) { sl[b] += sl[b + st]; sc[b] += sc[b + st]; }
        __syncthreads();
    }
    if (b == 0) {
        out[OUT_LOSS] = sl[0] * (5.0f / (float)BD);
        out[OUT_DC] = (float)sc[0];
    }
    for (int i = b; i < BD * NDD * PLD; i += BD) out[OUT_PRED_D + i] = pdr[i];
}

// ---------------------------------------------------------------------------
// Sim GEMM
// ---------------------------------------------------------------------------
__global__ void k_sim(const float* __restrict__ link, float* __restrict__ out) {
    __shared__ float sq[64][17];
    __shared__ float sl[16][65];
    const int tid = threadIdx.x;
    const int tx = tid & 15, ty = tid >> 4;
    const int eBase = blockIdx.x * 64;
    const int mBase = blockIdx.y * 64;

    float acc[16];
#pragma unroll
    for (int i = 0; i < 16; i++) acc[i] = 0.0f;

    for (int kb = 0; kb < EDD; kb += 16) {
#pragma unroll
        for (int i = 0; i < 4; i++) {
            int idx = tid + i * 256;
            int r = idx >> 4, c = idx & 15;
            sq[r][c] = g_query[(mBase + r) * EDD + kb + c];
            sl[c][r] = link[((size_t)(eBase + r + 1)) * EDD + kb + c];
        }
        __syncthreads();
#pragma unroll
        for (int kk = 0; kk < 16; kk++) {
            float a0 = sq[ty][kk],      a1 = sq[ty + 16][kk];
            float a2 = sq[ty + 32][kk], a3 = sq[ty + 48][kk];
            float w0 = sl[kk][tx],      w1 = sl[kk][tx + 16];
            float w2 = sl[kk][tx + 32], w3 = sl[kk][tx + 48];
            acc[0]  += a0 * w0; acc[1]  += a0 * w1; acc[2]  += a0 * w2; acc[3]  += a0 * w3;
            acc[4]  += a1 * w0; acc[5]  += a1 * w1; acc[6]  += a1 * w2; acc[7]  += a1 * w3;
            acc[8]  += a2 * w0; acc[9]  += a2 * w1; acc[10] += a2 * w2; acc[11] += a2 * w3;
            acc[12] += a3 * w0; acc[13] += a3 * w1; acc[14] += a3 * w2; acc[15] += a3 * w3;
        }
        __syncthreads();
    }
#pragma unroll
    for (int mi = 0; mi < 4; mi++)
#pragma unroll
        for (int ni = 0; ni < 4; ni++) {
            int b = mBase + ty + mi * 16;
            int e = eBase + tx + ni * 16;
            float v = acc[mi * 4 + ni];
            size_t base = (size_t)b * (NED * PLD) + e;
#pragma unroll
            for (int pl = 0; pl < PLD; pl++) out[base + (size_t)pl * NED] = v;
        }
}

// ---------------------------------------------------------------------------
// Launcher
// ---------------------------------------------------------------------------
extern "C" void kernel_launch(void* const* d_in, const int* in_sizes, int n_in,
                              void* d_out, int out_size) {
    const int*   inputs = (const int*)d_in[0];
    const int*   dirs   = (const int*)d_in[1];
    const int*   goal   = (const int*)d_in[2];
    const int*   locd   = (const int*)d_in[3];
    const float* pdr    = (const float*)d_in[4];
    const float* link   = (const float*)d_in[5];
    const float* dire   = (const float*)d_in[6];
    const float* w_ih   = (const float*)d_in[7];
    const float* b_ih   = (const float*)d_in[8];
    const float* w_hh   = (const float*)d_in[9];
    const float* b_hh   = (const float*)d_in[10];
    const float* W1     = (const float*)d_in[11];
    const float* b1     = (const float*)d_in[12];
    const float* W2     = (const float*)d_in[13];
    const float* b2     = (const float*)d_in[14];
    const float* W3     = (const float*)d_in[15];
    const float* b3     = (const float*)d_in[16];
    float* out = (float*)d_out;

    static int smem_set = 0;
    if (!smem_set) {
        cudaFuncSetAttribute(k_rnn, cudaFuncAttributeMaxDynamicSharedMemorySize, PK_SMEM);
        smem_set = 1;
    }

    k_init<<<1, 128>>>();
    k_split<<<512, 256>>>(w_hh, w_ih, link);
    k_q<<<((NDD+1) * G4D + 255) / 256, 256>>>(dire, w_ih, b_ih, b_hh);

    // P = link_emb @ Wih_link^T : M=8193, N=2048, K=128
    k_pe<<<dim3(65, 32), 256>>>();

    // Persistent recurrence: 128 CTAs, per-b-group barriers
    k_rnn<<<dim3(4, 32), 512, PK_SMEM>>>(inputs, dirs);

    k_mlp<<<dim3(BD / 32, HD / 32), 256>>>(0, W1, b1);
    k_mlp<<<dim3(BD / 32, HD / 32), 256>>>(1, W2, b2);
    k_logits<<<(BD * NDD + 255) / 256, 256>>>(W3, b3);
    k_head<<<1, BD>>>(inputs, goal, locd, link, dire, pdr, out);
    k_sim<<<dim3(NED / 64, BD / 64), 256>>>(link, out);
}

// round 11
// speedup vs baseline: 3.9172x; 1.0510x over previous
#include <cuda_runtime.h>
#include <cuda_fp16.h>
#include <math.h>
#include <stdint.h>

// Problem dims
#define BD   512
#define SD   128
#define NED  8192
#define EDD  128
#define DDD  32
#define IND  160
#define HD   512
#define G4D  2048
#define NDD  8
#define PLD  5

#define OUT_PRED_D (512u*8192u*5u)
#define OUT_LOSS   (OUT_PRED_D + 512u*8u*5u)
#define OUT_DC     (OUT_LOSS + 1u)

// ---------------- device scratch ----------------
__device__ float g_P[(NED+1)*G4D];
__device__ float g_Q[(NDD+1)*G4D];
__device__ __half g_whh_fhi[G4D*HD], g_whh_flo[G4D*HD];
__device__ __half g_hh[2][BD*HD], g_hl[2][BD*HD];
__device__ float g_wih_hi[G4D*IND], g_wih_lo[G4D*IND];
__device__ float g_link_hi[(NED+1)*EDD], g_link_lo[(NED+1)*EDD];
__device__ float g_hfp[BD*HD];
__device__ float g_z1[BD*HD], g_z2[BD*HD];
__device__ float g_logits[BD*NDD], g_query[BD*EDD];
// per-CTA step flags: [grp][jtile] padded to 128B lines
__device__ volatile unsigned g_flag[4 * 32 * 32];

__device__ __forceinline__ float sigmf(float x) { return 1.0f / (1.0f + expf(-x)); }

__device__ __forceinline__ void tf32_split(float v, float& hi, float& lo) {
    unsigned hb; asm("cvt.rna.tf32.f32 %0, %1;" : "=r"(hb) : "f"(v));
    hi = __uint_as_float(hb);
    float r = v - hi;
    unsigned lb; asm("cvt.rna.tf32.f32 %0, %1;" : "=r"(lb) : "f"(r));
    lo = __uint_as_float(lb);
}
__device__ __forceinline__ void h16_split(float v, __half& hi, __half& lo) {
    hi = __float2half_rn(v);
    float r = v - __half2float(hi);
    lo = __float2half_rn(r * 1024.0f);
}

__device__ __forceinline__ uint32_t smem_u32(const void* p) {
    uint32_t a;
    asm("{ .reg .u64 t; cvta.to.shared.u64 t, %1; cvt.u32.u64 %0, t; }" : "=r"(a) : "l"(p));
    return a;
}
__device__ __forceinline__ void cp16(uint32_t dst, const void* src) {
    asm volatile("cp.async.cg.shared.global [%0], [%1], 16;" :: "r"(dst), "l"(src));
}
__device__ __forceinline__ void ldsm4(uint32_t* r, uint32_t addr) {
    asm volatile("ldmatrix.sync.aligned.m8n8.x4.shared.b16 {%0,%1,%2,%3}, [%4];"
                 : "=r"(r[0]), "=r"(r[1]), "=r"(r[2]), "=r"(r[3]) : "r"(addr));
}
#define CP_COMMIT() asm volatile("cp.async.commit_group;" ::: "memory")
#define CP_WAIT0()  asm volatile("cp.async.wait_group 0;" ::: "memory")
#define CP_WAIT1()  asm volatile("cp.async.wait_group 1;" ::: "memory")
#define BARN(id, n) asm volatile("bar.sync %0, %1;" :: "r"(id), "r"(n) : "memory")

#define FB(x) __float_as_uint(x)
#define MMA8(d, a, b) \
    asm volatile("mma.sync.aligned.m16n8k8.row.col.f32.tf32.tf32.f32 " \
                 "{%0,%1,%2,%3},{%4,%5,%6,%7},{%8,%9},{%0,%1,%2,%3};" \
                 : "+f"(d[0]), "+f"(d[1]), "+f"(d[2]), "+f"(d[3]) \
                 : "r"(a[0]), "r"(a[1]), "r"(a[2]), "r"(a[3]), "r"(b[0]), "r"(b[1]))
#define MMAH(d, a, b) \
    asm volatile("mma.sync.aligned.m16n8k16.row.col.f32.f16.f16.f32 " \
                 "{%0,%1,%2,%3},{%4,%5,%6,%7},{%8,%9},{%0,%1,%2,%3};" \
                 : "+f"(d[0]), "+f"(d[1]), "+f"(d[2]), "+f"(d[3]) \
                 : "r"(a[0]), "r"(a[1]), "r"(a[2]), "r"(a[3]), "r"(b[0]), "r"(b[1]))

// ---------------------------------------------------------------------------
__global__ void k_init() {
    int i = blockIdx.x * blockDim.x + threadIdx.x;
    if (i < 4 * 32 * 32) g_flag[i] = 0u;
}

__global__ void k_split(const float* __restrict__ whh, const float* __restrict__ wih,
                        const float* __restrict__ link) {
    int i = blockIdx.x * blockDim.x + threadIdx.x;
    int stride = gridDim.x * blockDim.x;
    for (int idx = i; idx < G4D*HD; idx += stride) {
        __half hi, lo; h16_split(whh[idx], hi, lo);
        g_whh_fhi[idx] = hi; g_whh_flo[idx] = lo;
    }
    for (int idx = i; idx < G4D*IND; idx += stride) tf32_split(wih[idx], g_wih_hi[idx], g_wih_lo[idx]);
    for (int idx = i; idx < (NED+1)*EDD; idx += stride) tf32_split(link[idx], g_link_hi[idx], g_link_lo[idx]);
}

__global__ void k_q(const float* __restrict__ dire, const float* __restrict__ wih,
                    const float* __restrict__ bih, const float* __restrict__ bhh) {
    int idx = blockIdx.x * blockDim.x + threadIdx.x;
    if (idx >= (NDD+1) * G4D) return;
    int d = idx / G4D, n = idx - d * G4D;
    float acc = bih[n] + bhh[n];
#pragma unroll 8
    for (int k = 0; k < DDD; k++) acc += dire[d * DDD + k] * wih[n * IND + EDD + k];
    g_Q[idx] = acc;
}

// ---------------------------------------------------------------------------
// K-pe: P = link_emb @ Wih_link^T via 3xTF32 mma.sync. M=8193, N=2048, K=128.
// ---------------------------------------------------------------------------
__global__ void k_pe() {
    __shared__ float sAhi[16][132], sAlo[16][132];
    __shared__ float sBhi[16][68],  sBlo[16][68];

    const int tid = threadIdx.x;
    const int lane = tid & 31, wid = tid >> 5;
    const int gid = lane >> 2, tig = lane & 3;
    const int mBase = blockIdx.x * 128, nBase = blockIdx.y * 64;
    const int warpM = (wid >> 1) * 32, warpN = (wid & 1) * 32;

    float acc[2][4][4];
#pragma unroll
    for (int a = 0; a < 2; a++)
#pragma unroll
        for (int b = 0; b < 4; b++)
#pragma unroll
            for (int c = 0; c < 4; c++) acc[a][b][c] = 0.0f;

    for (int ch = 0; ch < 8; ch++) {
        int kb = ch * 16;
#pragma unroll
        for (int it = 0; it < 2; it++) {
            int idx = tid + it * 256;
            int r = idx >> 2, kq = idx & 3;
            int k = kb + kq * 4;
            int rr = mBase + r; if (rr > NED) rr = NED;
            size_t off = (size_t)rr * EDD + k;
            float4 vh = *(const float4*)(g_link_hi + off);
            float4 vl = *(const float4*)(g_link_lo + off);
            sAhi[kq*4+0][r] = vh.x; sAhi[kq*4+1][r] = vh.y; sAhi[kq*4+2][r] = vh.z; sAhi[kq*4+3][r] = vh.w;
            sAlo[kq*4+0][r] = vl.x; sAlo[kq*4+1][r] = vl.y; sAlo[kq*4+2][r] = vl.z; sAlo[kq*4+3][r] = vl.w;
        }
        {
            int r = tid >> 2, kq = tid & 3;
            int k = kb + kq * 4;
            size_t off = (size_t)(nBase + r) * IND + k;
            float4 vh = *(const float4*)(g_wih_hi + off);
            float4 vl = *(const float4*)(g_wih_lo + off);
            sBhi[kq*4+0][r] = vh.x; sBhi[kq*4+1][r] = vh.y; sBhi[kq*4+2][r] = vh.z; sBhi[kq*4+3][r] = vh.w;
            sBlo[kq*4+0][r] = vl.x; sBlo[kq*4+1][r] = vl.y; sBlo[kq*4+2][r] = vl.z; sBlo[kq*4+3][r] = vl.w;
        }
        __syncthreads();
#pragma unroll
        for (int kk = 0; kk < 2; kk++) {
            int k0 = kk * 8;
            uint32_t ahi[2][4], alo[2][4];
#pragma unroll
            for (int mt = 0; mt < 2; mt++) {
                int row = warpM + mt * 16 + gid;
                ahi[mt][0] = FB(sAhi[k0+tig  ][row  ]); ahi[mt][1] = FB(sAhi[k0+tig  ][row+8]);
                ahi[mt][2] = FB(sAhi[k0+tig+4][row  ]); ahi[mt][3] = FB(sAhi[k0+tig+4][row+8]);
                alo[mt][0] = FB(sAlo[k0+tig  ][row  ]); alo[mt][1] = FB(sAlo[k0+tig  ][row+8]);
                alo[mt][2] = FB(sAlo[k0+tig+4][row  ]); alo[mt][3] = FB(sAlo[k0+tig+4][row+8]);
            }
            uint32_t bhi[4][2], blo[4][2];
#pragma unroll
            for (int nt = 0; nt < 4; nt++) {
                int cn = warpN + nt * 8 + gid;
                bhi[nt][0] = FB(sBhi[k0+tig][cn]); bhi[nt][1] = FB(sBhi[k0+tig+4][cn]);
                blo[nt][0] = FB(sBlo[k0+tig][cn]); blo[nt][1] = FB(sBlo[k0+tig+4][cn]);
            }
#pragma unroll
            for (int mt = 0; mt < 2; mt++)
#pragma unroll
                for (int nt = 0; nt < 4; nt++) {
                    MMA8(acc[mt][nt], ahi[mt], bhi[nt]);
                    MMA8(acc[mt][nt], ahi[mt], blo[nt]);
                    MMA8(acc[mt][nt], alo[mt], bhi[nt]);
                }
        }
        __syncthreads();
    }
#pragma unroll
    for (int mt = 0; mt < 2; mt++)
#pragma unroll
        for (int nt = 0; nt < 4; nt++) {
            int r0 = mBase + warpM + mt * 16 + gid;
            int n0 = nBase + warpN + nt * 8 + 2 * tig;
            if (r0 < NED + 1) {
                g_P[(size_t)r0 * G4D + n0]     = acc[mt][nt][0];
                g_P[(size_t)r0 * G4D + n0 + 1] = acc[mt][nt][1];
            }
            if (r0 + 8 < NED + 1) {
                g_P[(size_t)(r0+8) * G4D + n0]   = acc[mt][nt][2];
                g_P[(size_t)(r0+8) * G4D + n0+1] = acc[mt][nt][3];
            }
        }
}

// ---------------------------------------------------------------------------
// K-rnn: persistent recurrence. Grid (4 bTile x 32 jTile) = 128 CTAs, 512 thr.
//   W_hh slice smem-resident; c in regs; h streamed via cp.async (issue-ahead
//   with correct wait->barrier->consume ordering); ldmatrix.x4; flag barriers.
// ---------------------------------------------------------------------------
#define BSTR 260
#define BW_LO 16640
#define AW0   33280
#define AKG   10240
#define ABUF  5120
#define A_LOW 2560
#define ASTR  20
#define PK_SMEM (53760 * 4)

__global__ void __launch_bounds__(512, 1) k_rnn(const int* __restrict__ inputs,
                                                const int* __restrict__ dirs) {
    extern __shared__ float sm[];
    uint32_t* smw = (uint32_t*)sm;
    const uint32_t sbase = smem_u32(sm);
    const int tid = threadIdx.x;
    const int lane = tid & 31, wid = tid >> 5;
    const int kg = wid >> 3, wid8 = wid & 7;
    const int lt = tid & 255;
    const int grp = blockIdx.x;
    const int jt = blockIdx.y;
    const int bBase = blockIdx.x * 128;
    const int jBase = blockIdx.y * 16;
    const int warpM = (wid8 >> 1) * 32, warpN = (wid8 & 1) * 32;

    // ---- one-time B load: n_local = j_local*4 + g
    for (int i = tid; i < 64 * 64; i += 512) {
        int r = i >> 6, q = i & 63;
        int g = r & 3, jl = r >> 2;
        size_t src = ((size_t)(g * HD + jBase + jl)) * HD + q * 8;
        uint4 vh = *(const uint4*)(g_whh_fhi + src);
        uint4 vl = *(const uint4*)(g_whh_flo + src);
        *(uint4*)(smw + r * BSTR + q * 4) = vh;
        *(uint4*)(smw + BW_LO + r * BSTR + q * 4) = vl;
    }
    __syncthreads();

    // ldmatrix lane-address components (byte offsets)
    const uint32_t aOffL = (uint32_t)(((warpM + (lane & 7) + ((lane >> 3) & 1) * 8) * ASTR
                                      + (lane >> 4) * 4) * 4);
    const uint32_t bOffL = (uint32_t)(((warpN + (lane & 7) + ((lane >> 4) & 1) * 8) * BSTR
                                      + ((lane >> 3) & 1) * 4) * 4);
    const uint32_t bHiL = sbase + bOffL;
    const uint32_t bLoL = sbase + (uint32_t)(BW_LO * 4) + bOffL;

    // epilogue ownership: b fixed, 4 consecutive j
    const int bl_ep = tid >> 2;
    const int b_ep = bBase + bl_ep;
    const int j0 = (tid & 3) * 4;
    float cst[4] = {0.f, 0.f, 0.f, 0.f};

    for (int s = 0; s < SD; s++) {
        // hoisted gate base: gb = P[inp] + Q[dir] (issues before the MMA loop;
        // latency hides under the chunk pipeline)
        const int inp = inputs[b_ep * SD + s];
        const int dr  = dirs[b_ep * SD + s];
        float gb[16];
#pragma unroll
        for (int g = 0; g < 4; g++) {
            float4 pv = *(const float4*)(g_P + (size_t)inp * G4D + g * HD + jBase + j0);
            float4 qv = *(const float4*)(g_Q + (size_t)dr * G4D + g * HD + jBase + j0);
            gb[g * 4 + 0] = pv.x + qv.x;
            gb[g * 4 + 1] = pv.y + qv.y;
            gb[g * 4 + 2] = pv.z + qv.z;
            gb[g * 4 + 3] = pv.w + qv.w;
        }

        float D[2][4][4], E[2][4][4];
#pragma unroll
        for (int mt = 0; mt < 2; mt++)
#pragma unroll
            for (int nt = 0; nt < 4; nt++)
#pragma unroll
                for (int r = 0; r < 4; r++) { D[mt][nt][r] = 0.f; E[mt][nt][r] = 0.f; }

        if (s > 0) {
            const __half* __restrict__ hh = g_hh[s & 1];
            const __half* __restrict__ hl = g_hl[s & 1];
            auto load_chunk = [&](int cc, int buf) {
                const int kb = kg * 256 + cc * 32;
                const uint32_t bu = sbase + (uint32_t)((AW0 + kg * AKG + buf * ABUF) * 4);
#pragma unroll
                for (int t = 0; t < 4; t++) {
                    int id = lt + t * 256;
                    int isLo = id >> 9;
                    int rem = id & 511;
                    int r = rem >> 2, t4 = rem & 3;
                    const __half* src = (isLo ? hl : hh) + (size_t)(bBase + r) * HD + kb + t4 * 8;
                    uint32_t dst = bu + (uint32_t)(((isLo ? A_LOW : 0) + r * ASTR + t4 * 4) * 4);
                    cp16(dst, src);
                }
                CP_COMMIT();
            };

            load_chunk(0, 0);
#pragma unroll 1
            for (int cc = 0; cc < 8; cc++) {
                const int buf = cc & 1;
                // 1) buffer-reuse guard: all kgroup warps done with MMA(cc-1)
                BARN(1 + kg, 256);
                // 2) issue next chunk (overwrites cc-1's buffer), then wait for cc
                if (cc < 7) {
                    load_chunk(cc + 1, buf ^ 1);
                    CP_WAIT1();
                } else {
                    CP_WAIT0();
                }
                // 3) visibility guard: every thread past its wait before consume
                BARN(3 + kg, 256);

                const uint32_t aHiBase = sbase + (uint32_t)((AW0 + kg * AKG + buf * ABUF) * 4) + aOffL;
                const uint32_t aLoBase = aHiBase + (uint32_t)(A_LOW * 4);
                const int kwBase = kg * 128 + cc * 16;
#pragma unroll
                for (int ksub = 0; ksub < 2; ksub++) {
                    const int k0 = ksub * 8;
                    uint32_t ahi[2][4], alo[2][4];
                    ldsm4(ahi[0], aHiBase + k0 * 4);
                    ldsm4(ahi[1], aHiBase + k0 * 4 + 16 * ASTR * 4);
                    ldsm4(alo[0], aLoBase + k0 * 4);
                    ldsm4(alo[1], aLoBase + k0 * 4 + 16 * ASTR * 4);
                    uint32_t bhi[4][2], blo[4][2];
                    {
                        const uint32_t kwb = (uint32_t)((kwBase + k0) * 4);
                        uint32_t t4[4];
                        ldsm4(t4, bHiL + kwb);
                        bhi[0][0] = t4[0]; bhi[0][1] = t4[1]; bhi[1][0] = t4[2]; bhi[1][1] = t4[3];
                        ldsm4(t4, bHiL + kwb + 16 * BSTR * 4);
                        bhi[2][0] = t4[0]; bhi[2][1] = t4[1]; bhi[3][0] = t4[2]; bhi[3][1] = t4[3];
                        ldsm4(t4, bLoL + kwb);
                        blo[0][0] = t4[0]; blo[0][1] = t4[1]; blo[1][0] = t4[2]; blo[1][1] = t4[3];
                        ldsm4(t4, bLoL + kwb + 16 * BSTR * 4);
                        blo[2][0] = t4[0]; blo[2][1] = t4[1]; blo[3][0] = t4[2]; blo[3][1] = t4[3];
                    }
#pragma unroll
                    for (int mt = 0; mt < 2; mt++)
#pragma unroll
                        for (int nt = 0; nt < 4; nt++) {
                            MMAH(D[mt][nt], ahi[mt], bhi[nt]);
                            MMAH(E[mt][nt], ahi[mt], blo[nt]);
                            MMAH(E[mt][nt], alo[mt], bhi[nt]);
                        }
                }
            }
#pragma unroll
            for (int mt = 0; mt < 2; mt++)
#pragma unroll
                for (int nt = 0; nt < 4; nt++)
#pragma unroll
                    for (int r = 0; r < 4; r++)
                        D[mt][nt][r] += E[mt][nt][r] * 0.0009765625f;
        }

        __syncthreads();
        float* red = sm + AW0;
        if (s > 0) {
            const int gid = lane >> 2, tig = lane & 3;
            if (kg == 1) {
#pragma unroll
                for (int mt = 0; mt < 2; mt++)
#pragma unroll
                    for (int nt = 0; nt < 4; nt++) {
                        int r0 = warpM + mt * 16 + gid;
                        int n0 = warpN + nt * 8 + 2 * tig;
                        red[r0 * 68 + n0]           = D[mt][nt][0];
                        red[r0 * 68 + n0 + 1]       = D[mt][nt][1];
                        red[(r0 + 8) * 68 + n0]     = D[mt][nt][2];
                        red[(r0 + 8) * 68 + n0 + 1] = D[mt][nt][3];
                    }
            }
            __syncthreads();
            if (kg == 0) {
#pragma unroll
                for (int mt = 0; mt < 2; mt++)
#pragma unroll
                    for (int nt = 0; nt < 4; nt++) {
                        int r0 = warpM + mt * 16 + gid;
                        int n0 = warpN + nt * 8 + 2 * tig;
                        red[r0 * 68 + n0]           += D[mt][nt][0];
                        red[r0 * 68 + n0 + 1]       += D[mt][nt][1];
                        red[(r0 + 8) * 68 + n0]     += D[mt][nt][2];
                        red[(r0 + 8) * 68 + n0 + 1] += D[mt][nt][3];
                    }
            }
            __syncthreads();
        }

        // ---- fused LSTM epilogue: thread owns (b_ep, j0..j0+3) ----
        {
            __half hhi[4], hlo[4];
            float hf[4];
#pragma unroll
            for (int jj = 0; jj < 4; jj++) {
                float gi = gb[0 * 4 + jj];
                float gf = gb[1 * 4 + jj];
                float gg = gb[2 * 4 + jj];
                float go = gb[3 * 4 + jj];
                if (s > 0) {
                    int nb = (j0 + jj) * 4;
                    gi += red[bl_ep * 68 + nb + 0];
                    gf += red[bl_ep * 68 + nb + 1];
                    gg += red[bl_ep * 68 + nb + 2];
                    go += red[bl_ep * 68 + nb + 3];
                }
                float cn = sigmf(gf) * cst[jj] + sigmf(gi) * tanhf(gg);
                cst[jj] = cn;
                float h = sigmf(go) * tanhf(cn);
                hf[jj] = h;
                h16_split(h, hhi[jj], hlo[jj]);
            }
            __half* hho = g_hh[(s + 1) & 1];
            __half* hlo_ = g_hl[(s + 1) & 1];
            size_t off = (size_t)b_ep * HD + jBase + j0;
            *(__half2*)(hho + off)     = __halves2half2(hhi[0], hhi[1]);
            *(__half2*)(hho + off + 2) = __halves2half2(hhi[2], hhi[3]);
            *(__half2*)(hlo_ + off)     = __halves2half2(hlo[0], hlo[1]);
            *(__half2*)(hlo_ + off + 2) = __halves2half2(hlo[2], hlo[3]);
            if (s == SD - 1)
                *(float4*)(g_hfp + off) = make_float4(hf[0], hf[1], hf[2], hf[3]);
        }

        // ---- flag-vector barrier over this b-group (32 CTAs) ----
        __threadfence();
        __syncthreads();
        if (tid == 0) g_flag[(grp * 32 + jt) * 32] = (unsigned)(s + 1);
        if (tid < 32) {
            while (g_flag[(grp * 32 + tid) * 32] < (unsigned)(s + 1)) { }
        }
        __threadfence();
        __syncthreads();
    }
}

// ---------------------------------------------------------------------------
// MLP layers (fp32)
// ---------------------------------------------------------------------------
__global__ void k_mlp(int which, const float* __restrict__ W, const float* __restrict__ bias) {
    __shared__ float sa[32][33];
    __shared__ float swm[32][33];
    const int tid = threadIdx.x;
    const int tx = tid & 15, ty = tid >> 4;
    const int mBase = blockIdx.x * 32;
    const int nBase = blockIdx.y * 32;
    const float* __restrict__ A = (which == 0) ? g_hfp : g_z1;
    float* __restrict__ out = (which == 0) ? g_z1 : g_z2;

    float acc[4] = {0.f, 0.f, 0.f, 0.f};
    for (int kb = 0; kb < HD; kb += 32) {
#pragma unroll
        for (int i = 0; i < 4; i++) {
            int idx = tid + i * 256;
            int r = idx >> 5, c = idx & 31;
            sa[r][c]  = A[(mBase + r) * HD + kb + c];
            swm[r][c] = W[(nBase + r) * HD + kb + c];
        }
        __syncthreads();
#pragma unroll
        for (int kk = 0; kk < 32; kk++) {
            float a0 = sa[ty][kk], a1 = sa[ty + 16][kk];
            float w0 = swm[tx][kk], w1 = swm[tx + 16][kk];
            acc[0] += a0 * w0; acc[1] += a0 * w1;
            acc[2] += a1 * w0; acc[3] += a1 * w1;
        }
        __syncthreads();
    }
#pragma unroll
    for (int bi = 0; bi < 2; bi++)
#pragma unroll
        for (int ni = 0; ni < 2; ni++) {
            int m = mBase + ty + bi * 16;
            int n = nBase + tx + ni * 16;
            float v = acc[bi * 2 + ni] + bias[n];
            out[m * HD + n] = fmaxf(v, 0.0f);
        }
}

__global__ void k_logits(const float* __restrict__ W3, const float* __restrict__ b3) {
    int idx = blockIdx.x * blockDim.x + threadIdx.x;
    if (idx >= BD * NDD) return;
    int b = idx >> 3, n = idx & 7;
    const float4* z = (const float4*)(g_z2 + b * HD);
    const float4* w = (const float4*)(W3 + n * HD);
    float acc = b3[n];
#pragma unroll 4
    for (int k = 0; k < HD / 4; k++) {
        float4 zv = z[k], wv = w[k];
        acc += zv.x * wv.x + zv.y * wv.y + zv.z * wv.z + zv.w * wv.w;
    }
    g_logits[idx] = acc;
}

// ---------------------------------------------------------------------------
// Head
// ---------------------------------------------------------------------------
__global__ void k_head(const int* __restrict__ inputs, const int* __restrict__ goal,
                       const int* __restrict__ locd, const float* __restrict__ link,
                       const float* __restrict__ dire, const float* __restrict__ pdr,
                       float* __restrict__ out) {
    int b = threadIdx.x;
    float p[NDD];
    float mx = -1e30f;
#pragma unroll
    for (int n = 0; n < NDD; n++) { p[n] = g_logits[b * NDD + n]; mx = fmaxf(mx, p[n]); }
    float se = 0.0f;
#pragma unroll
    for (int n = 0; n < NDD; n++) se += expf(p[n] - mx);
    float lse = mx + logf(se);
#pragma unroll
    for (int n = 0; n < NDD; n++) p[n] -= lse;

    float mx2 = -1e30f;
#pragma unroll
    for (int n = 0; n < NDD; n++) mx2 = fmaxf(mx2, p[n]);
    float se2 = 0.0f;
#pragma unroll
    for (int n = 0; n < NDD; n++) se2 += expf(p[n] - mx2);
    float lse2 = mx2 + logf(se2);

    int i0 = 0; float v0 = p[0];
#pragma unroll
    for (int n = 1; n < NDD; n++) if (p[n] > v0) { v0 = p[n]; i0 = n; }
    int i1 = -1; float v1 = -1e30f;
#pragma unroll
    for (int n = 0; n < NDD; n++) if (n != i0 && p[n] > v1) { v1 = p[n]; i1 = n; }

    int last = inputs[b * SD + SD - 1];
    int lbl = locd[(size_t)(last - 1) * NED + goal[b]];
    float lossi = -(p[lbl] - lse2);
    int corr = (i0 == lbl) || (i1 == lbl);

    const float* le = link + (size_t)last * EDD;
    const float* d0 = dire + (i0 + 1) * DDD;
    const float* d1 = dire + (i1 + 1) * DDD;
#pragma unroll 4
    for (int k = 0; k < EDD; k++) {
        float q = le[k];
        if (k < DDD) q += 0.5f * (d0[k] + d1[k]);
        g_query[b * EDD + k] = q;
    }

    __shared__ float sl[BD];
    __shared__ int sc[BD];
    sl[b] = lossi; sc[b] = corr;
    __syncthreads();
    for (int st = BD / 2; st > 0; st >>= 1) {
        if (b < st) { sl[b] += sl[b + st]; sc[b] += sc[b + st]; }
        __syncthreads();
    }
    if (b == 0) {
        out[OUT_LOSS] = sl[0] * (5.0f / (float)BD);
        out[OUT_DC] = (float)sc[0];
    }
    for (int i = b; i < BD * NDD * PLD; i += BD) out[OUT_PRED_D + i] = pdr[i];
}

// ---------------------------------------------------------------------------
// Sim GEMM
// ---------------------------------------------------------------------------
__global__ void k_sim(const float* __restrict__ link, float* __restrict__ out) {
    __shared__ float sq[64][17];
    __shared__ float sl[16][65];
    const int tid = threadIdx.x;
    const int tx = tid & 15, ty = tid >> 4;
    const int eBase = blockIdx.x * 64;
    const int mBase = blockIdx.y * 64;

    float acc[16];
#pragma unroll
    for (int i = 0; i < 16; i++) acc[i] = 0.0f;

    for (int kb = 0; kb < EDD; kb += 16) {
#pragma unroll
        for (int i = 0; i < 4; i++) {
            int idx = tid + i * 256;
            int r = idx >> 4, c = idx & 15;
            sq[r][c] = g_query[(mBase + r) * EDD + kb + c];
            sl[c][r] = link[((size_t)(eBase + r + 1)) * EDD + kb + c];
        }
        __syncthreads();
#pragma unroll
        for (int kk = 0; kk < 16; kk++) {
            float a0 = sq[ty][kk],      a1 = sq[ty + 16][kk];
            float a2 = sq[ty + 32][kk], a3 = sq[ty + 48][kk];
            float w0 = sl[kk][tx],      w1 = sl[kk][tx + 16];
            float w2 = sl[kk][tx + 32], w3 = sl[kk][tx + 48];
            acc[0]  += a0 * w0; acc[1]  += a0 * w1; acc[2]  += a0 * w2; acc[3]  += a0 * w3;
            acc[4]  += a1 * w0; acc[5]  += a1 * w1; acc[6]  += a1 * w2; acc[7]  += a1 * w3;
            acc[8]  += a2 * w0; acc[9]  += a2 * w1; acc[10] += a2 * w2; acc[11] += a2 * w3;
            acc[12] += a3 * w0; acc[13] += a3 * w1; acc[14] += a3 * w2; acc[15] += a3 * w3;
        }
        __syncthreads();
    }
#pragma unroll
    for (int mi = 0; mi < 4; mi++)
#pragma unroll
        for (int ni = 0; ni < 4; ni++) {
            int b = mBase + ty + mi * 16;
            int e = eBase + tx + ni * 16;
            float v = acc[mi * 4 + ni];
            size_t base = (size_t)b * (NED * PLD) + e;
#pragma unroll
            for (int pl = 0; pl < PLD; pl++) out[base + (size_t)pl * NED] = v;
        }
}

// ---------------------------------------------------------------------------
// Launcher
// ---------------------------------------------------------------------------
extern "C" void kernel_launch(void* const* d_in, const int* in_sizes, int n_in,
                              void* d_out, int out_size) {
    const int*   inputs = (const int*)d_in[0];
    const int*   dirs   = (const int*)d_in[1];
    const int*   goal   = (const int*)d_in[2];
    const int*   locd   = (const int*)d_in[3];
    const float* pdr    = (const float*)d_in[4];
    const float* link   = (const float*)d_in[5];
    const float* dire   = (const float*)d_in[6];
    const float* w_ih   = (const float*)d_in[7];
    const float* b_ih   = (const float*)d_in[8];
    const float* w_hh   = (const float*)d_in[9];
    const float* b_hh   = (const float*)d_in[10];
    const float* W1     = (const float*)d_in[11];
    const float* b1     = (const float*)d_in[12];
    const float* W2     = (const float*)d_in[13];
    const float* b2     = (const float*)d_in[14];
    const float* W3     = (const float*)d_in[15];
    const float* b3     = (const float*)d_in[16];
    float* out = (float*)d_out;

    static int smem_set = 0;
    if (!smem_set) {
        cudaFuncSetAttribute(k_rnn, cudaFuncAttributeMaxDynamicSharedMemorySize, PK_SMEM);
        smem_set = 1;
    }

    k_init<<<16, 256>>>();
    k_split<<<512, 256>>>(w_hh, w_ih, link);
    k_q<<<((NDD+1) * G4D + 255) / 256, 256>>>(dire, w_ih, b_ih, b_hh);

    // P = link_emb @ Wih_link^T : M=8193, N=2048, K=128
    k_pe<<<dim3(65, 32), 256>>>();

    // Persistent recurrence: 128 CTAs, flag-vector barriers
    k_rnn<<<dim3(4, 32), 512, PK_SMEM>>>(inputs, dirs);

    k_mlp<<<dim3(BD / 32, HD / 32), 256>>>(0, W1, b1);
    k_mlp<<<dim3(BD / 32, HD / 32), 256>>>(1, W2, b2);
    k_logits<<<(BD * NDD + 255) / 256, 256>>>(W3, b3);
    k_head<<<1, BD>>>(inputs, goal, locd, link, dire, pdr, out);
    k_sim<<<dim3(NED / 64, BD / 64), 256>>>(link, out);
}